// round 2
// baseline (speedup 1.0000x reference)
#include <cuda_runtime.h>
#include <math.h>

#define Bb 64
#define Tt 512
#define Ii 128
#define Rr 2048
#define Hh 512
#define Oo 128

typedef unsigned long long u64;

// ---------------- device scratch (static; no allocations) ----------------
__device__ float g_hE[2][Bb * Rr];   // ESN hidden, double buffered
__device__ float g_hG[2][Bb * Hh];   // GRU hidden, double buffered
__device__ float g_proj[Bb * Hh];
__device__ float g_cat [Bb * 2 * Hh];
__device__ float g_gate[Bb * Hh];
__device__ float g_comb[Bb * Hh];
__device__ float g_hid [Bb * Hh];

// ---------------- f32x2 helpers ----------------
__device__ __forceinline__ u64 pack2(float lo, float hi) {
    u64 r;
    asm("mov.b64 %0,{%1,%2};" : "=l"(r) : "f"(lo), "f"(hi));
    return r;
}
__device__ __forceinline__ void unpack2(u64 v, float& lo, float& hi) {
    asm("mov.b64 {%0,%1},%2;" : "=f"(lo), "=f"(hi) : "l"(v));
}
// packed fp32x2 fma: d = a*b + d (elementwise on the two f32 lanes)
__device__ __forceinline__ void fma2(u64& d, u64 a, u64 b) {
    asm("fma.rn.f32x2 %0,%1,%2,%0;" : "+l"(d) : "l"(a), "l"(b));
}

__device__ __forceinline__ float sigm(float x) { return 1.0f / (1.0f + expf(-x)); }

// ---------------- init: zero recurrent states ----------------
__global__ void k_init() {
    int i = blockIdx.x * blockDim.x + threadIdx.x;
    if (i < Bb * Rr) g_hE[0][i] = 0.0f;
    if (i < Bb * Hh) g_hG[0][i] = 0.0f;
}

// ---------------- fused per-timestep kernel ----------------
// grid = 160 blocks x 128 threads
//   bx in [0,128): ESN tile 64(b) x 16(cols), K = 2048 (h @ W_res) + 128 (x_t @ W_in)
//   bx in [128,160): GRU tile 64(b) x 16(j) x 3 gates, K = 512 (h @ W_hh^T) + 128 (x_t @ W_ih^T)
__global__ __launch_bounds__(128) void k_step(
    const float* __restrict__ x,    const float* __restrict__ Win,
    const float* __restrict__ Wres, const float* __restrict__ Wih,
    const float* __restrict__ Whh,  const float* __restrict__ bih,
    const float* __restrict__ bhh,  int t, int p)
{
    __shared__ __align__(16) float sA[32 * 68];     // A chunk transposed: sA[k][b]
    __shared__ __align__(16) u64   sW2[3 * 32 * 16];// weights as (w,w) pairs

    const int tid = threadIdx.x;
    const int tx  = tid & 7;     // column-pair index
    const int ty  = tid >> 3;    // batch quad index (0..15)
    const int bx  = blockIdx.x;

    if (bx < 128) {
        // ======================= ESN =======================
        const float* __restrict__ hOld = g_hE[p];
        float*       __restrict__ hNew = g_hE[p ^ 1];
        const int cb = bx * 16;

        u64 aE[2][2] = {{0ull, 0ull}, {0ull, 0ull}};  // [col][batch-pair]

        for (int ch = 0; ch < 68; ++ch) {             // 68*32 = 2176
            const int k0 = ch * 32;
            // load A chunk (64 b x 32 k), transposed
            #pragma unroll
            for (int r = 0; r < 4; ++r) {
                int idx = tid + r * 128;              // 0..511
                int b = idx >> 3, kq = idx & 7;
                const float* src = (k0 < Rr)
                    ? (hOld + b * Rr + k0 + 4 * kq)
                    : (x + b * (Tt * Ii) + t * Ii + (k0 - Rr) + 4 * kq);
                float4 v = *(const float4*)src;
                sA[(4 * kq + 0) * 68 + b] = v.x;
                sA[(4 * kq + 1) * 68 + b] = v.y;
                sA[(4 * kq + 2) * 68 + b] = v.z;
                sA[(4 * kq + 3) * 68 + b] = v.w;
            }
            // load W chunk (32 k x 16 c) as duplicated pairs
            #pragma unroll
            for (int r = 0; r < 4; ++r) {
                int idx = tid + r * 128;              // 0..511
                int kr = idx & 31, c = idx >> 5;
                int k = k0 + kr;
                float w = (k < Rr) ? Wres[k * Rr + cb + c]
                                   : Win[(k - Rr) * Rr + cb + c];
                sW2[kr * 16 + c] = pack2(w, w);
            }
            __syncthreads();
            #pragma unroll
            for (int kk = 0; kk < 32; ++kk) {
                ulonglong2 av = *(const ulonglong2*)&sA[kk * 68 + 4 * ty];
                ulonglong2 wv = *(const ulonglong2*)&sW2[kk * 16 + 2 * tx];
                fma2(aE[0][0], av.x, wv.x); fma2(aE[0][1], av.y, wv.x);
                fma2(aE[1][0], av.x, wv.y); fma2(aE[1][1], av.y, wv.y);
            }
            __syncthreads();
        }
        // epilogue: h' = 0.7 h + 0.3 tanh(acc)
        #pragma unroll
        for (int cc = 0; cc < 2; ++cc) {
            int c = cb + 2 * tx + cc;
            float v0, v1, v2, v3;
            unpack2(aE[cc][0], v0, v1);
            unpack2(aE[cc][1], v2, v3);
            int b0 = 4 * ty;
            hNew[(b0 + 0) * Rr + c] = 0.7f * hOld[(b0 + 0) * Rr + c] + 0.3f * tanhf(v0);
            hNew[(b0 + 1) * Rr + c] = 0.7f * hOld[(b0 + 1) * Rr + c] + 0.3f * tanhf(v1);
            hNew[(b0 + 2) * Rr + c] = 0.7f * hOld[(b0 + 2) * Rr + c] + 0.3f * tanhf(v2);
            hNew[(b0 + 3) * Rr + c] = 0.7f * hOld[(b0 + 3) * Rr + c] + 0.3f * tanhf(v3);
        }
    } else {
        // ======================= GRU =======================
        const float* __restrict__ hOld = g_hG[p];
        float*       __restrict__ hNew = g_hG[p ^ 1];
        const int jb = (bx - 128) * 16;

        u64 aR[2][2]  = {{0ull,0ull},{0ull,0ull}};
        u64 aZ[2][2]  = {{0ull,0ull},{0ull,0ull}};
        u64 aNH[2][2] = {{0ull,0ull},{0ull,0ull}};   // n-gate, h-part
        u64 aNX[2][2] = {{0ull,0ull},{0ull,0ull}};   // n-gate, x-part

        auto inner = [&](u64 (&aN)[2][2]) {
            #pragma unroll
            for (int kk = 0; kk < 32; ++kk) {
                ulonglong2 av = *(const ulonglong2*)&sA[kk * 68 + 4 * ty];
                ulonglong2 wr = *(const ulonglong2*)&sW2[0 * 512 + kk * 16 + 2 * tx];
                ulonglong2 wz = *(const ulonglong2*)&sW2[1 * 512 + kk * 16 + 2 * tx];
                ulonglong2 wn = *(const ulonglong2*)&sW2[2 * 512 + kk * 16 + 2 * tx];
                fma2(aR[0][0], av.x, wr.x); fma2(aR[0][1], av.y, wr.x);
                fma2(aR[1][0], av.x, wr.y); fma2(aR[1][1], av.y, wr.y);
                fma2(aZ[0][0], av.x, wz.x); fma2(aZ[0][1], av.y, wz.x);
                fma2(aZ[1][0], av.x, wz.y); fma2(aZ[1][1], av.y, wz.y);
                fma2(aN[0][0], av.x, wn.x); fma2(aN[0][1], av.y, wn.x);
                fma2(aN[1][0], av.x, wn.y); fma2(aN[1][1], av.y, wn.y);
            }
        };

        for (int ch = 0; ch < 20; ++ch) {             // 20*32 = 640 = 512 + 128
            const int k0 = ch * 32;
            // load A chunk (64 b x 32 k), transposed
            #pragma unroll
            for (int r = 0; r < 4; ++r) {
                int idx = tid + r * 128;
                int b = idx >> 3, kq = idx & 7;
                const float* src = (k0 < Hh)
                    ? (hOld + b * Hh + k0 + 4 * kq)
                    : (x + b * (Tt * Ii) + t * Ii + (k0 - Hh) + 4 * kq);
                float4 v = *(const float4*)src;
                sA[(4 * kq + 0) * 68 + b] = v.x;
                sA[(4 * kq + 1) * 68 + b] = v.y;
                sA[(4 * kq + 2) * 68 + b] = v.z;
                sA[(4 * kq + 3) * 68 + b] = v.w;
            }
            // load 3 gate weight chunks (32 k x 16 j each)
            #pragma unroll
            for (int g = 0; g < 3; ++g) {
                #pragma unroll
                for (int r = 0; r < 4; ++r) {
                    int idx = tid + r * 128;
                    int kr = idx & 31, c = idx >> 5;
                    int row = jb + c + g * Hh;
                    int k = k0 + kr;
                    float w = (k < Hh) ? Whh[row * Hh + k]
                                       : Wih[row * Ii + (k - Hh)];
                    sW2[g * 512 + kr * 16 + c] = pack2(w, w);
                }
            }
            __syncthreads();
            if (ch < 16) inner(aNH); else inner(aNX);
            __syncthreads();
        }
        // epilogue
        #pragma unroll
        for (int cc = 0; cc < 2; ++cc) {
            int j = jb + 2 * tx + cc;
            float br  = bih[j]            + bhh[j];
            float bz  = bih[j + Hh]       + bhh[j + Hh];
            float bxn = bih[j + 2 * Hh];
            float bhn = bhh[j + 2 * Hh];
            float r_[4], z_[4], nh_[4], nx_[4];
            unpack2(aR [cc][0], r_[0],  r_[1]);  unpack2(aR [cc][1], r_[2],  r_[3]);
            unpack2(aZ [cc][0], z_[0],  z_[1]);  unpack2(aZ [cc][1], z_[2],  z_[3]);
            unpack2(aNH[cc][0], nh_[0], nh_[1]); unpack2(aNH[cc][1], nh_[2], nh_[3]);
            unpack2(aNX[cc][0], nx_[0], nx_[1]); unpack2(aNX[cc][1], nx_[2], nx_[3]);
            #pragma unroll
            for (int i = 0; i < 4; ++i) {
                int b = 4 * ty + i;
                float rr = sigm(r_[i] + br);
                float zz = sigm(z_[i] + bz);
                float nn = tanhf(nx_[i] + bxn + rr * (nh_[i] + bhn));
                hNew[b * Hh + j] = (1.0f - zz) * nn + zz * hOld[b * Hh + j];
            }
        }
    }
}

// ---------------- generic small GEMM: C[b][j] = act(sum_k A[b][k]*W[j][k] + bias[j]) ----------------
// grid.x = J/16, 256 threads. K multiple of 32. act: 0=none, 1=sigmoid, 2=relu
__global__ __launch_bounds__(256) void k_gemm(
    const float* __restrict__ A, const float* __restrict__ W,
    const float* __restrict__ bias, float* __restrict__ C,
    int K, int J, int act)
{
    __shared__ __align__(16) float sA[32 * 68];
    __shared__ float sW[32 * 16];
    const int tid = threadIdx.x;
    const int tx = tid & 15, ty = tid >> 4;
    const int jb = blockIdx.x * 16;
    float acc[4] = {0.f, 0.f, 0.f, 0.f};
    const int nch = K >> 5;
    for (int ch = 0; ch < nch; ++ch) {
        const int k0 = ch * 32;
        #pragma unroll
        for (int r = 0; r < 2; ++r) {
            int idx = tid + r * 256;
            int b = idx >> 3, kq = idx & 7;
            float4 v = *(const float4*)(A + b * K + k0 + 4 * kq);
            sA[(4 * kq + 0) * 68 + b] = v.x;
            sA[(4 * kq + 1) * 68 + b] = v.y;
            sA[(4 * kq + 2) * 68 + b] = v.z;
            sA[(4 * kq + 3) * 68 + b] = v.w;
        }
        #pragma unroll
        for (int r = 0; r < 2; ++r) {
            int idx = tid + r * 256;
            int kr = idx & 31, c = idx >> 5;
            sW[kr * 16 + c] = W[(jb + c) * K + k0 + kr];
        }
        __syncthreads();
        #pragma unroll
        for (int kk = 0; kk < 32; ++kk) {
            float w = sW[kk * 16 + tx];
            float4 a = *(const float4*)&sA[kk * 68 + 4 * ty];
            acc[0] += a.x * w; acc[1] += a.y * w;
            acc[2] += a.z * w; acc[3] += a.w * w;
        }
        __syncthreads();
    }
    const int j = jb + tx;
    const float bv = bias[j];
    #pragma unroll
    for (int i = 0; i < 4; ++i) {
        int b = 4 * ty + i;
        float v = acc[i] + bv;
        if (act == 1)      v = sigm(v);
        else if (act == 2) v = fmaxf(v, 0.0f);
        C[b * J + j] = v;
    }
}

// ---------------- small pointwise kernels ----------------
__global__ void k_cat() {
    int idx = blockIdx.x * blockDim.x + threadIdx.x;
    if (idx < Bb * 2 * Hh) {
        int b = idx >> 10, k = idx & 1023;
        g_cat[idx] = (k < Hh) ? g_proj[b * Hh + k] : g_hG[0][b * Hh + (k - Hh)];
    }
}
__global__ void k_combine() {
    int idx = blockIdx.x * blockDim.x + threadIdx.x;
    if (idx < Bb * Hh) {
        float g = g_gate[idx];
        g_comb[idx] = g * g_proj[idx] + (1.0f - g) * g_hG[0][idx];
    }
}

// ---------------- launch ----------------
extern "C" void kernel_launch(void* const* d_in, const int* in_sizes, int n_in,
                              void* d_out, int out_size)
{
    const float* x     = (const float*)d_in[0];
    const float* Win   = (const float*)d_in[1];
    const float* Wres  = (const float*)d_in[2];
    const float* Wih   = (const float*)d_in[3];
    const float* Whh   = (const float*)d_in[4];
    const float* bih   = (const float*)d_in[5];
    const float* bhh   = (const float*)d_in[6];
    const float* projW = (const float*)d_in[7];
    const float* projb = (const float*)d_in[8];
    const float* gateW = (const float*)d_in[9];
    const float* gateb = (const float*)d_in[10];
    const float* hW1   = (const float*)d_in[11];
    const float* hb1   = (const float*)d_in[12];
    const float* hW2   = (const float*)d_in[13];
    const float* hb2   = (const float*)d_in[14];
    float* out = (float*)d_out;

    void *pE, *pProj, *pCat, *pGate, *pComb, *pHid;
    cudaGetSymbolAddress(&pE,    g_hE);
    cudaGetSymbolAddress(&pProj, g_proj);
    cudaGetSymbolAddress(&pCat,  g_cat);
    cudaGetSymbolAddress(&pGate, g_gate);
    cudaGetSymbolAddress(&pComb, g_comb);
    cudaGetSymbolAddress(&pHid,  g_hid);

    k_init<<<512, 256>>>();
    for (int t = 0; t < Tt; ++t)
        k_step<<<160, 128>>>(x, Win, Wres, Wih, Whh, bih, bhh, t, t & 1);
    // final states: g_hE[0], g_hG[0]
    k_gemm<<<32, 256>>>((const float*)pE,   projW, projb, (float*)pProj, Rr,     Hh, 0);
    k_cat    <<<256, 256>>>();
    k_gemm<<<32, 256>>>((const float*)pCat, gateW, gateb, (float*)pGate, 2 * Hh, Hh, 1);
    k_combine<<<128, 256>>>();
    k_gemm<<<32, 256>>>((const float*)pComb, hW1,  hb1,   (float*)pHid,  Hh,     Hh, 2);
    k_gemm<<<8,  256>>>((const float*)pHid,  hW2,  hb2,   out,           Hh,     Oo, 0);
}

// round 3
// speedup vs baseline: 1.0574x; 1.0574x over previous
#include <cuda_runtime.h>
#include <math.h>

#define Bb 64
#define Tt 512
#define Ii 128
#define Rr 2048
#define Hh 512
#define Oo 128

typedef unsigned long long u64;

// ---------------- device scratch (static; no allocations) ----------------
__device__ float g_hE[2][Bb * Rr];   // ESN hidden, double buffered
__device__ float g_hG[2][Bb * Hh];   // GRU hidden, double buffered
__device__ float g_proj[Bb * Hh];
__device__ float g_cat [Bb * 2 * Hh];
__device__ float g_gate[Bb * Hh];
__device__ float g_comb[Bb * Hh];
__device__ float g_hid [Bb * Hh];

// ---------------- f32x2 helpers ----------------
__device__ __forceinline__ u64 pack2(float lo, float hi) {
    u64 r;
    asm("mov.b64 %0,{%1,%2};" : "=l"(r) : "f"(lo), "f"(hi));
    return r;
}
__device__ __forceinline__ void unpack2(u64 v, float& lo, float& hi) {
    asm("mov.b64 {%0,%1},%2;" : "=f"(lo), "=f"(hi) : "l"(v));
}
// packed fp32x2 fma: d = a*b + d (elementwise on the two f32 lanes)
__device__ __forceinline__ void fma2(u64& d, u64 a, u64 b) {
    asm("fma.rn.f32x2 %0,%1,%2,%0;" : "+l"(d) : "l"(a), "l"(b));
}

__device__ __forceinline__ float sigm(float x) { return 1.0f / (1.0f + expf(-x)); }

// ---------------- init: zero recurrent states ----------------
__global__ void k_init() {
    int i = blockIdx.x * blockDim.x + threadIdx.x;
    if (i < Bb * Rr) g_hE[0][i] = 0.0f;
    if (i < Bb * Hh) g_hG[0][i] = 0.0f;
}

// ---------------- fused per-timestep kernel ----------------
// grid = 160 blocks x 128 threads
//   bx in [0,128): ESN tile 64(b) x 16(cols), K = 2048 (h @ W_res) + 128 (x_t @ W_in)
//   bx in [128,160): GRU tile 64(b) x 16(j) x 3 gates, K = 512 (h @ W_hh^T) + 128 (x_t @ W_ih^T)
__global__ __launch_bounds__(128) void k_step(
    const float* __restrict__ x,    const float* __restrict__ Win,
    const float* __restrict__ Wres, const float* __restrict__ Wih,
    const float* __restrict__ Whh,  const float* __restrict__ bih,
    const float* __restrict__ bhh,  int t, int p)
{
    __shared__ __align__(16) float sA[32 * 68];     // A chunk transposed: sA[k][b]
    __shared__ __align__(16) u64   sW2[3 * 32 * 16];// weights as (w,w) pairs

    const int tid = threadIdx.x;
    const int tx  = tid & 7;     // column-pair index
    const int ty  = tid >> 3;    // batch quad index (0..15)
    const int bx  = blockIdx.x;

    if (bx < 128) {
        // ======================= ESN =======================
        const float* __restrict__ hOld = g_hE[p];
        float*       __restrict__ hNew = g_hE[p ^ 1];
        const int cb = bx * 16;

        u64 aE[2][2] = {{0ull, 0ull}, {0ull, 0ull}};  // [col][batch-pair]

        for (int ch = 0; ch < 68; ++ch) {             // 68*32 = 2176
            const int k0 = ch * 32;
            // load A chunk (64 b x 32 k), transposed
            #pragma unroll
            for (int r = 0; r < 4; ++r) {
                int idx = tid + r * 128;              // 0..511
                int b = idx >> 3, kq = idx & 7;
                const float* src = (k0 < Rr)
                    ? (hOld + b * Rr + k0 + 4 * kq)
                    : (x + b * (Tt * Ii) + t * Ii + (k0 - Rr) + 4 * kq);
                float4 v = *(const float4*)src;
                sA[(4 * kq + 0) * 68 + b] = v.x;
                sA[(4 * kq + 1) * 68 + b] = v.y;
                sA[(4 * kq + 2) * 68 + b] = v.z;
                sA[(4 * kq + 3) * 68 + b] = v.w;
            }
            // load W chunk (32 k x 16 c) as duplicated pairs
            #pragma unroll
            for (int r = 0; r < 4; ++r) {
                int idx = tid + r * 128;              // 0..511
                int kr = idx & 31, c = idx >> 5;
                int k = k0 + kr;
                float w = (k < Rr) ? Wres[k * Rr + cb + c]
                                   : Win[(k - Rr) * Rr + cb + c];
                sW2[kr * 16 + c] = pack2(w, w);
            }
            __syncthreads();
            #pragma unroll
            for (int kk = 0; kk < 32; ++kk) {
                ulonglong2 av = *(const ulonglong2*)&sA[kk * 68 + 4 * ty];
                ulonglong2 wv = *(const ulonglong2*)&sW2[kk * 16 + 2 * tx];
                fma2(aE[0][0], av.x, wv.x); fma2(aE[0][1], av.y, wv.x);
                fma2(aE[1][0], av.x, wv.y); fma2(aE[1][1], av.y, wv.y);
            }
            __syncthreads();
        }
        // epilogue: h' = 0.7 h + 0.3 tanh(acc)
        #pragma unroll
        for (int cc = 0; cc < 2; ++cc) {
            int c = cb + 2 * tx + cc;
            float v0, v1, v2, v3;
            unpack2(aE[cc][0], v0, v1);
            unpack2(aE[cc][1], v2, v3);
            int b0 = 4 * ty;
            hNew[(b0 + 0) * Rr + c] = 0.7f * hOld[(b0 + 0) * Rr + c] + 0.3f * tanhf(v0);
            hNew[(b0 + 1) * Rr + c] = 0.7f * hOld[(b0 + 1) * Rr + c] + 0.3f * tanhf(v1);
            hNew[(b0 + 2) * Rr + c] = 0.7f * hOld[(b0 + 2) * Rr + c] + 0.3f * tanhf(v2);
            hNew[(b0 + 3) * Rr + c] = 0.7f * hOld[(b0 + 3) * Rr + c] + 0.3f * tanhf(v3);
        }
    } else {
        // ======================= GRU =======================
        const float* __restrict__ hOld = g_hG[p];
        float*       __restrict__ hNew = g_hG[p ^ 1];
        const int jb = (bx - 128) * 16;

        u64 aR[2][2]  = {{0ull,0ull},{0ull,0ull}};
        u64 aZ[2][2]  = {{0ull,0ull},{0ull,0ull}};
        u64 aNH[2][2] = {{0ull,0ull},{0ull,0ull}};   // n-gate, h-part
        u64 aNX[2][2] = {{0ull,0ull},{0ull,0ull}};   // n-gate, x-part

        auto inner = [&](u64 (&aN)[2][2]) {
            #pragma unroll
            for (int kk = 0; kk < 32; ++kk) {
                ulonglong2 av = *(const ulonglong2*)&sA[kk * 68 + 4 * ty];
                ulonglong2 wr = *(const ulonglong2*)&sW2[0 * 512 + kk * 16 + 2 * tx];
                ulonglong2 wz = *(const ulonglong2*)&sW2[1 * 512 + kk * 16 + 2 * tx];
                ulonglong2 wn = *(const ulonglong2*)&sW2[2 * 512 + kk * 16 + 2 * tx];
                fma2(aR[0][0], av.x, wr.x); fma2(aR[0][1], av.y, wr.x);
                fma2(aR[1][0], av.x, wr.y); fma2(aR[1][1], av.y, wr.y);
                fma2(aZ[0][0], av.x, wz.x); fma2(aZ[0][1], av.y, wz.x);
                fma2(aZ[1][0], av.x, wz.y); fma2(aZ[1][1], av.y, wz.y);
                fma2(aN[0][0], av.x, wn.x); fma2(aN[0][1], av.y, wn.x);
                fma2(aN[1][0], av.x, wn.y); fma2(aN[1][1], av.y, wn.y);
            }
        };

        for (int ch = 0; ch < 20; ++ch) {             // 20*32 = 640 = 512 + 128
            const int k0 = ch * 32;
            // load A chunk (64 b x 32 k), transposed
            #pragma unroll
            for (int r = 0; r < 4; ++r) {
                int idx = tid + r * 128;
                int b = idx >> 3, kq = idx & 7;
                const float* src = (k0 < Hh)
                    ? (hOld + b * Hh + k0 + 4 * kq)
                    : (x + b * (Tt * Ii) + t * Ii + (k0 - Hh) + 4 * kq);
                float4 v = *(const float4*)src;
                sA[(4 * kq + 0) * 68 + b] = v.x;
                sA[(4 * kq + 1) * 68 + b] = v.y;
                sA[(4 * kq + 2) * 68 + b] = v.z;
                sA[(4 * kq + 3) * 68 + b] = v.w;
            }
            // load 3 gate weight chunks (32 k x 16 j each)
            #pragma unroll
            for (int g = 0; g < 3; ++g) {
                #pragma unroll
                for (int r = 0; r < 4; ++r) {
                    int idx = tid + r * 128;
                    int kr = idx & 31, c = idx >> 5;
                    int row = jb + c + g * Hh;
                    int k = k0 + kr;
                    float w = (k < Hh) ? Whh[row * Hh + k]
                                       : Wih[row * Ii + (k - Hh)];
                    sW2[g * 512 + kr * 16 + c] = pack2(w, w);
                }
            }
            __syncthreads();
            if (ch < 16) inner(aNH); else inner(aNX);
            __syncthreads();
        }
        // epilogue
        #pragma unroll
        for (int cc = 0; cc < 2; ++cc) {
            int j = jb + 2 * tx + cc;
            float br  = bih[j]            + bhh[j];
            float bz  = bih[j + Hh]       + bhh[j + Hh];
            float bxn = bih[j + 2 * Hh];
            float bhn = bhh[j + 2 * Hh];
            float r_[4], z_[4], nh_[4], nx_[4];
            unpack2(aR [cc][0], r_[0],  r_[1]);  unpack2(aR [cc][1], r_[2],  r_[3]);
            unpack2(aZ [cc][0], z_[0],  z_[1]);  unpack2(aZ [cc][1], z_[2],  z_[3]);
            unpack2(aNH[cc][0], nh_[0], nh_[1]); unpack2(aNH[cc][1], nh_[2], nh_[3]);
            unpack2(aNX[cc][0], nx_[0], nx_[1]); unpack2(aNX[cc][1], nx_[2], nx_[3]);
            #pragma unroll
            for (int i = 0; i < 4; ++i) {
                int b = 4 * ty + i;
                float rr = sigm(r_[i] + br);
                float zz = sigm(z_[i] + bz);
                float nn = tanhf(nx_[i] + bxn + rr * (nh_[i] + bhn));
                hNew[b * Hh + j] = (1.0f - zz) * nn + zz * hOld[b * Hh + j];
            }
        }
    }
}

// ---------------- generic small GEMM: C[b][j] = act(sum_k A[b][k]*W[j][k] + bias[j]) ----------------
// grid.x = J/16, 256 threads. K multiple of 32. act: 0=none, 1=sigmoid, 2=relu
__global__ __launch_bounds__(256) void k_gemm(
    const float* __restrict__ A, const float* __restrict__ W,
    const float* __restrict__ bias, float* __restrict__ C,
    int K, int J, int act)
{
    __shared__ __align__(16) float sA[32 * 68];
    __shared__ float sW[32 * 16];
    const int tid = threadIdx.x;
    const int tx = tid & 15, ty = tid >> 4;
    const int jb = blockIdx.x * 16;
    float acc[4] = {0.f, 0.f, 0.f, 0.f};
    const int nch = K >> 5;
    for (int ch = 0; ch < nch; ++ch) {
        const int k0 = ch * 32;
        #pragma unroll
        for (int r = 0; r < 2; ++r) {
            int idx = tid + r * 256;
            int b = idx >> 3, kq = idx & 7;
            float4 v = *(const float4*)(A + b * K + k0 + 4 * kq);
            sA[(4 * kq + 0) * 68 + b] = v.x;
            sA[(4 * kq + 1) * 68 + b] = v.y;
            sA[(4 * kq + 2) * 68 + b] = v.z;
            sA[(4 * kq + 3) * 68 + b] = v.w;
        }
        #pragma unroll
        for (int r = 0; r < 2; ++r) {
            int idx = tid + r * 256;
            int kr = idx & 31, c = idx >> 5;
            sW[kr * 16 + c] = W[(jb + c) * K + k0 + kr];
        }
        __syncthreads();
        #pragma unroll
        for (int kk = 0; kk < 32; ++kk) {
            float w = sW[kk * 16 + tx];
            float4 a = *(const float4*)&sA[kk * 68 + 4 * ty];
            acc[0] += a.x * w; acc[1] += a.y * w;
            acc[2] += a.z * w; acc[3] += a.w * w;
        }
        __syncthreads();
    }
    const int j = jb + tx;
    const float bv = bias[j];
    #pragma unroll
    for (int i = 0; i < 4; ++i) {
        int b = 4 * ty + i;
        float v = acc[i] + bv;
        if (act == 1)      v = sigm(v);
        else if (act == 2) v = fmaxf(v, 0.0f);
        C[b * J + j] = v;
    }
}

// ---------------- small pointwise kernels ----------------
__global__ void k_cat() {
    int idx = blockIdx.x * blockDim.x + threadIdx.x;
    if (idx < Bb * 2 * Hh) {
        int b = idx >> 10, k = idx & 1023;
        g_cat[idx] = (k < Hh) ? g_proj[b * Hh + k] : g_hG[0][b * Hh + (k - Hh)];
    }
}
__global__ void k_combine() {
    int idx = blockIdx.x * blockDim.x + threadIdx.x;
    if (idx < Bb * Hh) {
        float g = g_gate[idx];
        g_comb[idx] = g * g_proj[idx] + (1.0f - g) * g_hG[0][idx];
    }
}

// ---------------- launch ----------------
extern "C" void kernel_launch(void* const* d_in, const int* in_sizes, int n_in,
                              void* d_out, int out_size)
{
    const float* x     = (const float*)d_in[0];
    const float* Win   = (const float*)d_in[1];
    const float* Wres  = (const float*)d_in[2];
    const float* Wih   = (const float*)d_in[3];
    const float* Whh   = (const float*)d_in[4];
    const float* bih   = (const float*)d_in[5];
    const float* bhh   = (const float*)d_in[6];
    const float* projW = (const float*)d_in[7];
    const float* projb = (const float*)d_in[8];
    const float* gateW = (const float*)d_in[9];
    const float* gateb = (const float*)d_in[10];
    const float* hW1   = (const float*)d_in[11];
    const float* hb1   = (const float*)d_in[12];
    const float* hW2   = (const float*)d_in[13];
    const float* hb2   = (const float*)d_in[14];
    float* out = (float*)d_out;

    void *pE, *pProj, *pCat, *pGate, *pComb, *pHid;
    cudaGetSymbolAddress(&pE,    g_hE);
    cudaGetSymbolAddress(&pProj, g_proj);
    cudaGetSymbolAddress(&pCat,  g_cat);
    cudaGetSymbolAddress(&pGate, g_gate);
    cudaGetSymbolAddress(&pComb, g_comb);
    cudaGetSymbolAddress(&pHid,  g_hid);

    k_init<<<512, 256>>>();
    for (int t = 0; t < Tt; ++t)
        k_step<<<160, 128>>>(x, Win, Wres, Wih, Whh, bih, bhh, t, t & 1);
    // final states: g_hE[0], g_hG[0]
    k_gemm<<<32, 256>>>((const float*)pE,   projW, projb, (float*)pProj, Rr,     Hh, 0);
    k_cat    <<<256, 256>>>();
    k_gemm<<<32, 256>>>((const float*)pCat, gateW, gateb, (float*)pGate, 2 * Hh, Hh, 1);
    k_combine<<<128, 256>>>();
    k_gemm<<<32, 256>>>((const float*)pComb, hW1,  hb1,   (float*)pHid,  Hh,     Hh, 2);
    k_gemm<<<8,  256>>>((const float*)pHid,  hW2,  hb2,   out,           Hh,     Oo, 0);
}

// round 4
// speedup vs baseline: 2.0625x; 1.9505x over previous
#include <cuda_runtime.h>
#include <math.h>

#define Bb 64
#define Tt 512
#define Ii 128
#define Rr 2048
#define Hh 512
#define Oo 128

typedef unsigned long long u64;

__device__ float g_hE [2][Bb * Rr];
__device__ float g_hTE[2][Rr * Bb];
__device__ float g_hG [2][Bb * Hh];
__device__ float g_hTG[2][Hh * Bb];
__device__ float g_xT [Tt * Ii * Bb];
__device__ float g_proj[Bb * Hh];
__device__ float g_cat [Bb * 2 * Hh];
__device__ float g_gate[Bb * Hh];
__device__ float g_comb[Bb * Hh];
__device__ float g_hid [Bb * Hh];

__device__ __forceinline__ u64 dup2(float v) {
    u64 r; asm("mov.b64 %0,{%1,%1};" : "=l"(r) : "f"(v)); return r;
}
__device__ __forceinline__ void unpack2(u64 v, float& lo, float& hi) {
    asm("mov.b64 {%0,%1},%2;" : "=f"(lo), "=f"(hi) : "l"(v));
}
__device__ __forceinline__ void fma2(u64& d, u64 a, u64 b) {
    asm("fma.rn.f32x2 %0,%1,%2,%0;" : "+l"(d) : "l"(a), "l"(b));
}
__device__ __forceinline__ float sigm(float x) { return 1.0f / (1.0f + expf(-x)); }

__global__ void k_init() {
    int i = blockIdx.x * blockDim.x + threadIdx.x;
    if (i < Bb * Rr) { g_hE[0][i] = 0.0f; g_hTE[0][i] = 0.0f; }
    if (i < Bb * Hh) { g_hG[0][i] = 0.0f; g_hTG[0][i] = 0.0f; }
}

// x[b][t][i] -> xT[t][i][b]
__global__ void k_xT(const float* __restrict__ x) {
    int idx = blockIdx.x * blockDim.x + threadIdx.x;   // 4M
    int b = idx >> 16, rest = idx & 65535, t = rest >> 7, i = idx & 127;
    g_xT[(t * Ii + i) * Bb + b] = x[idx];
}

// ---------------- fused per-timestep kernel ----------------
// 160 blocks x 128 threads. bx<128: ESN 64b x 16c (K=2176). bx>=128: GRU 64b x 16j x 3g (K=640).
// Double-buffered: A chunk [32k][64b] (stride 68), W chunk as (w,w) u64 pairs (stride 18).
__global__ void __launch_bounds__(128) k_step(
    const float* __restrict__ Win,  const float* __restrict__ Wres,
    const float* __restrict__ Wih,  const float* __restrict__ Whh,
    const float* __restrict__ bih,  const float* __restrict__ bhh,
    int t, int p)
{
    __shared__ __align__(16) float sA[2][32 * 68];
    __shared__ __align__(16) u64   sW[2][3 * 32 * 18];

    const int tid = threadIdx.x;
    const int tx  = tid & 7;      // col/j pair
    const int ty  = tid >> 3;     // batch quad (0..15)
    const int bx  = blockIdx.x;
    const float* xTt = g_xT + t * (Ii * Bb);

    float4 rA[4];

    if (bx < 128) {
        // ======================= ESN =======================
        const float* __restrict__ hT   = g_hTE[p];
        const float* __restrict__ hOld = g_hE[p];
        float* __restrict__ hNew  = g_hE[p ^ 1];
        float* __restrict__ hTNew = g_hTE[p ^ 1];
        const int cb = bx * 16;
        float4 rW;

        auto ldA = [&](int k0) {
            #pragma unroll
            for (int i = 0; i < 4; ++i) {
                int flat = tid + i * 128;
                int bq = flat & 15, k = flat >> 4, kk = k0 + k;
                const float* row = (kk < Rr) ? (hT + kk * Bb) : (xTt + (kk - Rr) * Bb);
                rA[i] = *(const float4*)(row + 4 * bq);
            }
        };
        auto stA = [&](int buf) {
            #pragma unroll
            for (int i = 0; i < 4; ++i) {
                int flat = tid + i * 128;
                int bq = flat & 15, k = flat >> 4;
                *(float4*)&sA[buf][k * 68 + 4 * bq] = rA[i];
            }
        };
        auto ldW = [&](int k0) {
            int kr = tid >> 2, c4 = tid & 3, kk = k0 + kr;
            const float* row = (kk < Rr) ? (Wres + kk * Rr) : (Win + (kk - Rr) * Rr);
            rW = *(const float4*)(row + cb + 4 * c4);
        };
        auto stW = [&](int buf) {
            int kr = tid >> 2, c4 = tid & 3;
            u64* d = &sW[buf][kr * 18 + 4 * c4];
            d[0] = dup2(rW.x); d[1] = dup2(rW.y); d[2] = dup2(rW.z); d[3] = dup2(rW.w);
        };

        u64 acc[2][2] = {{0ull,0ull},{0ull,0ull}};   // [colpair][batchpair]

        ldA(0); ldW(0); stA(0); stW(0); __syncthreads();
        for (int ch = 0; ch < 68; ++ch) {
            const int cur = ch & 1;
            if (ch < 67) { ldA((ch + 1) * 32); ldW((ch + 1) * 32); }
            const float* A = sA[cur];
            const u64*   W = sW[cur];
            #pragma unroll
            for (int k = 0; k < 32; ++k) {
                ulonglong2 av = *(const ulonglong2*)&A[k * 68 + 4 * ty];
                ulonglong2 wv = *(const ulonglong2*)&W[k * 18 + 2 * tx];
                fma2(acc[0][0], av.x, wv.x); fma2(acc[0][1], av.y, wv.x);
                fma2(acc[1][0], av.x, wv.y); fma2(acc[1][1], av.y, wv.y);
            }
            if (ch < 67) { stA(cur ^ 1); stW(cur ^ 1); }
            __syncthreads();
        }
        #pragma unroll
        for (int cp = 0; cp < 2; ++cp) {
            const int c = cb + 2 * tx + cp;
            float v[4];
            unpack2(acc[cp][0], v[0], v[1]);
            unpack2(acc[cp][1], v[2], v[3]);
            float nv[4];
            const int b0 = 4 * ty;
            #pragma unroll
            for (int i = 0; i < 4; ++i) {
                nv[i] = 0.7f * hOld[(b0 + i) * Rr + c] + 0.3f * tanhf(v[i]);
                hNew[(b0 + i) * Rr + c] = nv[i];
            }
            *(float4*)&hTNew[c * Bb + b0] = make_float4(nv[0], nv[1], nv[2], nv[3]);
        }
    } else {
        // ======================= GRU =======================
        const float* __restrict__ hT   = g_hTG[p];
        const float* __restrict__ hOld = g_hG[p];
        float* __restrict__ hNew  = g_hG[p ^ 1];
        float* __restrict__ hTNew = g_hTG[p ^ 1];
        const int jb = (bx - 128) * 16;
        float4 rW[3];

        auto ldA = [&](int k0) {
            #pragma unroll
            for (int i = 0; i < 4; ++i) {
                int flat = tid + i * 128;
                int bq = flat & 15, k = flat >> 4, kk = k0 + k;
                const float* row = (kk < Hh) ? (hT + kk * Bb) : (xTt + (kk - Hh) * Bb);
                rA[i] = *(const float4*)(row + 4 * bq);
            }
        };
        auto stA = [&](int buf) {
            #pragma unroll
            for (int i = 0; i < 4; ++i) {
                int flat = tid + i * 128;
                int bq = flat & 15, k = flat >> 4;
                *(float4*)&sA[buf][k * 68 + 4 * bq] = rA[i];
            }
        };
        auto ldW = [&](int k0) {
            int j = tid >> 3, kq = tid & 7, k = k0 + 4 * kq;
            #pragma unroll
            for (int g = 0; g < 3; ++g) {
                int row = g * Hh + jb + j;
                rW[g] = (k < Hh) ? *(const float4*)(Whh + row * Hh + k)
                                 : *(const float4*)(Wih + row * Ii + (k - Hh));
            }
        };
        auto stW = [&](int buf) {
            int j = tid >> 3, kq = tid & 7;
            #pragma unroll
            for (int g = 0; g < 3; ++g) {
                u64* d = &sW[buf][g * 576 + (4 * kq) * 18 + j];
                d[0]  = dup2(rW[g].x); d[18] = dup2(rW[g].y);
                d[36] = dup2(rW[g].z); d[54] = dup2(rW[g].w);
            }
        };

        u64 aR[2][2] = {{0,0},{0,0}}, aZ[2][2] = {{0,0},{0,0}};
        u64 aNH[2][2] = {{0,0},{0,0}}, aNX[2][2] = {{0,0},{0,0}};

        ldA(0); ldW(0); stA(0); stW(0); __syncthreads();
        for (int ch = 0; ch < 20; ++ch) {
            const int cur = ch & 1;
            if (ch < 19) { ldA((ch + 1) * 32); ldW((ch + 1) * 32); }
            const float* A = sA[cur];
            const u64*   W = sW[cur];
            u64 (&aN)[2][2] = (ch < 16) ? aNH : aNX;
            #pragma unroll
            for (int k = 0; k < 32; ++k) {
                ulonglong2 av = *(const ulonglong2*)&A[k * 68 + 4 * ty];
                ulonglong2 wr = *(const ulonglong2*)&W[k * 18 + 2 * tx];
                ulonglong2 wz = *(const ulonglong2*)&W[576 + k * 18 + 2 * tx];
                ulonglong2 wn = *(const ulonglong2*)&W[1152 + k * 18 + 2 * tx];
                fma2(aR[0][0], av.x, wr.x); fma2(aR[0][1], av.y, wr.x);
                fma2(aR[1][0], av.x, wr.y); fma2(aR[1][1], av.y, wr.y);
                fma2(aZ[0][0], av.x, wz.x); fma2(aZ[0][1], av.y, wz.x);
                fma2(aZ[1][0], av.x, wz.y); fma2(aZ[1][1], av.y, wz.y);
                fma2(aN[0][0], av.x, wn.x); fma2(aN[0][1], av.y, wn.x);
                fma2(aN[1][0], av.x, wn.y); fma2(aN[1][1], av.y, wn.y);
            }
            if (ch < 19) { stA(cur ^ 1); stW(cur ^ 1); }
            __syncthreads();
        }
        #pragma unroll
        for (int jp = 0; jp < 2; ++jp) {
            const int j = jb + 2 * tx + jp;
            const float br = bih[j] + bhh[j];
            const float bz = bih[j + Hh] + bhh[j + Hh];
            const float bxn = bih[j + 2 * Hh], bhn = bhh[j + 2 * Hh];
            float r_[4], z_[4], nh_[4], nx_[4], nv[4];
            unpack2(aR [jp][0], r_[0],  r_[1]);  unpack2(aR [jp][1], r_[2],  r_[3]);
            unpack2(aZ [jp][0], z_[0],  z_[1]);  unpack2(aZ [jp][1], z_[2],  z_[3]);
            unpack2(aNH[jp][0], nh_[0], nh_[1]); unpack2(aNH[jp][1], nh_[2], nh_[3]);
            unpack2(aNX[jp][0], nx_[0], nx_[1]); unpack2(aNX[jp][1], nx_[2], nx_[3]);
            const int b0 = 4 * ty;
            #pragma unroll
            for (int i = 0; i < 4; ++i) {
                float rr = sigm(r_[i] + br);
                float zz = sigm(z_[i] + bz);
                float nn = tanhf(nx_[i] + bxn + rr * (nh_[i] + bhn));
                nv[i] = (1.0f - zz) * nn + zz * hOld[(b0 + i) * Hh + j];
                hNew[(b0 + i) * Hh + j] = nv[i];
            }
            *(float4*)&hTNew[j * Bb + b0] = make_float4(nv[0], nv[1], nv[2], nv[3]);
        }
    }
}

// ---------------- small GEMM: C[b][j] = act(A[b][:] . W[j][:] + bias[j]) ----------------
__global__ __launch_bounds__(256) void k_gemm(
    const float* __restrict__ A, const float* __restrict__ W,
    const float* __restrict__ bias, float* __restrict__ C,
    int K, int J, int act)
{
    __shared__ __align__(16) float sA[32 * 68];
    __shared__ float sW[32 * 16];
    const int tid = threadIdx.x;
    const int tx = tid & 15, ty = tid >> 4;
    const int jb = blockIdx.x * 16;
    float acc[4] = {0.f, 0.f, 0.f, 0.f};
    for (int ch = 0; ch < (K >> 5); ++ch) {
        const int k0 = ch * 32;
        #pragma unroll
        for (int r = 0; r < 2; ++r) {
            int idx = tid + r * 256;
            int b = idx >> 3, kq = idx & 7;
            float4 v = *(const float4*)(A + b * K + k0 + 4 * kq);
            sA[(4 * kq + 0) * 68 + b] = v.x; sA[(4 * kq + 1) * 68 + b] = v.y;
            sA[(4 * kq + 2) * 68 + b] = v.z; sA[(4 * kq + 3) * 68 + b] = v.w;
        }
        #pragma unroll
        for (int r = 0; r < 2; ++r) {
            int idx = tid + r * 256;
            int kr = idx & 31, c = idx >> 5;
            sW[kr * 16 + c] = W[(jb + c) * K + k0 + kr];
        }
        __syncthreads();
        #pragma unroll
        for (int kk = 0; kk < 32; ++kk) {
            float w = sW[kk * 16 + tx];
            float4 a = *(const float4*)&sA[kk * 68 + 4 * ty];
            acc[0] += a.x * w; acc[1] += a.y * w;
            acc[2] += a.z * w; acc[3] += a.w * w;
        }
        __syncthreads();
    }
    const int j = jb + tx;
    const float bv = bias[j];
    #pragma unroll
    for (int i = 0; i < 4; ++i) {
        float v = acc[i] + bv;
        if (act == 1) v = sigm(v);
        else if (act == 2) v = fmaxf(v, 0.0f);
        C[(4 * ty + i) * J + j] = v;
    }
}

__global__ void k_cat() {
    int idx = blockIdx.x * blockDim.x + threadIdx.x;
    if (idx < Bb * 2 * Hh) {
        int b = idx >> 10, k = idx & 1023;
        g_cat[idx] = (k < Hh) ? g_proj[b * Hh + k] : g_hG[0][b * Hh + (k - Hh)];
    }
}
__global__ void k_combine() {
    int idx = blockIdx.x * blockDim.x + threadIdx.x;
    if (idx < Bb * Hh) {
        float g = g_gate[idx];
        g_comb[idx] = g * g_proj[idx] + (1.0f - g) * g_hG[0][idx];
    }
}

extern "C" void kernel_launch(void* const* d_in, const int* in_sizes, int n_in,
                              void* d_out, int out_size)
{
    const float* x     = (const float*)d_in[0];
    const float* Win   = (const float*)d_in[1];
    const float* Wres  = (const float*)d_in[2];
    const float* Wih   = (const float*)d_in[3];
    const float* Whh   = (const float*)d_in[4];
    const float* bih   = (const float*)d_in[5];
    const float* bhh   = (const float*)d_in[6];
    const float* projW = (const float*)d_in[7];
    const float* projb = (const float*)d_in[8];
    const float* gateW = (const float*)d_in[9];
    const float* gateb = (const float*)d_in[10];
    const float* hW1   = (const float*)d_in[11];
    const float* hb1   = (const float*)d_in[12];
    const float* hW2   = (const float*)d_in[13];
    const float* hb2   = (const float*)d_in[14];
    float* out = (float*)d_out;

    void *pE, *pProj, *pCat, *pGate, *pComb, *pHid;
    cudaGetSymbolAddress(&pE,    g_hE);
    cudaGetSymbolAddress(&pProj, g_proj);
    cudaGetSymbolAddress(&pCat,  g_cat);
    cudaGetSymbolAddress(&pGate, g_gate);
    cudaGetSymbolAddress(&pComb, g_comb);
    cudaGetSymbolAddress(&pHid,  g_hid);

    k_init<<<512, 256>>>();
    k_xT<<<16384, 256>>>(x);
    for (int t = 0; t < Tt; ++t)
        k_step<<<160, 128>>>(Win, Wres, Wih, Whh, bih, bhh, t, t & 1);
    k_gemm<<<32, 256>>>((const float*)pE,   projW, projb, (float*)pProj, Rr,     Hh, 0);
    k_cat    <<<256, 256>>>();
    k_gemm<<<32, 256>>>((const float*)pCat, gateW, gateb, (float*)pGate, 2 * Hh, Hh, 1);
    k_combine<<<128, 256>>>();
    k_gemm<<<32, 256>>>((const float*)pComb, hW1,  hb1,   (float*)pHid,  Hh,     Hh, 2);
    k_gemm<<<8,  256>>>((const float*)pHid,  hW2,  hb2,   out,           Hh,     Oo, 0);
}

// round 5
// speedup vs baseline: 2.1526x; 1.0437x over previous
#include <cuda_runtime.h>
#include <math.h>

#define Bb 64
#define Tt 512
#define Ii 128
#define Rr 2048
#define Hh 512
#define Oo 128

typedef unsigned long long u64;

__device__ float g_hE [2][Bb * Rr];
__device__ float g_hTE[2][Rr * Bb];
__device__ float g_hG [2][Bb * Hh];
__device__ float g_hTG[2][Hh * Bb];
__device__ float g_xT [Tt * Ii * Bb];
__device__ float g_proj[Bb * Hh];
__device__ float g_cat [Bb * 2 * Hh];
__device__ float g_gate[Bb * Hh];
__device__ float g_comb[Bb * Hh];
__device__ float g_hid [Bb * Hh];

__device__ __forceinline__ u64 dup2(float v) {
    u64 r; asm("mov.b64 %0,{%1,%1};" : "=l"(r) : "f"(v)); return r;
}
__device__ __forceinline__ void unpack2(u64 v, float& lo, float& hi) {
    asm("mov.b64 {%0,%1},%2;" : "=f"(lo), "=f"(hi) : "l"(v));
}
__device__ __forceinline__ void fma2(u64& d, u64 a, u64 b) {
    asm("fma.rn.f32x2 %0,%1,%2,%0;" : "+l"(d) : "l"(a), "l"(b));
}
__device__ __forceinline__ u64 add2(u64 a, u64 b) {
    u64 r; asm("add.rn.f32x2 %0,%1,%2;" : "=l"(r) : "l"(a), "l"(b)); return r;
}
__device__ __forceinline__ float sigm(float x) { return 1.0f / (1.0f + expf(-x)); }
__device__ __forceinline__ void barg(int id) {
    asm volatile("bar.sync %0, 128;" :: "r"(id) : "memory");
}

__global__ void k_init() {
    int i = blockIdx.x * blockDim.x + threadIdx.x;
    if (i < Bb * Rr) { g_hE[0][i] = 0.0f; g_hTE[0][i] = 0.0f; }
    if (i < Bb * Hh) { g_hG[0][i] = 0.0f; g_hTG[0][i] = 0.0f; }
}

__global__ void k_xT(const float* __restrict__ x) {
    int idx = blockIdx.x * blockDim.x + threadIdx.x;
    int b = idx >> 16, rest = idx & 65535, t = rest >> 7, i = idx & 127;
    g_xT[(t * Ii + i) * Bb + b] = x[idx];
}

// ---------------- fused per-timestep kernel ----------------
// 160 blocks x 256 threads (2 warp-groups of 128, K-split).
//   bx<128 : ESN tile 64b x 16c, K=2176 -> 34 chunks/group
//   bx>=128: GRU tile 64b x 16j x 3 gates, K=640 -> 10 chunks/group
__global__ void __launch_bounds__(256) k_step(
    const float* __restrict__ Win,  const float* __restrict__ Wres,
    const float* __restrict__ Wih,  const float* __restrict__ Whh,
    const float* __restrict__ bih,  const float* __restrict__ bhh,
    int t, int p)
{
    __shared__ __align__(16) float sA[2][32 * 68];       // per-group A chunk
    __shared__ __align__(16) u64   sW[2][3 * 32 * 18];   // per-group W chunk (dup pairs)

    const int tid = threadIdx.x;
    const int grp = tid >> 7;           // warp-group 0/1
    const int lt  = tid & 127;
    const int tx  = lt & 7;             // col/j pair
    const int ty  = lt >> 3;            // batch quad (0..15)
    const int bar_id = 1 + grp;
    const int bx  = blockIdx.x;
    const float* xTt = g_xT + t * (Ii * Bb);

    float4 rA[4];

    if (bx < 128) {
        // ======================= ESN =======================
        const float* __restrict__ hT   = g_hTE[p];
        const float* __restrict__ hOld = g_hE[p];
        float* __restrict__ hNew  = g_hE[p ^ 1];
        float* __restrict__ hTNew = g_hTE[p ^ 1];
        const int cb = bx * 16;
        float4 rW;

        auto ldA = [&](int k0) {
            #pragma unroll
            for (int i = 0; i < 4; ++i) {
                int flat = lt + i * 128;
                int bq = flat & 15, k = flat >> 4, kk = k0 + k;
                const float* row = (kk < Rr) ? (hT + kk * Bb) : (xTt + (kk - Rr) * Bb);
                rA[i] = *(const float4*)(row + 4 * bq);
            }
        };
        auto stA = [&]() {
            #pragma unroll
            for (int i = 0; i < 4; ++i) {
                int flat = lt + i * 128;
                int bq = flat & 15, k = flat >> 4;
                *(float4*)&sA[grp][k * 68 + 4 * bq] = rA[i];
            }
        };
        auto ldW = [&](int k0) {
            int kr = lt >> 2, c4 = lt & 3, kk = k0 + kr;
            const float* row = (kk < Rr) ? (Wres + kk * Rr) : (Win + (kk - Rr) * Rr);
            rW = *(const float4*)(row + cb + 4 * c4);
        };
        auto stW = [&]() {
            int kr = lt >> 2, c4 = lt & 3;
            u64* d = &sW[grp][kr * 18 + 4 * c4];
            d[0] = dup2(rW.x); d[1] = dup2(rW.y); d[2] = dup2(rW.z); d[3] = dup2(rW.w);
        };

        u64 acc[2][2] = {{0ull,0ull},{0ull,0ull}};   // [colpair][batchpair]

        const int cbase = grp * 34;
        ldA(cbase * 32); ldW(cbase * 32);
        for (int c = 0; c < 34; ++c) {
            stA(); stW();
            barg(bar_id);
            if (c < 33) { int kn = (cbase + c + 1) * 32; ldA(kn); ldW(kn); }
            const float* A = sA[grp];
            const u64*   W = sW[grp];
            #pragma unroll
            for (int k = 0; k < 32; ++k) {
                ulonglong2 av = *(const ulonglong2*)&A[k * 68 + 4 * ty];
                ulonglong2 wv = *(const ulonglong2*)&W[k * 18 + 2 * tx];
                fma2(acc[0][0], av.x, wv.x); fma2(acc[0][1], av.y, wv.x);
                fma2(acc[1][0], av.x, wv.y); fma2(acc[1][1], av.y, wv.y);
            }
            barg(bar_id);
        }

        // cross-group reduction through smem, then epilogue by group 0
        u64* red = (u64*)&sA[0][0];
        __syncthreads();
        if (grp == 1) {
            red[lt * 4 + 0] = acc[0][0]; red[lt * 4 + 1] = acc[0][1];
            red[lt * 4 + 2] = acc[1][0]; red[lt * 4 + 3] = acc[1][1];
        }
        __syncthreads();
        if (grp == 0) {
            acc[0][0] = add2(acc[0][0], red[lt * 4 + 0]);
            acc[0][1] = add2(acc[0][1], red[lt * 4 + 1]);
            acc[1][0] = add2(acc[1][0], red[lt * 4 + 2]);
            acc[1][1] = add2(acc[1][1], red[lt * 4 + 3]);
            #pragma unroll
            for (int cp = 0; cp < 2; ++cp) {
                const int c = cb + 2 * tx + cp;
                float v[4], nv[4];
                unpack2(acc[cp][0], v[0], v[1]);
                unpack2(acc[cp][1], v[2], v[3]);
                const int b0 = 4 * ty;
                #pragma unroll
                for (int i = 0; i < 4; ++i) {
                    nv[i] = 0.7f * hOld[(b0 + i) * Rr + c] + 0.3f * tanhf(v[i]);
                    hNew[(b0 + i) * Rr + c] = nv[i];
                }
                *(float4*)&hTNew[c * Bb + b0] = make_float4(nv[0], nv[1], nv[2], nv[3]);
            }
        }
    } else {
        // ======================= GRU =======================
        const float* __restrict__ hT   = g_hTG[p];
        const float* __restrict__ hOld = g_hG[p];
        float* __restrict__ hNew  = g_hG[p ^ 1];
        float* __restrict__ hTNew = g_hTG[p ^ 1];
        const int jb = (bx - 128) * 16;
        float4 rW[3];

        auto ldA = [&](int k0) {
            #pragma unroll
            for (int i = 0; i < 4; ++i) {
                int flat = lt + i * 128;
                int bq = flat & 15, k = flat >> 4, kk = k0 + k;
                const float* row = (kk < Hh) ? (hT + kk * Bb) : (xTt + (kk - Hh) * Bb);
                rA[i] = *(const float4*)(row + 4 * bq);
            }
        };
        auto stA = [&]() {
            #pragma unroll
            for (int i = 0; i < 4; ++i) {
                int flat = lt + i * 128;
                int bq = flat & 15, k = flat >> 4;
                *(float4*)&sA[grp][k * 68 + 4 * bq] = rA[i];
            }
        };
        auto ldW = [&](int k0) {
            int j = lt >> 3, kq = lt & 7, k = k0 + 4 * kq;
            #pragma unroll
            for (int g = 0; g < 3; ++g) {
                int row = g * Hh + jb + j;
                rW[g] = (k < Hh) ? *(const float4*)(Whh + row * Hh + k)
                                 : *(const float4*)(Wih + row * Ii + (k - Hh));
            }
        };
        auto stW = [&]() {
            int j = lt >> 3, kq = lt & 7;
            #pragma unroll
            for (int g = 0; g < 3; ++g) {
                u64* d = &sW[grp][g * 576 + (4 * kq) * 18 + j];
                d[0]  = dup2(rW[g].x); d[18] = dup2(rW[g].y);
                d[36] = dup2(rW[g].z); d[54] = dup2(rW[g].w);
            }
        };

        u64 aR[2][2] = {{0,0},{0,0}}, aZ[2][2] = {{0,0},{0,0}};
        u64 aNH[2][2] = {{0,0},{0,0}}, aNX[2][2] = {{0,0},{0,0}};

        const int cbase = grp * 10;
        ldA(cbase * 32); ldW(cbase * 32);
        for (int c = 0; c < 10; ++c) {
            stA(); stW();
            barg(bar_id);
            if (c < 9) { int kn = (cbase + c + 1) * 32; ldA(kn); ldW(kn); }
            const float* A = sA[grp];
            const u64*   W = sW[grp];
            u64 (&aN)[2][2] = ((cbase + c) < 16) ? aNH : aNX;
            #pragma unroll
            for (int k = 0; k < 32; ++k) {
                ulonglong2 av = *(const ulonglong2*)&A[k * 68 + 4 * ty];
                ulonglong2 wr = *(const ulonglong2*)&W[k * 18 + 2 * tx];
                ulonglong2 wz = *(const ulonglong2*)&W[576 + k * 18 + 2 * tx];
                ulonglong2 wn = *(const ulonglong2*)&W[1152 + k * 18 + 2 * tx];
                fma2(aR[0][0], av.x, wr.x); fma2(aR[0][1], av.y, wr.x);
                fma2(aR[1][0], av.x, wr.y); fma2(aR[1][1], av.y, wr.y);
                fma2(aZ[0][0], av.x, wz.x); fma2(aZ[0][1], av.y, wz.x);
                fma2(aZ[1][0], av.x, wz.y); fma2(aZ[1][1], av.y, wz.y);
                fma2(aN[0][0], av.x, wn.x); fma2(aN[0][1], av.y, wn.x);
                fma2(aN[1][0], av.x, wn.y); fma2(aN[1][1], av.y, wn.y);
            }
            barg(bar_id);
        }

        u64* red = (u64*)&sA[0][0];
        __syncthreads();
        if (grp == 1) {
            u64* d = red + lt * 16;
            d[0]=aR[0][0];  d[1]=aR[0][1];  d[2]=aR[1][0];  d[3]=aR[1][1];
            d[4]=aZ[0][0];  d[5]=aZ[0][1];  d[6]=aZ[1][0];  d[7]=aZ[1][1];
            d[8]=aNH[0][0]; d[9]=aNH[0][1]; d[10]=aNH[1][0];d[11]=aNH[1][1];
            d[12]=aNX[0][0];d[13]=aNX[0][1];d[14]=aNX[1][0];d[15]=aNX[1][1];
        }
        __syncthreads();
        if (grp == 0) {
            const u64* d = red + lt * 16;
            aR[0][0]=add2(aR[0][0],d[0]);   aR[0][1]=add2(aR[0][1],d[1]);
            aR[1][0]=add2(aR[1][0],d[2]);   aR[1][1]=add2(aR[1][1],d[3]);
            aZ[0][0]=add2(aZ[0][0],d[4]);   aZ[0][1]=add2(aZ[0][1],d[5]);
            aZ[1][0]=add2(aZ[1][0],d[6]);   aZ[1][1]=add2(aZ[1][1],d[7]);
            aNH[0][0]=add2(aNH[0][0],d[8]); aNH[0][1]=add2(aNH[0][1],d[9]);
            aNH[1][0]=add2(aNH[1][0],d[10]);aNH[1][1]=add2(aNH[1][1],d[11]);
            aNX[0][0]=add2(aNX[0][0],d[12]);aNX[0][1]=add2(aNX[0][1],d[13]);
            aNX[1][0]=add2(aNX[1][0],d[14]);aNX[1][1]=add2(aNX[1][1],d[15]);
            #pragma unroll
            for (int jp = 0; jp < 2; ++jp) {
                const int j = jb + 2 * tx + jp;
                const float br = bih[j] + bhh[j];
                const float bz = bih[j + Hh] + bhh[j + Hh];
                const float bxn = bih[j + 2 * Hh], bhn = bhh[j + 2 * Hh];
                float r_[4], z_[4], nh_[4], nx_[4], nv[4];
                unpack2(aR [jp][0], r_[0],  r_[1]);  unpack2(aR [jp][1], r_[2],  r_[3]);
                unpack2(aZ [jp][0], z_[0],  z_[1]);  unpack2(aZ [jp][1], z_[2],  z_[3]);
                unpack2(aNH[jp][0], nh_[0], nh_[1]); unpack2(aNH[jp][1], nh_[2], nh_[3]);
                unpack2(aNX[jp][0], nx_[0], nx_[1]); unpack2(aNX[jp][1], nx_[2], nx_[3]);
                const int b0 = 4 * ty;
                #pragma unroll
                for (int i = 0; i < 4; ++i) {
                    float rr = sigm(r_[i] + br);
                    float zz = sigm(z_[i] + bz);
                    float nn = tanhf(nx_[i] + bxn + rr * (nh_[i] + bhn));
                    nv[i] = (1.0f - zz) * nn + zz * hOld[(b0 + i) * Hh + j];
                    hNew[(b0 + i) * Hh + j] = nv[i];
                }
                *(float4*)&hTNew[j * Bb + b0] = make_float4(nv[0], nv[1], nv[2], nv[3]);
            }
        }
    }
}

// ---------------- small GEMM: C[b][j] = act(A[b][:] . W[j][:] + bias[j]) ----------------
__global__ __launch_bounds__(256) void k_gemm(
    const float* __restrict__ A, const float* __restrict__ W,
    const float* __restrict__ bias, float* __restrict__ C,
    int K, int J, int act)
{
    __shared__ __align__(16) float sA[32 * 68];
    __shared__ float sW[32 * 16];
    const int tid = threadIdx.x;
    const int tx = tid & 15, ty = tid >> 4;
    const int jb = blockIdx.x * 16;
    float acc[4] = {0.f, 0.f, 0.f, 0.f};
    for (int ch = 0; ch < (K >> 5); ++ch) {
        const int k0 = ch * 32;
        #pragma unroll
        for (int r = 0; r < 2; ++r) {
            int idx = tid + r * 256;
            int b = idx >> 3, kq = idx & 7;
            float4 v = *(const float4*)(A + b * K + k0 + 4 * kq);
            sA[(4 * kq + 0) * 68 + b] = v.x; sA[(4 * kq + 1) * 68 + b] = v.y;
            sA[(4 * kq + 2) * 68 + b] = v.z; sA[(4 * kq + 3) * 68 + b] = v.w;
        }
        #pragma unroll
        for (int r = 0; r < 2; ++r) {
            int idx = tid + r * 256;
            int kr = idx & 31, c = idx >> 5;
            sW[kr * 16 + c] = W[(jb + c) * K + k0 + kr];
        }
        __syncthreads();
        #pragma unroll
        for (int kk = 0; kk < 32; ++kk) {
            float w = sW[kk * 16 + tx];
            float4 a = *(const float4*)&sA[kk * 68 + 4 * ty];
            acc[0] += a.x * w; acc[1] += a.y * w;
            acc[2] += a.z * w; acc[3] += a.w * w;
        }
        __syncthreads();
    }
    const int j = jb + tx;
    const float bv = bias[j];
    #pragma unroll
    for (int i = 0; i < 4; ++i) {
        float v = acc[i] + bv;
        if (act == 1) v = sigm(v);
        else if (act == 2) v = fmaxf(v, 0.0f);
        C[(4 * ty + i) * J + j] = v;
    }
}

__global__ void k_cat() {
    int idx = blockIdx.x * blockDim.x + threadIdx.x;
    if (idx < Bb * 2 * Hh) {
        int b = idx >> 10, k = idx & 1023;
        g_cat[idx] = (k < Hh) ? g_proj[b * Hh + k] : g_hG[0][b * Hh + (k - Hh)];
    }
}
__global__ void k_combine() {
    int idx = blockIdx.x * blockDim.x + threadIdx.x;
    if (idx < Bb * Hh) {
        float g = g_gate[idx];
        g_comb[idx] = g * g_proj[idx] + (1.0f - g) * g_hG[0][idx];
    }
}

extern "C" void kernel_launch(void* const* d_in, const int* in_sizes, int n_in,
                              void* d_out, int out_size)
{
    const float* x     = (const float*)d_in[0];
    const float* Win   = (const float*)d_in[1];
    const float* Wres  = (const float*)d_in[2];
    const float* Wih   = (const float*)d_in[3];
    const float* Whh   = (const float*)d_in[4];
    const float* bih   = (const float*)d_in[5];
    const float* bhh   = (const float*)d_in[6];
    const float* projW = (const float*)d_in[7];
    const float* projb = (const float*)d_in[8];
    const float* gateW = (const float*)d_in[9];
    const float* gateb = (const float*)d_in[10];
    const float* hW1   = (const float*)d_in[11];
    const float* hb1   = (const float*)d_in[12];
    const float* hW2   = (const float*)d_in[13];
    const float* hb2   = (const float*)d_in[14];
    float* out = (float*)d_out;

    void *pE, *pProj, *pCat, *pGate, *pComb, *pHid;
    cudaGetSymbolAddress(&pE,    g_hE);
    cudaGetSymbolAddress(&pProj, g_proj);
    cudaGetSymbolAddress(&pCat,  g_cat);
    cudaGetSymbolAddress(&pGate, g_gate);
    cudaGetSymbolAddress(&pComb, g_comb);
    cudaGetSymbolAddress(&pHid,  g_hid);

    k_init<<<512, 256>>>();
    k_xT<<<16384, 256>>>(x);
    for (int t = 0; t < Tt; ++t)
        k_step<<<160, 256>>>(Win, Wres, Wih, Whh, bih, bhh, t, t & 1);
    k_gemm<<<32, 256>>>((const float*)pE,   projW, projb, (float*)pProj, Rr,     Hh, 0);
    k_cat    <<<256, 256>>>();
    k_gemm<<<32, 256>>>((const float*)pCat, gateW, gateb, (float*)pGate, 2 * Hh, Hh, 1);
    k_combine<<<128, 256>>>();
    k_gemm<<<32, 256>>>((const float*)pComb, hW1,  hb1,   (float*)pHid,  Hh,     Hh, 2);
    k_gemm<<<8,  256>>>((const float*)pHid,  hW2,  hb2,   out,           Hh,     Oo, 0);
}

// round 7
// speedup vs baseline: 4.1418x; 1.9241x over previous
#include <cuda_runtime.h>
#include <cuda_bf16.h>
#include <math.h>

#define Bb 64
#define Tt 512
#define Ii 128
#define Rr 2048
#define Hh 512
#define Oo 128
#define KE 2176
#define KG 640
#define MG 1536
#define NBLK 88

typedef __nv_bfloat16 bf;

// ---------------- device scratch ----------------
__device__ bf WEh[Rr*KE], WEl[Rr*KE];      // ESN weights^T hi/lo  [c][k]
__device__ bf WGh[MG*KG], WGl[MG*KG];      // GRU weights^T hi/lo  [m][k]
__device__ bf Xh[Tt*Ii*Bb], Xl[Tt*Ii*Bb];  // x transposed hi/lo   [t][i][b]
__device__ bf HEh[Rr*Bb], HEl[Rr*Bb];      // ESN state bf16       [c][b]
__device__ bf HGh[Hh*Bb], HGl[Hh*Bb];      // GRU state bf16       [j][b]
__device__ float hET[Rr*Bb], hGT[Hh*Bb];   // fp32 states (transposed)
__device__ float accE[4][Rr*Bb];
__device__ float accG[2][MG*Bb];
__device__ unsigned g_ctr;
__device__ float g_hE[Bb*Rr], g_hG[Bb*Hh];
__device__ float g_proj[Bb*Hh], g_cat[Bb*2*Hh], g_gate[Bb*Hh], g_comb[Bb*Hh], g_hid[Bb*Hh];

__device__ __forceinline__ float sigm(float x){ return 1.0f/(1.0f+expf(-x)); }
__device__ __forceinline__ void bsplit(float v, bf* ph, bf* pl){
    bf h = __float2bfloat16(v); *ph = h; *pl = __float2bfloat16(v - __bfloat162float(h));
}
__device__ __forceinline__ void ldsm4(unsigned* r, const bf* p){
    unsigned a = (unsigned)__cvta_generic_to_shared(p);
    asm volatile("ldmatrix.sync.aligned.m8n8.x4.shared.b16 {%0,%1,%2,%3},[%4];"
        : "=r"(r[0]),"=r"(r[1]),"=r"(r[2]),"=r"(r[3]) : "r"(a));
}
__device__ __forceinline__ void ldsm4t(unsigned* r, const bf* p){
    unsigned a = (unsigned)__cvta_generic_to_shared(p);
    asm volatile("ldmatrix.sync.aligned.m8n8.x4.trans.shared.b16 {%0,%1,%2,%3},[%4];"
        : "=r"(r[0]),"=r"(r[1]),"=r"(r[2]),"=r"(r[3]) : "r"(a));
}
__device__ __forceinline__ void mma_bf(float* d, const unsigned* a, const unsigned* b){
    asm volatile("mma.sync.aligned.m16n8k16.row.col.f32.bf16.bf16.f32 "
        "{%0,%1,%2,%3},{%4,%5,%6,%7},{%8,%9},{%0,%1,%2,%3};"
        : "+f"(d[0]),"+f"(d[1]),"+f"(d[2]),"+f"(d[3])
        : "r"(a[0]),"r"(a[1]),"r"(a[2]),"r"(a[3]),"r"(b[0]),"r"(b[1]));
}

// ---------------- prep ----------------
__global__ void k_prepWE(const float* __restrict__ Wres, const float* __restrict__ Win){
    int idx = blockIdx.x*blockDim.x + threadIdx.x;        // c*KE + k
    int c = idx/KE, k = idx - c*KE;
    float w = (k < Rr) ? Wres[k*Rr + c] : Win[(k-Rr)*Rr + c];
    bsplit(w, &WEh[idx], &WEl[idx]);
}
__global__ void k_prepWG(const float* __restrict__ Whh, const float* __restrict__ Wih){
    int idx = blockIdx.x*blockDim.x + threadIdx.x;        // m*KG + k
    int m = idx/KG, k = idx - m*KG;
    float w = (k < Hh) ? Whh[m*Hh + k] : Wih[m*Ii + (k-Hh)];
    bsplit(w, &WGh[idx], &WGl[idx]);
}
__global__ void k_prepX(const float* __restrict__ x){
    int idx = blockIdx.x*blockDim.x + threadIdx.x;        // t*8192 + i*64 + b
    int t = idx >> 13, r = idx & 8191, i = r >> 6, b = r & 63;
    bsplit(x[b*(Tt*Ii) + t*Ii + i], &Xh[idx], &Xl[idx]);
}
__global__ void k_init0(){
    int i = blockIdx.x*blockDim.x + threadIdx.x;
    bf z = __float2bfloat16(0.0f);
    if(i == 0) g_ctr = 0u;
    if(i < Rr*Bb){ hET[i]=0.0f; HEh[i]=z; HEl[i]=z; }
    if(i < Hh*Bb){ hGT[i]=0.0f; HGh[i]=z; HGl[i]=z; }
}

// ---------------- per-step fused MMA + epilogue kernel ----------------
// 88 blocks x 128 thr (single wave -> spin barrier is safe).
// bx<64: ESN (m-tile bx>>2, K-split bx&3, 34 k16 chunks).
// bx>=64: GRU (m-tile g>>1; split0=h K[0,512) 32 chunks, split1=x K[512,640) 8 chunks).
#define SWS 24
#define SBS 72
__global__ void __launch_bounds__(128) k_mma(int t,
    const float* __restrict__ bih, const float* __restrict__ bhh)
{
    __shared__ __align__(16) bf sW[2][2][128*SWS];
    __shared__ __align__(16) bf sB[2][2][16*SBS];
    const int tid = threadIdx.x, lane = tid & 31, wid = tid >> 5, bx = blockIdx.x;

    const bf *Wh, *Wl, *Bh, *Bl; float* acc; int Kst, kbase, nch, kth;
    if(bx < 64){
        int m0 = (bx>>2)*128, ks = bx&3;
        kbase = ks*544; nch = 34; kth = Rr; Kst = KE;
        Wh = WEh + (size_t)m0*KE; Wl = WEl + (size_t)m0*KE;
        Bh = HEh; Bl = HEl; acc = accE[ks] + m0*Bb;
    } else {
        int g = bx-64, m0 = (g>>1)*128, ks = g&1;
        kbase = ks ? Hh : 0; nch = ks ? 8 : 32; kth = Hh; Kst = KG;
        Wh = WGh + (size_t)m0*KG; Wl = WGl + (size_t)m0*KG;
        Bh = HGh; Bl = HGl; acc = accG[ks] + m0*Bb;
    }
    const bf* Xht = Xh + (size_t)t*Ii*Bb;
    const bf* Xlt = Xl + (size_t)t*Ii*Bb;

    uint4 rw0, rw1, rw2, rw3, rb0, rb1;
    auto ldg = [&](int c){
        int k0 = kbase + c*16;
        const bf* p = Wh + (size_t)tid*Kst + k0; rw0 = *(const uint4*)p; rw1 = *(const uint4*)(p+8);
        p = Wl + (size_t)tid*Kst + k0;           rw2 = *(const uint4*)p; rw3 = *(const uint4*)(p+8);
        int kr = k0 + (tid>>3), off = (tid&7)*8;
        const bf* q = (kr < kth) ? Bh + kr*Bb + off : Xht + (kr-kth)*Bb + off; rb0 = *(const uint4*)q;
        q = (kr < kth) ? Bl + kr*Bb + off : Xlt + (kr-kth)*Bb + off;           rb1 = *(const uint4*)q;
    };
    auto sts = [&](int u){
        bf* w = &sW[u][0][tid*SWS]; *(uint4*)w = rw0; *(uint4*)(w+8) = rw1;
        w = &sW[u][1][tid*SWS];     *(uint4*)w = rw2; *(uint4*)(w+8) = rw3;
        bf* b = &sB[u][0][(tid>>3)*SBS + (tid&7)*8]; *(uint4*)b = rb0;
        b = &sB[u][1][(tid>>3)*SBS + (tid&7)*8];     *(uint4*)b = rb1;
    };

    float d[2][8][4];
    #pragma unroll
    for(int i=0;i<2;i++)
        #pragma unroll
        for(int j=0;j<8;j++)
            #pragma unroll
            for(int q=0;q<4;q++) d[i][j][q] = 0.0f;

    const int mw = wid*32;
    const int ar = lane & 15, ac = (lane>>4)*8;

    ldg(0);
    for(int c=0; c<nch; c++){
        int u = c & 1;
        sts(u);
        __syncthreads();
        if(c+1 < nch) ldg(c+1);
        unsigned A[2][2][4], Bf[2][4][4];
        #pragma unroll
        for(int mt=0; mt<2; mt++)
            #pragma unroll
            for(int s=0; s<2; s++)
                ldsm4(A[mt][s], &sW[u][s][(mw + mt*16 + ar)*SWS + ac]);
        #pragma unroll
        for(int s=0; s<2; s++)
            #pragma unroll
            for(int np=0; np<4; np++)
                ldsm4t(Bf[s][np], &sB[u][s][ar*SBS + np*16 + ac]);
        #pragma unroll
        for(int mt=0; mt<2; mt++)
            #pragma unroll
            for(int nt=0; nt<8; nt++){
                const unsigned* bh = &Bf[0][nt>>1][(nt&1)*2];
                const unsigned* bl = &Bf[1][nt>>1][(nt&1)*2];
                mma_bf(d[mt][nt], A[mt][0], bh);   // hi*hi
                mma_bf(d[mt][nt], A[mt][1], bh);   // lo*hi
                mma_bf(d[mt][nt], A[mt][0], bl);   // hi*lo
            }
    }
    const int r4 = lane>>2, c2 = 2*(lane&3);
    #pragma unroll
    for(int mt=0; mt<2; mt++)
        #pragma unroll
        for(int nt=0; nt<8; nt++){
            int m = mw + mt*16 + r4, b = nt*8 + c2;
            *(float2*)&acc[m*Bb + b]     = make_float2(d[mt][nt][0], d[mt][nt][1]);
            *(float2*)&acc[(m+8)*Bb + b] = make_float2(d[mt][nt][2], d[mt][nt][3]);
        }

    // ---------- single-wave grid barrier ----------
    __threadfence();
    __syncthreads();
    const unsigned target = (unsigned)NBLK * (unsigned)(t + 1);
    if(tid == 0){
        atomicAdd(&g_ctr, 1u);
        volatile unsigned* p = &g_ctr;
        while(*p < target) __nanosleep(64);
    }
    __syncthreads();
    __threadfence();

    // ---------- fused epilogue (strided over all state elems) ----------
    const int NT = NBLK * 128;
    for(int idx = bx*128 + tid; idx < Rr*Bb + Hh*Bb; idx += NT){
        if(idx < Rr*Bb){
            float s = accE[0][idx] + accE[1][idx] + accE[2][idx] + accE[3][idx];
            float nv = 0.7f*hET[idx] + 0.3f*tanhf(s);
            hET[idx] = nv; bsplit(nv, &HEh[idx], &HEl[idx]);
        } else {
            int ix = idx - Rr*Bb;
            int j = ix >> 6, b = ix & 63;
            float hr = accG[0][ix],              xr = accG[1][ix];
            float hz = accG[0][(j+Hh)*Bb + b],   xz = accG[1][(j+Hh)*Bb + b];
            float hn = accG[0][(j+2*Hh)*Bb + b], xn = accG[1][(j+2*Hh)*Bb + b];
            float rg = sigm(xr + hr + bih[j] + bhh[j]);
            float zg = sigm(xz + hz + bih[j+Hh] + bhh[j+Hh]);
            float nn = tanhf(xn + bih[j+2*Hh] + rg*(hn + bhh[j+2*Hh]));
            float nv = (1.0f - zg)*nn + zg*hGT[ix];
            hGT[ix] = nv; bsplit(nv, &HGh[ix], &HGl[ix]);
        }
    }
}

// ---------------- final transpose + head ----------------
__global__ void k_tr(){
    int idx = blockIdx.x*blockDim.x + threadIdx.x;
    if(idx < Bb*Rr){ int b = idx/Rr, c = idx - b*Rr; g_hE[idx] = hET[c*Bb + b]; }
    if(idx < Bb*Hh){ int b = idx/Hh, j = idx - b*Hh; g_hG[idx] = hGT[j*Bb + b]; }
}
__global__ __launch_bounds__(256) void k_gemm(
    const float* __restrict__ A, const float* __restrict__ W,
    const float* __restrict__ bias, float* __restrict__ C, int K, int J, int act)
{
    __shared__ __align__(16) float sA[32*68];
    __shared__ float sW2[32*16];
    const int tid = threadIdx.x, tx = tid & 15, ty = tid >> 4, jb = blockIdx.x*16;
    float acc[4] = {0.f,0.f,0.f,0.f};
    for(int ch=0; ch<(K>>5); ch++){
        const int k0 = ch*32;
        #pragma unroll
        for(int r=0;r<2;r++){
            int idx = tid + r*256, b = idx>>3, kq = idx&7;
            float4 v = *(const float4*)(A + b*K + k0 + 4*kq);
            sA[(4*kq+0)*68+b]=v.x; sA[(4*kq+1)*68+b]=v.y;
            sA[(4*kq+2)*68+b]=v.z; sA[(4*kq+3)*68+b]=v.w;
        }
        #pragma unroll
        for(int r=0;r<2;r++){
            int idx = tid + r*256, kr = idx&31, c = idx>>5;
            sW2[kr*16+c] = W[(jb+c)*K + k0 + kr];
        }
        __syncthreads();
        #pragma unroll
        for(int kk=0;kk<32;kk++){
            float w = sW2[kk*16+tx];
            float4 a = *(const float4*)&sA[kk*68 + 4*ty];
            acc[0]+=a.x*w; acc[1]+=a.y*w; acc[2]+=a.z*w; acc[3]+=a.w*w;
        }
        __syncthreads();
    }
    const int j = jb + tx; const float bv = bias[j];
    #pragma unroll
    for(int i=0;i<4;i++){
        float v = acc[i] + bv;
        if(act==1) v = sigm(v); else if(act==2) v = fmaxf(v, 0.0f);
        C[(4*ty+i)*J + j] = v;
    }
}
__global__ void k_cat(){
    int idx = blockIdx.x*blockDim.x + threadIdx.x;
    if(idx < Bb*2*Hh){
        int b = idx>>10, k = idx & 1023;
        g_cat[idx] = (k < Hh) ? g_proj[b*Hh + k] : g_hG[b*Hh + (k-Hh)];
    }
}
__global__ void k_combine(){
    int idx = blockIdx.x*blockDim.x + threadIdx.x;
    if(idx < Bb*Hh){
        float g = g_gate[idx];
        g_comb[idx] = g*g_proj[idx] + (1.0f - g)*g_hG[idx];
    }
}

extern "C" void kernel_launch(void* const* d_in, const int* in_sizes, int n_in,
                              void* d_out, int out_size)
{
    const float* x     = (const float*)d_in[0];
    const float* Win   = (const float*)d_in[1];
    const float* Wres  = (const float*)d_in[2];
    const float* Wih   = (const float*)d_in[3];
    const float* Whh   = (const float*)d_in[4];
    const float* bih   = (const float*)d_in[5];
    const float* bhh   = (const float*)d_in[6];
    const float* projW = (const float*)d_in[7];
    const float* projb = (const float*)d_in[8];
    const float* gateW = (const float*)d_in[9];
    const float* gateb = (const float*)d_in[10];
    const float* hW1   = (const float*)d_in[11];
    const float* hb1   = (const float*)d_in[12];
    const float* hW2   = (const float*)d_in[13];
    const float* hb2   = (const float*)d_in[14];
    float* out = (float*)d_out;

    void *pE, *pProj, *pCat, *pComb, *pHid, *pGate;
    cudaGetSymbolAddress(&pE,    g_hE);
    cudaGetSymbolAddress(&pProj, g_proj);
    cudaGetSymbolAddress(&pCat,  g_cat);
    cudaGetSymbolAddress(&pComb, g_comb);
    cudaGetSymbolAddress(&pGate, g_gate);
    cudaGetSymbolAddress(&pHid,  g_hid);

    k_prepWE<<<(Rr*KE)/256, 256>>>(Wres, Win);
    k_prepWG<<<(MG*KG)/256, 256>>>(Whh, Wih);
    k_prepX <<<(Tt*Ii*Bb)/256, 256>>>(x);
    k_init0 <<<512, 256>>>();
    for(int t=0; t<Tt; t++)
        k_mma<<<NBLK, 128>>>(t, bih, bhh);
    k_tr<<<512, 256>>>();
    k_gemm<<<32, 256>>>((const float*)pE,   projW, projb, (float*)pProj, Rr,   Hh, 0);
    k_cat    <<<256, 256>>>();
    k_gemm<<<32, 256>>>((const float*)pCat, gateW, gateb, (float*)pGate, 2*Hh, Hh, 1);
    k_combine<<<128, 256>>>();
    k_gemm<<<32, 256>>>((const float*)pComb, hW1,  hb1,   (float*)pHid,  Hh,   Hh, 2);
    k_gemm<<<8,  256>>>((const float*)pHid,  hW2,  hb2,   out,           Hh,   Oo, 0);
}

// round 8
// speedup vs baseline: 5.0520x; 1.2198x over previous
#include <cuda_runtime.h>
#include <cuda_bf16.h>
#include <math.h>

#define Bb 64
#define Tt 512
#define Ii 128
#define Rr 2048
#define Hh 512
#define Oo 128
#define KE 2176
#define KG 640
#define MG 1536
#define NBLK 88
#define STG_ELEMS 8448           // bf16 elems per pipeline stage
#define STG_BYTES 16896
#define SMEM_BYTES (4*STG_BYTES) // 67584

typedef __nv_bfloat16 bf;

// ---------------- device scratch ----------------
__device__ bf WEh[Rr*KE], WEl[Rr*KE];      // ESN weights^T hi/lo  [c][k]
__device__ bf WGh[MG*KG], WGl[MG*KG];      // GRU weights^T hi/lo  [m][k]
__device__ bf Xh[Tt*Ii*Bb], Xl[Tt*Ii*Bb];  // x transposed hi/lo   [t][i][b]
__device__ bf HEh[Rr*Bb], HEl[Rr*Bb];      // ESN state bf16       [c][b]
__device__ bf HGh[Hh*Bb], HGl[Hh*Bb];      // GRU state bf16       [j][b]
__device__ float hET[Rr*Bb], hGT[Hh*Bb];   // fp32 states (transposed)
__device__ float accE[4][Rr*Bb];
__device__ float accG[2][MG*Bb];
__device__ unsigned g_ctr;
__device__ float g_hE[Bb*Rr], g_hG[Bb*Hh];
__device__ float g_proj[Bb*Hh], g_cat[Bb*2*Hh], g_gate[Bb*Hh], g_comb[Bb*Hh], g_hid[Bb*Hh];

__device__ __forceinline__ float sigm(float x){ return 1.0f/(1.0f+expf(-x)); }
__device__ __forceinline__ float fsig(float x){ return __fdividef(1.0f, 1.0f + __expf(-x)); }
__device__ __forceinline__ float ftanh(float x){
    float e = __expf(2.0f*x);
    return 1.0f - __fdividef(2.0f, e + 1.0f);
}
__device__ __forceinline__ void bsplit(float v, bf* ph, bf* pl){
    bf h = __float2bfloat16(v); *ph = h; *pl = __float2bfloat16(v - __bfloat162float(h));
}
__device__ __forceinline__ unsigned bp2(bf a, bf b){
    return (unsigned)__bfloat16_as_ushort(a) | ((unsigned)__bfloat16_as_ushort(b) << 16);
}
__device__ __forceinline__ void bpack4(float v0,float v1,float v2,float v3, bf* dh, bf* dl){
    bf h0=__float2bfloat16(v0), h1=__float2bfloat16(v1), h2=__float2bfloat16(v2), h3=__float2bfloat16(v3);
    bf l0=__float2bfloat16(v0-__bfloat162float(h0));
    bf l1=__float2bfloat16(v1-__bfloat162float(h1));
    bf l2=__float2bfloat16(v2-__bfloat162float(h2));
    bf l3=__float2bfloat16(v3-__bfloat162float(h3));
    *(uint2*)dh = make_uint2(bp2(h0,h1), bp2(h2,h3));
    *(uint2*)dl = make_uint2(bp2(l0,l1), bp2(l2,l3));
}
__device__ __forceinline__ void ldsm4(unsigned* r, const bf* p){
    unsigned a = (unsigned)__cvta_generic_to_shared(p);
    asm volatile("ldmatrix.sync.aligned.m8n8.x4.shared.b16 {%0,%1,%2,%3},[%4];"
        : "=r"(r[0]),"=r"(r[1]),"=r"(r[2]),"=r"(r[3]) : "r"(a));
}
__device__ __forceinline__ void ldsm4t(unsigned* r, const bf* p){
    unsigned a = (unsigned)__cvta_generic_to_shared(p);
    asm volatile("ldmatrix.sync.aligned.m8n8.x4.trans.shared.b16 {%0,%1,%2,%3},[%4];"
        : "=r"(r[0]),"=r"(r[1]),"=r"(r[2]),"=r"(r[3]) : "r"(a));
}
__device__ __forceinline__ void mma_bf(float* d, const unsigned* a, const unsigned* b){
    asm volatile("mma.sync.aligned.m16n8k16.row.col.f32.bf16.bf16.f32 "
        "{%0,%1,%2,%3},{%4,%5,%6,%7},{%8,%9},{%0,%1,%2,%3};"
        : "+f"(d[0]),"+f"(d[1]),"+f"(d[2]),"+f"(d[3])
        : "r"(a[0]),"r"(a[1]),"r"(a[2]),"r"(a[3]),"r"(b[0]),"r"(b[1]));
}
__device__ __forceinline__ void cp16(unsigned dst, const void* src){
    asm volatile("cp.async.cg.shared.global [%0],[%1],16;" :: "r"(dst),"l"(src));
}

// ---------------- prep ----------------
__global__ void k_prepWE(const float* __restrict__ Wres, const float* __restrict__ Win){
    int idx = blockIdx.x*blockDim.x + threadIdx.x;        // c*KE + k
    int c = idx/KE, k = idx - c*KE;
    float w = (k < Rr) ? Wres[k*Rr + c] : Win[(k-Rr)*Rr + c];
    bsplit(w, &WEh[idx], &WEl[idx]);
}
__global__ void k_prepWG(const float* __restrict__ Whh, const float* __restrict__ Wih){
    int idx = blockIdx.x*blockDim.x + threadIdx.x;        // m*KG + k
    int m = idx/KG, k = idx - m*KG;
    float w = (k < Hh) ? Whh[m*Hh + k] : Wih[m*Ii + (k-Hh)];
    bsplit(w, &WGh[idx], &WGl[idx]);
}
__global__ void k_prepX(const float* __restrict__ x){
    int idx = blockIdx.x*blockDim.x + threadIdx.x;        // t*8192 + i*64 + b
    int t = idx >> 13, r = idx & 8191, i = r >> 6, b = r & 63;
    bsplit(x[b*(Tt*Ii) + t*Ii + i], &Xh[idx], &Xl[idx]);
}
__global__ void k_init0(){
    int i = blockIdx.x*blockDim.x + threadIdx.x;
    bf z = __float2bfloat16(0.0f);
    if(i == 0) g_ctr = 0u;
    if(i < Rr*Bb){ hET[i]=0.0f; HEh[i]=z; HEl[i]=z; }
    if(i < Hh*Bb){ hGT[i]=0.0f; HGh[i]=z; HGl[i]=z; }
}

// ---------------- persistent all-timesteps kernel ----------------
// 88 blocks x 128 thr, single wave. Per step: MMA phase -> grid barrier ->
// epilogue phase -> grid barrier. 4-stage cp.async pipeline feeds the MMAs.
// Stage layout (bf elems): Whi[128*24] @0, Wlo @3072, Bhi[16*72] @6144, Blo @7296.
__device__ __forceinline__ void gbar(unsigned target){
    __threadfence();
    __syncthreads();
    if(threadIdx.x == 0){
        atomicAdd(&g_ctr, 1u);
        volatile unsigned* p = &g_ctr;
        while(*p < target) __nanosleep(32);
    }
    __syncthreads();
    __threadfence();
}

__global__ void __launch_bounds__(128) k_all(
    const float* __restrict__ bih, const float* __restrict__ bhh)
{
    extern __shared__ __align__(16) bf sm[];
    const int tid = threadIdx.x, lane = tid & 31, wid = tid >> 5, bx = blockIdx.x;
    const unsigned sb = (unsigned)__cvta_generic_to_shared(sm);

    // ---- role setup ----
    const bf *Wh, *Wl, *Bh, *Bl; float* acc; int Kst, kbase, nch, kth;
    if(bx < 64){
        int m0 = (bx>>2)*128, ks = bx&3;
        kbase = ks*544; nch = 34; kth = Rr; Kst = KE;
        Wh = WEh + (size_t)m0*KE; Wl = WEl + (size_t)m0*KE;
        Bh = HEh; Bl = HEl; acc = accE[ks] + m0*Bb;
    } else {
        int g = bx-64, m0 = (g>>1)*128, ks = g&1;
        kbase = ks ? Hh : 0; nch = ks ? 8 : 32; kth = Hh; Kst = KG;
        Wh = WGh + (size_t)m0*KG; Wl = WGl + (size_t)m0*KG;
        Bh = HGh; Bl = HGl; acc = accG[ks] + m0*Bb;
    }
    const bf* wsrc_h = Wh + (size_t)tid*Kst;
    const bf* wsrc_l = Wl + (size_t)tid*Kst;
    const unsigned wdh = sb + tid*48;           // W hi dst (bytes)
    const unsigned wdl = wdh + 6144;
    const unsigned bdh = sb + 12288 + (tid>>3)*144 + (tid&7)*16;
    const unsigned bdl = bdh + 2304;
    const int krow = tid >> 3, boff = (tid & 7) * 8;
    const int mw = wid*32, ar = lane & 15, ac = (lane>>4)*8;
    const int r4 = lane>>2, c2 = 2*(lane&3);
    const int gbase = bx*128 + tid;
    const int NT = NBLK*128;

    for(int t = 0; t < Tt; t++){
        const bf* Xht = Xh + (size_t)t*Ii*Bb;
        const bf* Xlt = Xl + (size_t)t*Ii*Bb;

        auto issue = [&](int c){
            unsigned so = (unsigned)(c & 3) * STG_BYTES;
            int k0 = kbase + c*16;
            cp16(wdh + so,      wsrc_h + k0);
            cp16(wdh + so + 16, wsrc_h + k0 + 8);
            cp16(wdl + so,      wsrc_l + k0);
            cp16(wdl + so + 16, wsrc_l + k0 + 8);
            int kr = k0 + krow;
            const bf* q = (kr < kth) ? Bh + kr*Bb + boff : Xht + (kr-kth)*Bb + boff;
            cp16(bdh + so, q);
            q = (kr < kth) ? Bl + kr*Bb + boff : Xlt + (kr-kth)*Bb + boff;
            cp16(bdl + so, q);
            asm volatile("cp.async.commit_group;");
        };

        float d[2][8][4];
        #pragma unroll
        for(int i=0;i<2;i++)
            #pragma unroll
            for(int j=0;j<8;j++)
                #pragma unroll
                for(int q=0;q<4;q++) d[i][j][q] = 0.0f;

        issue(0); issue(1); issue(2);

        for(int c = 0; c < nch; c++){
            if(c < nch-2)       asm volatile("cp.async.wait_group 2;");
            else if(c == nch-2) asm volatile("cp.async.wait_group 1;");
            else                asm volatile("cp.async.wait_group 0;");
            __syncthreads();
            if(c + 3 < nch) issue(c + 3);

            const bf* stg = sm + (size_t)(c & 3) * STG_ELEMS;
            const bf* swh = stg;
            const bf* swl = stg + 3072;
            const bf* sbh = stg + 6144;
            const bf* sbl = stg + 7296;

            unsigned A[2][2][4], Bf[2][4][4];
            #pragma unroll
            for(int mt=0; mt<2; mt++){
                ldsm4(A[mt][0], swh + (mw + mt*16 + ar)*24 + ac);
                ldsm4(A[mt][1], swl + (mw + mt*16 + ar)*24 + ac);
            }
            #pragma unroll
            for(int np=0; np<4; np++){
                ldsm4t(Bf[0][np], sbh + ar*72 + np*16 + ac);
                ldsm4t(Bf[1][np], sbl + ar*72 + np*16 + ac);
            }
            #pragma unroll
            for(int mt=0; mt<2; mt++)
                #pragma unroll
                for(int nt=0; nt<8; nt++){
                    const unsigned* bh = &Bf[0][nt>>1][(nt&1)*2];
                    const unsigned* bl = &Bf[1][nt>>1][(nt&1)*2];
                    mma_bf(d[mt][nt], A[mt][0], bh);   // hi*hi
                    mma_bf(d[mt][nt], A[mt][1], bh);   // lo*hi
                    mma_bf(d[mt][nt], A[mt][0], bl);   // hi*lo
                }
        }
        #pragma unroll
        for(int mt=0; mt<2; mt++)
            #pragma unroll
            for(int nt=0; nt<8; nt++){
                int m = mw + mt*16 + r4, b = nt*8 + c2;
                *(float2*)&acc[m*Bb + b]     = make_float2(d[mt][nt][0], d[mt][nt][1]);
                *(float2*)&acc[(m+8)*Bb + b] = make_float2(d[mt][nt][2], d[mt][nt][3]);
            }

        gbar((unsigned)NBLK * (unsigned)(2*t + 1));

        // ---------- epilogue (float4-vectorized, fast activations) ----------
        for(int g = gbase; g < (Rr*Bb)/4; g += NT){
            int o = g*4;
            float4 a0 = *(const float4*)&accE[0][o];
            float4 a1 = *(const float4*)&accE[1][o];
            float4 a2 = *(const float4*)&accE[2][o];
            float4 a3 = *(const float4*)&accE[3][o];
            float4 hp = *(const float4*)&hET[o];
            float n0 = 0.7f*hp.x + 0.3f*ftanh(a0.x+a1.x+a2.x+a3.x);
            float n1 = 0.7f*hp.y + 0.3f*ftanh(a0.y+a1.y+a2.y+a3.y);
            float n2 = 0.7f*hp.z + 0.3f*ftanh(a0.z+a1.z+a2.z+a3.z);
            float n3 = 0.7f*hp.w + 0.3f*ftanh(a0.w+a1.w+a2.w+a3.w);
            *(float4*)&hET[o] = make_float4(n0,n1,n2,n3);
            bpack4(n0,n1,n2,n3, &HEh[o], &HEl[o]);
        }
        for(int g = gbase; g < (Hh*Bb)/4; g += NT){
            int j = g >> 4, b4 = (g & 15)*4, ix = j*64 + b4;
            float4 hr = *(const float4*)&accG[0][ix];
            float4 xr = *(const float4*)&accG[1][ix];
            float4 hz = *(const float4*)&accG[0][(j+Hh)*64 + b4];
            float4 xz = *(const float4*)&accG[1][(j+Hh)*64 + b4];
            float4 hn = *(const float4*)&accG[0][(j+2*Hh)*64 + b4];
            float4 xn = *(const float4*)&accG[1][(j+2*Hh)*64 + b4];
            float4 hp = *(const float4*)&hGT[ix];
            float br  = bih[j] + bhh[j];
            float bz2 = bih[j+Hh] + bhh[j+Hh];
            float bxn = bih[j+2*Hh], bhn = bhh[j+2*Hh];
            float n[4];
            #pragma unroll
            for(int i=0;i<4;i++){
                float hrv = (&hr.x)[i], xrv = (&xr.x)[i];
                float hzv = (&hz.x)[i], xzv = (&xz.x)[i];
                float hnv = (&hn.x)[i], xnv = (&xn.x)[i];
                float hpv = (&hp.x)[i];
                float rg = fsig(xrv + hrv + br);
                float zg = fsig(xzv + hzv + bz2);
                float nn = ftanh(xnv + bxn + rg*(hnv + bhn));
                n[i] = (1.0f - zg)*nn + zg*hpv;
            }
            *(float4*)&hGT[ix] = make_float4(n[0],n[1],n[2],n[3]);
            bpack4(n[0],n[1],n[2],n[3], &HGh[ix], &HGl[ix]);
        }

        gbar((unsigned)NBLK * (unsigned)(2*t + 2));
    }
}

// ---------------- final transpose + head ----------------
__global__ void k_tr(){
    int idx = blockIdx.x*blockDim.x + threadIdx.x;
    if(idx < Bb*Rr){ int b = idx/Rr, c = idx - b*Rr; g_hE[idx] = hET[c*Bb + b]; }
    if(idx < Bb*Hh){ int b = idx/Hh, j = idx - b*Hh; g_hG[idx] = hGT[j*Bb + b]; }
}
__global__ __launch_bounds__(256) void k_gemm(
    const float* __restrict__ A, const float* __restrict__ W,
    const float* __restrict__ bias, float* __restrict__ C, int K, int J, int act)
{
    __shared__ __align__(16) float sA[32*68];
    __shared__ float sW2[32*16];
    const int tid = threadIdx.x, tx = tid & 15, ty = tid >> 4, jb = blockIdx.x*16;
    float acc[4] = {0.f,0.f,0.f,0.f};
    for(int ch=0; ch<(K>>5); ch++){
        const int k0 = ch*32;
        #pragma unroll
        for(int r=0;r<2;r++){
            int idx = tid + r*256, b = idx>>3, kq = idx&7;
            float4 v = *(const float4*)(A + b*K + k0 + 4*kq);
            sA[(4*kq+0)*68+b]=v.x; sA[(4*kq+1)*68+b]=v.y;
            sA[(4*kq+2)*68+b]=v.z; sA[(4*kq+3)*68+b]=v.w;
        }
        #pragma unroll
        for(int r=0;r<2;r++){
            int idx = tid + r*256, kr = idx&31, c = idx>>5;
            sW2[kr*16+c] = W[(jb+c)*K + k0 + kr];
        }
        __syncthreads();
        #pragma unroll
        for(int kk=0;kk<32;kk++){
            float w = sW2[kk*16+tx];
            float4 a = *(const float4*)&sA[kk*68 + 4*ty];
            acc[0]+=a.x*w; acc[1]+=a.y*w; acc[2]+=a.z*w; acc[3]+=a.w*w;
        }
        __syncthreads();
    }
    const int j = jb + tx; const float bv = bias[j];
    #pragma unroll
    for(int i=0;i<4;i++){
        float v = acc[i] + bv;
        if(act==1) v = sigm(v); else if(act==2) v = fmaxf(v, 0.0f);
        C[(4*ty+i)*J + j] = v;
    }
}
__global__ void k_cat(){
    int idx = blockIdx.x*blockDim.x + threadIdx.x;
    if(idx < Bb*2*Hh){
        int b = idx>>10, k = idx & 1023;
        g_cat[idx] = (k < Hh) ? g_proj[b*Hh + k] : g_hG[b*Hh + (k-Hh)];
    }
}
__global__ void k_combine(){
    int idx = blockIdx.x*blockDim.x + threadIdx.x;
    if(idx < Bb*Hh){
        float g = g_gate[idx];
        g_comb[idx] = g*g_proj[idx] + (1.0f - g)*g_hG[idx];
    }
}

extern "C" void kernel_launch(void* const* d_in, const int* in_sizes, int n_in,
                              void* d_out, int out_size)
{
    const float* x     = (const float*)d_in[0];
    const float* Win   = (const float*)d_in[1];
    const float* Wres  = (const float*)d_in[2];
    const float* Wih   = (const float*)d_in[3];
    const float* Whh   = (const float*)d_in[4];
    const float* bih   = (const float*)d_in[5];
    const float* bhh   = (const float*)d_in[6];
    const float* projW = (const float*)d_in[7];
    const float* projb = (const float*)d_in[8];
    const float* gateW = (const float*)d_in[9];
    const float* gateb = (const float*)d_in[10];
    const float* hW1   = (const float*)d_in[11];
    const float* hb1   = (const float*)d_in[12];
    const float* hW2   = (const float*)d_in[13];
    const float* hb2   = (const float*)d_in[14];
    float* out = (float*)d_out;

    void *pE, *pProj, *pCat, *pComb, *pHid, *pGate;
    cudaGetSymbolAddress(&pE,    g_hE);
    cudaGetSymbolAddress(&pProj, g_proj);
    cudaGetSymbolAddress(&pCat,  g_cat);
    cudaGetSymbolAddress(&pComb, g_comb);
    cudaGetSymbolAddress(&pGate, g_gate);
    cudaGetSymbolAddress(&pHid,  g_hid);

    cudaFuncSetAttribute(k_all, cudaFuncAttributeMaxDynamicSharedMemorySize, SMEM_BYTES);

    k_prepWE<<<(Rr*KE)/256, 256>>>(Wres, Win);
    k_prepWG<<<(MG*KG)/256, 256>>>(Whh, Wih);
    k_prepX <<<(Tt*Ii*Bb)/256, 256>>>(x);
    k_init0 <<<512, 256>>>();
    k_all<<<NBLK, 128, SMEM_BYTES>>>(bih, bhh);
    k_tr<<<512, 256>>>();
    k_gemm<<<32, 256>>>((const float*)pE,   projW, projb, (float*)pProj, Rr,   Hh, 0);
    k_cat    <<<256, 256>>>();
    k_gemm<<<32, 256>>>((const float*)pCat, gateW, gateb, (float*)pGate, 2*Hh, Hh, 1);
    k_combine<<<128, 256>>>();
    k_gemm<<<32, 256>>>((const float*)pComb, hW1,  hb1,   (float*)pHid,  Hh,   Hh, 2);
    k_gemm<<<8,  256>>>((const float*)pHid,  hW2,  hb2,   out,           Hh,   Oo, 0);
}

// round 9
// speedup vs baseline: 7.7047x; 1.5251x over previous
#include <cuda_runtime.h>
#include <cuda_bf16.h>
#include <math.h>

#define Bb 64
#define Tt 512
#define Ii 128
#define Rr 2048
#define Hh 512
#define Oo 128
#define KE 2176
#define KG 640
#define MG 1536
#define NBLK 140
#define STG_ELEMS 8448           // bf16 elems per pipeline stage
#define STG_BYTES 16896
#define SMEM_BYTES (4*STG_BYTES) // 67584

typedef __nv_bfloat16 bf;

// ---------------- device scratch ----------------
__device__ bf WEh[Rr*KE], WEl[Rr*KE];      // ESN weights^T hi/lo  [c][k]
__device__ bf WGh[MG*KG], WGl[MG*KG];      // GRU weights^T hi/lo  [m][k]
__device__ bf Xh[Tt*Ii*Bb], Xl[Tt*Ii*Bb];  // x transposed hi/lo   [t][i][b]
__device__ bf HEh[Rr*Bb], HEl[Rr*Bb];      // ESN state bf16       [c][b]
__device__ bf HGh[Hh*Bb], HGl[Hh*Bb];      // GRU state bf16       [j][b]
__device__ float hET[Rr*Bb], hGT[Hh*Bb];   // fp32 states (transposed)
__device__ float accE[7][Rr*Bb];           // ESN K-split partials
__device__ float accRZ[2][1024*Bb];        // GRU r,z rows 0..1024, K-split
__device__ float accNH[2][Hh*Bb];          // GRU n-gate h-part, K-split
__device__ float accNX[Hh*Bb];             // GRU n-gate x-part
__device__ unsigned g_ctr;
__device__ float g_hE[Bb*Rr], g_hG[Bb*Hh];
__device__ float g_proj[Bb*Hh], g_cat[Bb*2*Hh], g_gate[Bb*Hh], g_comb[Bb*Hh], g_hid[Bb*Hh];

__device__ __forceinline__ float sigm(float x){ return 1.0f/(1.0f+expf(-x)); }
__device__ __forceinline__ float fsig(float x){ return __fdividef(1.0f, 1.0f + __expf(-x)); }
__device__ __forceinline__ float ftanh(float x){
    float e = __expf(2.0f*x);
    return 1.0f - __fdividef(2.0f, e + 1.0f);
}
__device__ __forceinline__ void bsplit(float v, bf* ph, bf* pl){
    bf h = __float2bfloat16(v); *ph = h; *pl = __float2bfloat16(v - __bfloat162float(h));
}
__device__ __forceinline__ unsigned bp2(bf a, bf b){
    return (unsigned)__bfloat16_as_ushort(a) | ((unsigned)__bfloat16_as_ushort(b) << 16);
}
__device__ __forceinline__ void bpack4(float v0,float v1,float v2,float v3, bf* dh, bf* dl){
    bf h0=__float2bfloat16(v0), h1=__float2bfloat16(v1), h2=__float2bfloat16(v2), h3=__float2bfloat16(v3);
    bf l0=__float2bfloat16(v0-__bfloat162float(h0));
    bf l1=__float2bfloat16(v1-__bfloat162float(h1));
    bf l2=__float2bfloat16(v2-__bfloat162float(h2));
    bf l3=__float2bfloat16(v3-__bfloat162float(h3));
    *(uint2*)dh = make_uint2(bp2(h0,h1), bp2(h2,h3));
    *(uint2*)dl = make_uint2(bp2(l0,l1), bp2(l2,l3));
}
__device__ __forceinline__ void ldsm4(unsigned* r, const bf* p){
    unsigned a = (unsigned)__cvta_generic_to_shared(p);
    asm volatile("ldmatrix.sync.aligned.m8n8.x4.shared.b16 {%0,%1,%2,%3},[%4];"
        : "=r"(r[0]),"=r"(r[1]),"=r"(r[2]),"=r"(r[3]) : "r"(a));
}
__device__ __forceinline__ void ldsm4t(unsigned* r, const bf* p){
    unsigned a = (unsigned)__cvta_generic_to_shared(p);
    asm volatile("ldmatrix.sync.aligned.m8n8.x4.trans.shared.b16 {%0,%1,%2,%3},[%4];"
        : "=r"(r[0]),"=r"(r[1]),"=r"(r[2]),"=r"(r[3]) : "r"(a));
}
__device__ __forceinline__ void mma_bf(float* d, const unsigned* a, const unsigned* b){
    asm volatile("mma.sync.aligned.m16n8k16.row.col.f32.bf16.bf16.f32 "
        "{%0,%1,%2,%3},{%4,%5,%6,%7},{%8,%9},{%0,%1,%2,%3};"
        : "+f"(d[0]),"+f"(d[1]),"+f"(d[2]),"+f"(d[3])
        : "r"(a[0]),"r"(a[1]),"r"(a[2]),"r"(a[3]),"r"(b[0]),"r"(b[1]));
}
__device__ __forceinline__ void cp16(unsigned dst, const void* src){
    asm volatile("cp.async.cg.shared.global [%0],[%1],16;" :: "r"(dst),"l"(src));
}

// ---------------- prep ----------------
__global__ void k_prepWE(const float* __restrict__ Wres, const float* __restrict__ Win){
    int idx = blockIdx.x*blockDim.x + threadIdx.x;        // c*KE + k
    int c = idx/KE, k = idx - c*KE;
    float w = (k < Rr) ? Wres[k*Rr + c] : Win[(k-Rr)*Rr + c];
    bsplit(w, &WEh[idx], &WEl[idx]);
}
__global__ void k_prepWG(const float* __restrict__ Whh, const float* __restrict__ Wih){
    int idx = blockIdx.x*blockDim.x + threadIdx.x;        // m*KG + k
    int m = idx/KG, k = idx - m*KG;
    float w = (k < Hh) ? Whh[m*Hh + k] : Wih[m*Ii + (k-Hh)];
    bsplit(w, &WGh[idx], &WGl[idx]);
}
__global__ void k_prepX(const float* __restrict__ x){
    int idx = blockIdx.x*blockDim.x + threadIdx.x;        // t*8192 + i*64 + b
    int t = idx >> 13, r = idx & 8191, i = r >> 6, b = r & 63;
    bsplit(x[b*(Tt*Ii) + t*Ii + i], &Xh[idx], &Xl[idx]);
}
__global__ void k_init0(){
    int i = blockIdx.x*blockDim.x + threadIdx.x;
    bf z = __float2bfloat16(0.0f);
    if(i == 0) g_ctr = 0u;
    if(i < Rr*Bb){ hET[i]=0.0f; HEh[i]=z; HEl[i]=z; }
    if(i < Hh*Bb){ hGT[i]=0.0f; HGh[i]=z; HGl[i]=z; }
}

// ---------------- persistent all-timesteps kernel ----------------
// 140 blocks x 128 thr, single wave. Per step: MMA -> barrier -> epilogue -> barrier.
// Blocks: [0,112)  ESN: m-tile bx/7 (128 rows), K-split bx%7 (6x320 + 1x256)
//         [112,128) GRU r,z: m-tile (128 rows of first 1024), K-split of full 640
//         [128,136) GRU n-gate h-part: 4 m-tiles x 2 K-splits of 512
//         [136,140) GRU n-gate x-part: 4 m-tiles, K=[512,640)
__device__ __forceinline__ void gbar(unsigned target){
    __threadfence();
    __syncthreads();
    if(threadIdx.x == 0){
        atomicAdd(&g_ctr, 1u);
        volatile unsigned* p = &g_ctr;
        while(*p < target) __nanosleep(32);
    }
    __syncthreads();
    __threadfence();
}

__global__ void __launch_bounds__(128) k_all(
    const float* __restrict__ bih, const float* __restrict__ bhh)
{
    extern __shared__ __align__(16) bf sm[];
    const int tid = threadIdx.x, lane = tid & 31, wid = tid >> 5, bx = blockIdx.x;
    const unsigned sb = (unsigned)__cvta_generic_to_shared(sm);

    // ---- role setup ----
    const bf *Wh, *Wl, *Bh, *Bl; float* acc; int Kst, kbase, nch, kth;
    if(bx < 112){
        int m0 = (bx/7)*128, ks = bx%7;
        kbase = ks*320; nch = (ks < 6) ? 20 : 16; kth = Rr; Kst = KE;
        Wh = WEh + (size_t)m0*KE; Wl = WEl + (size_t)m0*KE;
        Bh = HEh; Bl = HEl; acc = accE[ks] + m0*Bb;
    } else if(bx < 128){
        int g = bx-112, m0 = (g>>1)*128, ks = g&1;
        kbase = ks*320; nch = 20; kth = Hh; Kst = KG;
        Wh = WGh + (size_t)m0*KG; Wl = WGl + (size_t)m0*KG;
        Bh = HGh; Bl = HGl; acc = accRZ[ks] + m0*Bb;
    } else if(bx < 136){
        int g = bx-128, mt = g>>1, ks = g&1;
        kbase = ks*256; nch = 16; kth = Hh; Kst = KG;
        Wh = WGh + (size_t)(1024 + mt*128)*KG; Wl = WGl + (size_t)(1024 + mt*128)*KG;
        Bh = HGh; Bl = HGl; acc = accNH[ks] + mt*128*Bb;
    } else {
        int mt = bx-136;
        kbase = 512; nch = 8; kth = Hh; Kst = KG;
        Wh = WGh + (size_t)(1024 + mt*128)*KG; Wl = WGl + (size_t)(1024 + mt*128)*KG;
        Bh = HGh; Bl = HGl; acc = accNX + mt*128*Bb;
    }
    const bf* wsrc_h = Wh + (size_t)tid*Kst;
    const bf* wsrc_l = Wl + (size_t)tid*Kst;
    const unsigned wdh = sb + tid*48;           // W hi dst (bytes)
    const unsigned wdl = wdh + 6144;
    const unsigned bdh = sb + 12288 + (tid>>3)*144 + (tid&7)*16;
    const unsigned bdl = bdh + 2304;
    const int krow = tid >> 3, boff = (tid & 7) * 8;
    const int mw = wid*32, ar = lane & 15, ac = (lane>>4)*8;
    const int r4 = lane>>2, c2 = 2*(lane&3);
    const int gbase = bx*128 + tid;
    const int NT = NBLK*128;

    for(int t = 0; t < Tt; t++){
        const bf* Xht = Xh + (size_t)t*Ii*Bb;
        const bf* Xlt = Xl + (size_t)t*Ii*Bb;

        auto issue = [&](int c){
            unsigned so = (unsigned)(c & 3) * STG_BYTES;
            int k0 = kbase + c*16;
            cp16(wdh + so,      wsrc_h + k0);
            cp16(wdh + so + 16, wsrc_h + k0 + 8);
            cp16(wdl + so,      wsrc_l + k0);
            cp16(wdl + so + 16, wsrc_l + k0 + 8);
            int kr = k0 + krow;
            const bf* q = (kr < kth) ? Bh + kr*Bb + boff : Xht + (kr-kth)*Bb + boff;
            cp16(bdh + so, q);
            q = (kr < kth) ? Bl + kr*Bb + boff : Xlt + (kr-kth)*Bb + boff;
            cp16(bdl + so, q);
            asm volatile("cp.async.commit_group;");
        };

        float d[2][8][4];
        #pragma unroll
        for(int i=0;i<2;i++)
            #pragma unroll
            for(int j=0;j<8;j++)
                #pragma unroll
                for(int q=0;q<4;q++) d[i][j][q] = 0.0f;

        issue(0); issue(1); issue(2);

        for(int c = 0; c < nch; c++){
            if(c < nch-2)       asm volatile("cp.async.wait_group 2;");
            else if(c == nch-2) asm volatile("cp.async.wait_group 1;");
            else                asm volatile("cp.async.wait_group 0;");
            __syncthreads();
            if(c + 3 < nch) issue(c + 3);

            const bf* stg = sm + (size_t)(c & 3) * STG_ELEMS;
            const bf* swh = stg;
            const bf* swl = stg + 3072;
            const bf* sbh = stg + 6144;
            const bf* sbl = stg + 7296;

            unsigned A[2][2][4], Bf[2][4][4];
            #pragma unroll
            for(int mt=0; mt<2; mt++){
                ldsm4(A[mt][0], swh + (mw + mt*16 + ar)*24 + ac);
                ldsm4(A[mt][1], swl + (mw + mt*16 + ar)*24 + ac);
            }
            #pragma unroll
            for(int np=0; np<4; np++){
                ldsm4t(Bf[0][np], sbh + ar*72 + np*16 + ac);
                ldsm4t(Bf[1][np], sbl + ar*72 + np*16 + ac);
            }
            #pragma unroll
            for(int mt=0; mt<2; mt++)
                #pragma unroll
                for(int nt=0; nt<8; nt++){
                    const unsigned* bh = &Bf[0][nt>>1][(nt&1)*2];
                    const unsigned* bl = &Bf[1][nt>>1][(nt&1)*2];
                    mma_bf(d[mt][nt], A[mt][0], bh);   // hi*hi
                    mma_bf(d[mt][nt], A[mt][1], bh);   // lo*hi
                    mma_bf(d[mt][nt], A[mt][0], bl);   // hi*lo
                }
        }
        #pragma unroll
        for(int mt=0; mt<2; mt++)
            #pragma unroll
            for(int nt=0; nt<8; nt++){
                int m = mw + mt*16 + r4, b = nt*8 + c2;
                *(float2*)&acc[m*Bb + b]     = make_float2(d[mt][nt][0], d[mt][nt][1]);
                *(float2*)&acc[(m+8)*Bb + b] = make_float2(d[mt][nt][2], d[mt][nt][3]);
            }

        gbar((unsigned)NBLK * (unsigned)(2*t + 1));

        // ---------- epilogue ----------
        for(int g = gbase; g < (Rr*Bb)/4; g += NT){
            int o = g*4;
            float4 a0 = *(const float4*)&accE[0][o];
            float4 a1 = *(const float4*)&accE[1][o];
            float4 a2 = *(const float4*)&accE[2][o];
            float4 a3 = *(const float4*)&accE[3][o];
            float4 a4 = *(const float4*)&accE[4][o];
            float4 a5 = *(const float4*)&accE[5][o];
            float4 a6 = *(const float4*)&accE[6][o];
            float4 hp = *(const float4*)&hET[o];
            float n0 = 0.7f*hp.x + 0.3f*ftanh(a0.x+a1.x+a2.x+a3.x+a4.x+a5.x+a6.x);
            float n1 = 0.7f*hp.y + 0.3f*ftanh(a0.y+a1.y+a2.y+a3.y+a4.y+a5.y+a6.y);
            float n2 = 0.7f*hp.z + 0.3f*ftanh(a0.z+a1.z+a2.z+a3.z+a4.z+a5.z+a6.z);
            float n3 = 0.7f*hp.w + 0.3f*ftanh(a0.w+a1.w+a2.w+a3.w+a4.w+a5.w+a6.w);
            *(float4*)&hET[o] = make_float4(n0,n1,n2,n3);
            bpack4(n0,n1,n2,n3, &HEh[o], &HEl[o]);
        }
        for(int g = gbase; g < (Hh*Bb)/4; g += NT){
            int j = g >> 4, b4 = (g & 15)*4, ix = j*64 + b4;
            float4 r0 = *(const float4*)&accRZ[0][ix];
            float4 r1 = *(const float4*)&accRZ[1][ix];
            float4 z0 = *(const float4*)&accRZ[0][(j+Hh)*64 + b4];
            float4 z1 = *(const float4*)&accRZ[1][(j+Hh)*64 + b4];
            float4 h0 = *(const float4*)&accNH[0][ix];
            float4 h1 = *(const float4*)&accNH[1][ix];
            float4 xn = *(const float4*)&accNX[ix];
            float4 hp = *(const float4*)&hGT[ix];
            float br  = bih[j] + bhh[j];
            float bz2 = bih[j+Hh] + bhh[j+Hh];
            float bxn = bih[j+2*Hh], bhn = bhh[j+2*Hh];
            float n[4];
            #pragma unroll
            for(int i=0;i<4;i++){
                float rv = (&r0.x)[i] + (&r1.x)[i];
                float zv = (&z0.x)[i] + (&z1.x)[i];
                float hnv = (&h0.x)[i] + (&h1.x)[i];
                float xnv = (&xn.x)[i];
                float hpv = (&hp.x)[i];
                float rg = fsig(rv + br);
                float zg = fsig(zv + bz2);
                float nn = ftanh(xnv + bxn + rg*(hnv + bhn));
                n[i] = (1.0f - zg)*nn + zg*hpv;
            }
            *(float4*)&hGT[ix] = make_float4(n[0],n[1],n[2],n[3]);
            bpack4(n[0],n[1],n[2],n[3], &HGh[ix], &HGl[ix]);
        }

        gbar((unsigned)NBLK * (unsigned)(2*t + 2));
    }
}

// ---------------- final transpose + head ----------------
__global__ void k_tr(){
    int idx = blockIdx.x*blockDim.x + threadIdx.x;
    if(idx < Bb*Rr){ int b = idx/Rr, c = idx - b*Rr; g_hE[idx] = hET[c*Bb + b]; }
    if(idx < Bb*Hh){ int b = idx/Hh, j = idx - b*Hh; g_hG[idx] = hGT[j*Bb + b]; }
}
__global__ __launch_bounds__(256) void k_gemm(
    const float* __restrict__ A, const float* __restrict__ W,
    const float* __restrict__ bias, float* __restrict__ C, int K, int J, int act)
{
    __shared__ __align__(16) float sA[32*68];
    __shared__ float sW2[32*16];
    const int tid = threadIdx.x, tx = tid & 15, ty = tid >> 4, jb = blockIdx.x*16;
    float acc[4] = {0.f,0.f,0.f,0.f};
    for(int ch=0; ch<(K>>5); ch++){
        const int k0 = ch*32;
        #pragma unroll
        for(int r=0;r<2;r++){
            int idx = tid + r*256, b = idx>>3, kq = idx&7;
            float4 v = *(const float4*)(A + b*K + k0 + 4*kq);
            sA[(4*kq+0)*68+b]=v.x; sA[(4*kq+1)*68+b]=v.y;
            sA[(4*kq+2)*68+b]=v.z; sA[(4*kq+3)*68+b]=v.w;
        }
        #pragma unroll
        for(int r=0;r<2;r++){
            int idx = tid + r*256, kr = idx&31, c = idx>>5;
            sW2[kr*16+c] = W[(jb+c)*K + k0 + kr];
        }
        __syncthreads();
        #pragma unroll
        for(int kk=0;kk<32;kk++){
            float w = sW2[kk*16+tx];
            float4 a = *(const float4*)&sA[kk*68 + 4*ty];
            acc[0]+=a.x*w; acc[1]+=a.y*w; acc[2]+=a.z*w; acc[3]+=a.w*w;
        }
        __syncthreads();
    }
    const int j = jb + tx; const float bv = bias[j];
    #pragma unroll
    for(int i=0;i<4;i++){
        float v = acc[i] + bv;
        if(act==1) v = sigm(v); else if(act==2) v = fmaxf(v, 0.0f);
        C[(4*ty+i)*J + j] = v;
    }
}
__global__ void k_cat(){
    int idx = blockIdx.x*blockDim.x + threadIdx.x;
    if(idx < Bb*2*Hh){
        int b = idx>>10, k = idx & 1023;
        g_cat[idx] = (k < Hh) ? g_proj[b*Hh + k] : g_hG[b*Hh + (k-Hh)];
    }
}
__global__ void k_combine(){
    int idx = blockIdx.x*blockDim.x + threadIdx.x;
    if(idx < Bb*Hh){
        float g = g_gate[idx];
        g_comb[idx] = g*g_proj[idx] + (1.0f - g)*g_hG[idx];
    }
}

extern "C" void kernel_launch(void* const* d_in, const int* in_sizes, int n_in,
                              void* d_out, int out_size)
{
    const float* x     = (const float*)d_in[0];
    const float* Win   = (const float*)d_in[1];
    const float* Wres  = (const float*)d_in[2];
    const float* Wih   = (const float*)d_in[3];
    const float* Whh   = (const float*)d_in[4];
    const float* bih   = (const float*)d_in[5];
    const float* bhh   = (const float*)d_in[6];
    const float* projW = (const float*)d_in[7];
    const float* projb = (const float*)d_in[8];
    const float* gateW = (const float*)d_in[9];
    const float* gateb = (const float*)d_in[10];
    const float* hW1   = (const float*)d_in[11];
    const float* hb1   = (const float*)d_in[12];
    const float* hW2   = (const float*)d_in[13];
    const float* hb2   = (const float*)d_in[14];
    float* out = (float*)d_out;

    void *pE, *pProj, *pCat, *pComb, *pHid, *pGate;
    cudaGetSymbolAddress(&pE,    g_hE);
    cudaGetSymbolAddress(&pProj, g_proj);
    cudaGetSymbolAddress(&pCat,  g_cat);
    cudaGetSymbolAddress(&pComb, g_comb);
    cudaGetSymbolAddress(&pGate, g_gate);
    cudaGetSymbolAddress(&pHid,  g_hid);

    cudaFuncSetAttribute(k_all, cudaFuncAttributeMaxDynamicSharedMemorySize, SMEM_BYTES);

    k_prepWE<<<(Rr*KE)/256, 256>>>(Wres, Win);
    k_prepWG<<<(MG*KG)/256, 256>>>(Whh, Wih);
    k_prepX <<<(Tt*Ii*Bb)/256, 256>>>(x);
    k_init0 <<<512, 256>>>();
    k_all<<<NBLK, 128, SMEM_BYTES>>>(bih, bhh);
    k_tr<<<512, 256>>>();
    k_gemm<<<32, 256>>>((const float*)pE,   projW, projb, (float*)pProj, Rr,   Hh, 0);
    k_cat    <<<256, 256>>>();
    k_gemm<<<32, 256>>>((const float*)pCat, gateW, gateb, (float*)pGate, 2*Hh, Hh, 1);
    k_combine<<<128, 256>>>();
    k_gemm<<<32, 256>>>((const float*)pComb, hW1,  hb1,   (float*)pHid,  Hh,   Hh, 2);
    k_gemm<<<8,  256>>>((const float*)pHid,  hW2,  hb2,   out,           Hh,   Oo, 0);
}

// round 10
// speedup vs baseline: 7.9978x; 1.0380x over previous
#include <cuda_runtime.h>
#include <cuda_bf16.h>
#include <math.h>

#define Bb 64
#define Tt 512
#define Ii 128
#define Rr 2048
#define Hh 512
#define Oo 128
#define KE 2176
#define KG 640
#define MG 1536
#define NBLK 140
#define SUB_ELEMS 8448            // bf16 elems per 16-k sub-chunk
#define SUB_BYTES 16896
#define STG_BYTES (2*SUB_BYTES)   // 33792 (k=32 stage)
#define STG_ELEMS (2*SUB_ELEMS)
#define SMEM_BYTES (4*STG_BYTES)  // 135168

typedef __nv_bfloat16 bf;

// ---------------- device scratch ----------------
__device__ bf WEh[Rr*KE], WEl[Rr*KE];      // ESN weights^T hi/lo  [c][k]
__device__ bf WGh[MG*KG], WGl[MG*KG];      // GRU weights^T hi/lo  [m][k]
__device__ bf Xh[Tt*Ii*Bb], Xl[Tt*Ii*Bb];  // x transposed hi/lo   [t][i][b]
__device__ bf HEh[Rr*Bb], HEl[Rr*Bb];      // ESN state bf16       [c][b]
__device__ bf HGh[Hh*Bb], HGl[Hh*Bb];      // GRU state bf16       [j][b]
__device__ float hET[Rr*Bb], hGT[Hh*Bb];   // fp32 states (transposed)
__device__ float accE[7][Rr*Bb];           // ESN K-split partials
__device__ float accRZ[2][1024*Bb];        // GRU r,z rows, K-split
__device__ float accNH[2][Hh*Bb];          // GRU n-gate h-part, K-split
__device__ float accNX[Hh*Bb];             // GRU n-gate x-part
__device__ unsigned g_ctr;
__device__ float g_hE[Bb*Rr], g_hG[Bb*Hh];
__device__ float g_proj[Bb*Hh], g_cat[Bb*2*Hh], g_gate[Bb*Hh], g_comb[Bb*Hh], g_hid[Bb*Hh];

__device__ __forceinline__ float sigm(float x){ return 1.0f/(1.0f+expf(-x)); }
__device__ __forceinline__ float fsig(float x){ return __fdividef(1.0f, 1.0f + __expf(-x)); }
__device__ __forceinline__ float ftanh(float x){
    float e = __expf(2.0f*x);
    return 1.0f - __fdividef(2.0f, e + 1.0f);
}
__device__ __forceinline__ void bsplit(float v, bf* ph, bf* pl){
    bf h = __float2bfloat16(v); *ph = h; *pl = __float2bfloat16(v - __bfloat162float(h));
}
__device__ __forceinline__ unsigned bp2(bf a, bf b){
    return (unsigned)__bfloat16_as_ushort(a) | ((unsigned)__bfloat16_as_ushort(b) << 16);
}
__device__ __forceinline__ void bpack4(float v0,float v1,float v2,float v3, bf* dh, bf* dl){
    bf h0=__float2bfloat16(v0), h1=__float2bfloat16(v1), h2=__float2bfloat16(v2), h3=__float2bfloat16(v3);
    bf l0=__float2bfloat16(v0-__bfloat162float(h0));
    bf l1=__float2bfloat16(v1-__bfloat162float(h1));
    bf l2=__float2bfloat16(v2-__bfloat162float(h2));
    bf l3=__float2bfloat16(v3-__bfloat162float(h3));
    *(uint2*)dh = make_uint2(bp2(h0,h1), bp2(h2,h3));
    *(uint2*)dl = make_uint2(bp2(l0,l1), bp2(l2,l3));
}
__device__ __forceinline__ void ldsm4(unsigned* r, const bf* p){
    unsigned a = (unsigned)__cvta_generic_to_shared(p);
    asm volatile("ldmatrix.sync.aligned.m8n8.x4.shared.b16 {%0,%1,%2,%3},[%4];"
        : "=r"(r[0]),"=r"(r[1]),"=r"(r[2]),"=r"(r[3]) : "r"(a));
}
__device__ __forceinline__ void ldsm4t(unsigned* r, const bf* p){
    unsigned a = (unsigned)__cvta_generic_to_shared(p);
    asm volatile("ldmatrix.sync.aligned.m8n8.x4.trans.shared.b16 {%0,%1,%2,%3},[%4];"
        : "=r"(r[0]),"=r"(r[1]),"=r"(r[2]),"=r"(r[3]) : "r"(a));
}
__device__ __forceinline__ void mma_bf(float* d, const unsigned* a, const unsigned* b){
    asm volatile("mma.sync.aligned.m16n8k16.row.col.f32.bf16.bf16.f32 "
        "{%0,%1,%2,%3},{%4,%5,%6,%7},{%8,%9},{%0,%1,%2,%3};"
        : "+f"(d[0]),"+f"(d[1]),"+f"(d[2]),"+f"(d[3])
        : "r"(a[0]),"r"(a[1]),"r"(a[2]),"r"(a[3]),"r"(b[0]),"r"(b[1]));
}
__device__ __forceinline__ void cp16(unsigned dst, const void* src){
    asm volatile("cp.async.cg.shared.global [%0],[%1],16;" :: "r"(dst),"l"(src));
}

// ---------------- prep ----------------
__global__ void k_prepWE(const float* __restrict__ Wres, const float* __restrict__ Win){
    int idx = blockIdx.x*blockDim.x + threadIdx.x;        // c*KE + k
    int c = idx/KE, k = idx - c*KE;
    float w = (k < Rr) ? Wres[k*Rr + c] : Win[(k-Rr)*Rr + c];
    bsplit(w, &WEh[idx], &WEl[idx]);
}
__global__ void k_prepWG(const float* __restrict__ Whh, const float* __restrict__ Wih){
    int idx = blockIdx.x*blockDim.x + threadIdx.x;        // m*KG + k
    int m = idx/KG, k = idx - m*KG;
    float w = (k < Hh) ? Whh[m*Hh + k] : Wih[m*Ii + (k-Hh)];
    bsplit(w, &WGh[idx], &WGl[idx]);
}
__global__ void k_prepX(const float* __restrict__ x){
    int idx = blockIdx.x*blockDim.x + threadIdx.x;        // t*8192 + i*64 + b
    int t = idx >> 13, r = idx & 8191, i = r >> 6, b = r & 63;
    bsplit(x[b*(Tt*Ii) + t*Ii + i], &Xh[idx], &Xl[idx]);
}
__global__ void k_init0(){
    int i = blockIdx.x*blockDim.x + threadIdx.x;
    bf z = __float2bfloat16(0.0f);
    if(i == 0) g_ctr = 0u;
    if(i < Rr*Bb){ hET[i]=0.0f; HEh[i]=z; HEl[i]=z; }
    if(i < Hh*Bb){ hGT[i]=0.0f; HGh[i]=z; HGl[i]=z; }
}

// ---------------- persistent all-timesteps kernel ----------------
// 140 blocks x 128 thr, single wave. Per step: MMA -> barrier -> epilogue -> barrier.
// Stages carry k=32 (two 16-k sub-chunks); 4-stage cp.async pipeline, 3 ahead.
// Blocks: [0,112)  ESN: m-tile bx/7, K-split bx%7 (6x320 + 1x256) -> 10/8 stages
//         [112,128) GRU r,z: K-split of 640 -> 10 stages
//         [128,136) GRU n h-part: 2 splits of 512 -> 8 stages
//         [136,140) GRU n x-part: K=[512,640) -> 4 stages
__device__ __forceinline__ void gbar(unsigned target){
    __threadfence();
    __syncthreads();
    if(threadIdx.x == 0){
        atomicAdd(&g_ctr, 1u);
        volatile unsigned* p = &g_ctr;
        while(*p < target) __nanosleep(32);
    }
    __syncthreads();
    __threadfence();
}

__global__ void __launch_bounds__(128) k_all(
    const float* __restrict__ bih, const float* __restrict__ bhh)
{
    extern __shared__ __align__(16) bf sm[];
    const int tid = threadIdx.x, lane = tid & 31, wid = tid >> 5, bx = blockIdx.x;
    const unsigned sb = (unsigned)__cvta_generic_to_shared(sm);

    // ---- role setup ----
    const bf *Wh, *Wl, *Bh, *Bl; float* acc; int Kst, kbase, nch, kth;
    if(bx < 112){
        int m0 = (bx/7)*128, ks = bx%7;
        kbase = ks*320; nch = (ks < 6) ? 10 : 8; kth = Rr; Kst = KE;
        Wh = WEh + (size_t)m0*KE; Wl = WEl + (size_t)m0*KE;
        Bh = HEh; Bl = HEl; acc = accE[ks] + m0*Bb;
    } else if(bx < 128){
        int g = bx-112, m0 = (g>>1)*128, ks = g&1;
        kbase = ks*320; nch = 10; kth = Hh; Kst = KG;
        Wh = WGh + (size_t)m0*KG; Wl = WGl + (size_t)m0*KG;
        Bh = HGh; Bl = HGl; acc = accRZ[ks] + m0*Bb;
    } else if(bx < 136){
        int g = bx-128, mt = g>>1, ks = g&1;
        kbase = ks*256; nch = 8; kth = Hh; Kst = KG;
        Wh = WGh + (size_t)(1024 + mt*128)*KG; Wl = WGl + (size_t)(1024 + mt*128)*KG;
        Bh = HGh; Bl = HGl; acc = accNH[ks] + mt*128*Bb;
    } else {
        int mt = bx-136;
        kbase = 512; nch = 4; kth = Hh; Kst = KG;
        Wh = WGh + (size_t)(1024 + mt*128)*KG; Wl = WGl + (size_t)(1024 + mt*128)*KG;
        Bh = HGh; Bl = HGl; acc = accNX + mt*128*Bb;
    }
    const bf* wsrc_h = Wh + (size_t)tid*Kst;
    const bf* wsrc_l = Wl + (size_t)tid*Kst;
    const unsigned wdh = sb + tid*48;           // W hi dst within sub (bytes)
    const unsigned wdl = wdh + 6144;
    const unsigned bdh = sb + 12288 + (tid>>3)*144 + (tid&7)*16;
    const unsigned bdl = bdh + 2304;
    const int krow = tid >> 3, boff = (tid & 7) * 8;
    const int mw = wid*32, ar = lane & 15, ac = (lane>>4)*8;
    const int r4 = lane>>2, c2 = 2*(lane&3);
    const int gbase = bx*128 + tid;
    const int NT = NBLK*128;

    for(int t = 0; t < Tt; t++){
        const bf* Xht = Xh + (size_t)t*Ii*Bb;
        const bf* Xlt = Xl + (size_t)t*Ii*Bb;

        auto issue = [&](int c){
            unsigned st = (unsigned)(c & 3) * STG_BYTES;
            int k0 = kbase + c*32;
            #pragma unroll
            for(int sub = 0; sub < 2; ++sub){
                unsigned so = st + sub*SUB_BYTES;
                int ks16 = k0 + sub*16;
                cp16(wdh + so,      wsrc_h + ks16);
                cp16(wdh + so + 16, wsrc_h + ks16 + 8);
                cp16(wdl + so,      wsrc_l + ks16);
                cp16(wdl + so + 16, wsrc_l + ks16 + 8);
                int kr = ks16 + krow;
                const bf* q = (kr < kth) ? Bh + kr*Bb + boff : Xht + (kr-kth)*Bb + boff;
                cp16(bdh + so, q);
                q = (kr < kth) ? Bl + kr*Bb + boff : Xlt + (kr-kth)*Bb + boff;
                cp16(bdl + so, q);
            }
            asm volatile("cp.async.commit_group;");
        };

        float d[2][8][4];
        #pragma unroll
        for(int i=0;i<2;i++)
            #pragma unroll
            for(int j=0;j<8;j++)
                #pragma unroll
                for(int q=0;q<4;q++) d[i][j][q] = 0.0f;

        issue(0); issue(1); issue(2);

        for(int c = 0; c < nch; c++){
            if(c < nch-2)       asm volatile("cp.async.wait_group 2;");
            else if(c == nch-2) asm volatile("cp.async.wait_group 1;");
            else                asm volatile("cp.async.wait_group 0;");
            __syncthreads();
            if(c + 3 < nch) issue(c + 3);

            #pragma unroll
            for(int sub = 0; sub < 2; ++sub){
                const bf* stg = sm + (size_t)(c & 3) * STG_ELEMS + sub*SUB_ELEMS;
                const bf* swh = stg;
                const bf* swl = stg + 3072;
                const bf* sbh = stg + 6144;
                const bf* sbl = stg + 7296;

                unsigned A[2][2][4], Bf[2][4][4];
                #pragma unroll
                for(int mt=0; mt<2; mt++){
                    ldsm4(A[mt][0], swh + (mw + mt*16 + ar)*24 + ac);
                    ldsm4(A[mt][1], swl + (mw + mt*16 + ar)*24 + ac);
                }
                #pragma unroll
                for(int np=0; np<4; np++){
                    ldsm4t(Bf[0][np], sbh + ar*72 + np*16 + ac);
                    ldsm4t(Bf[1][np], sbl + ar*72 + np*16 + ac);
                }
                #pragma unroll
                for(int mt=0; mt<2; mt++)
                    #pragma unroll
                    for(int nt=0; nt<8; nt++){
                        const unsigned* bh = &Bf[0][nt>>1][(nt&1)*2];
                        const unsigned* bl = &Bf[1][nt>>1][(nt&1)*2];
                        mma_bf(d[mt][nt], A[mt][0], bh);   // hi*hi
                        mma_bf(d[mt][nt], A[mt][1], bh);   // lo*hi
                        mma_bf(d[mt][nt], A[mt][0], bl);   // hi*lo
                    }
            }
        }
        #pragma unroll
        for(int mt=0; mt<2; mt++)
            #pragma unroll
            for(int nt=0; nt<8; nt++){
                int m = mw + mt*16 + r4, b = nt*8 + c2;
                *(float2*)&acc[m*Bb + b]     = make_float2(d[mt][nt][0], d[mt][nt][1]);
                *(float2*)&acc[(m+8)*Bb + b] = make_float2(d[mt][nt][2], d[mt][nt][3]);
            }

        gbar((unsigned)NBLK * (unsigned)(2*t + 1));

        // ---------- epilogue ----------
        for(int g = gbase; g < (Rr*Bb)/4; g += NT){
            int o = g*4;
            float4 a0 = *(const float4*)&accE[0][o];
            float4 a1 = *(const float4*)&accE[1][o];
            float4 a2 = *(const float4*)&accE[2][o];
            float4 a3 = *(const float4*)&accE[3][o];
            float4 a4 = *(const float4*)&accE[4][o];
            float4 a5 = *(const float4*)&accE[5][o];
            float4 a6 = *(const float4*)&accE[6][o];
            float4 hp = *(const float4*)&hET[o];
            float n0 = 0.7f*hp.x + 0.3f*ftanh(a0.x+a1.x+a2.x+a3.x+a4.x+a5.x+a6.x);
            float n1 = 0.7f*hp.y + 0.3f*ftanh(a0.y+a1.y+a2.y+a3.y+a4.y+a5.y+a6.y);
            float n2 = 0.7f*hp.z + 0.3f*ftanh(a0.z+a1.z+a2.z+a3.z+a4.z+a5.z+a6.z);
            float n3 = 0.7f*hp.w + 0.3f*ftanh(a0.w+a1.w+a2.w+a3.w+a4.w+a5.w+a6.w);
            *(float4*)&hET[o] = make_float4(n0,n1,n2,n3);
            bpack4(n0,n1,n2,n3, &HEh[o], &HEl[o]);
        }
        for(int g = gbase; g < (Hh*Bb)/4; g += NT){
            int j = g >> 4, b4 = (g & 15)*4, ix = j*64 + b4;
            float4 r0 = *(const float4*)&accRZ[0][ix];
            float4 r1 = *(const float4*)&accRZ[1][ix];
            float4 z0 = *(const float4*)&accRZ[0][(j+Hh)*64 + b4];
            float4 z1 = *(const float4*)&accRZ[1][(j+Hh)*64 + b4];
            float4 h0 = *(const float4*)&accNH[0][ix];
            float4 h1 = *(const float4*)&accNH[1][ix];
            float4 xn = *(const float4*)&accNX[ix];
            float4 hp = *(const float4*)&hGT[ix];
            float br  = bih[j] + bhh[j];
            float bz2 = bih[j+Hh] + bhh[j+Hh];
            float bxn = bih[j+2*Hh], bhn = bhh[j+2*Hh];
            float n[4];
            #pragma unroll
            for(int i=0;i<4;i++){
                float rv = (&r0.x)[i] + (&r1.x)[i];
                float zv = (&z0.x)[i] + (&z1.x)[i];
                float hnv = (&h0.x)[i] + (&h1.x)[i];
                float xnv = (&xn.x)[i];
                float hpv = (&hp.x)[i];
                float rg = fsig(rv + br);
                float zg = fsig(zv + bz2);
                float nn = ftanh(xnv + bxn + rg*(hnv + bhn));
                n[i] = (1.0f - zg)*nn + zg*hpv;
            }
            *(float4*)&hGT[ix] = make_float4(n[0],n[1],n[2],n[3]);
            bpack4(n[0],n[1],n[2],n[3], &HGh[ix], &HGl[ix]);
        }

        gbar((unsigned)NBLK * (unsigned)(2*t + 2));
    }
}

// ---------------- final transpose + head ----------------
__global__ void k_tr(){
    int idx = blockIdx.x*blockDim.x + threadIdx.x;
    if(idx < Bb*Rr){ int b = idx/Rr, c = idx - b*Rr; g_hE[idx] = hET[c*Bb + b]; }
    if(idx < Bb*Hh){ int b = idx/Hh, j = idx - b*Hh; g_hG[idx] = hGT[j*Bb + b]; }
}
__global__ __launch_bounds__(256) void k_gemm(
    const float* __restrict__ A, const float* __restrict__ W,
    const float* __restrict__ bias, float* __restrict__ C, int K, int J, int act)
{
    __shared__ __align__(16) float sA[32*68];
    __shared__ float sW2[32*16];
    const int tid = threadIdx.x, tx = tid & 15, ty = tid >> 4, jb = blockIdx.x*16;
    float acc[4] = {0.f,0.f,0.f,0.f};
    for(int ch=0; ch<(K>>5); ch++){
        const int k0 = ch*32;
        #pragma unroll
        for(int r=0;r<2;r++){
            int idx = tid + r*256, b = idx>>3, kq = idx&7;
            float4 v = *(const float4*)(A + b*K + k0 + 4*kq);
            sA[(4*kq+0)*68+b]=v.x; sA[(4*kq+1)*68+b]=v.y;
            sA[(4*kq+2)*68+b]=v.z; sA[(4*kq+3)*68+b]=v.w;
        }
        #pragma unroll
        for(int r=0;r<2;r++){
            int idx = tid + r*256, kr = idx&31, c = idx>>5;
            sW2[kr*16+c] = W[(jb+c)*K + k0 + kr];
        }
        __syncthreads();
        #pragma unroll
        for(int kk=0;kk<32;kk++){
            float w = sW2[kk*16+tx];
            float4 a = *(const float4*)&sA[kk*68 + 4*ty];
            acc[0]+=a.x*w; acc[1]+=a.y*w; acc[2]+=a.z*w; acc[3]+=a.w*w;
        }
        __syncthreads();
    }
    const int j = jb + tx; const float bv = bias[j];
    #pragma unroll
    for(int i=0;i<4;i++){
        float v = acc[i] + bv;
        if(act==1) v = sigm(v); else if(act==2) v = fmaxf(v, 0.0f);
        C[(4*ty+i)*J + j] = v;
    }
}
__global__ void k_cat(){
    int idx = blockIdx.x*blockDim.x + threadIdx.x;
    if(idx < Bb*2*Hh){
        int b = idx>>10, k = idx & 1023;
        g_cat[idx] = (k < Hh) ? g_proj[b*Hh + k] : g_hG[b*Hh + (k-Hh)];
    }
}
__global__ void k_combine(){
    int idx = blockIdx.x*blockDim.x + threadIdx.x;
    if(idx < Bb*Hh){
        float g = g_gate[idx];
        g_comb[idx] = g*g_proj[idx] + (1.0f - g)*g_hG[idx];
    }
}

extern "C" void kernel_launch(void* const* d_in, const int* in_sizes, int n_in,
                              void* d_out, int out_size)
{
    const float* x     = (const float*)d_in[0];
    const float* Win   = (const float*)d_in[1];
    const float* Wres  = (const float*)d_in[2];
    const float* Wih   = (const float*)d_in[3];
    const float* Whh   = (const float*)d_in[4];
    const float* bih   = (const float*)d_in[5];
    const float* bhh   = (const float*)d_in[6];
    const float* projW = (const float*)d_in[7];
    const float* projb = (const float*)d_in[8];
    const float* gateW = (const float*)d_in[9];
    const float* gateb = (const float*)d_in[10];
    const float* hW1   = (const float*)d_in[11];
    const float* hb1   = (const float*)d_in[12];
    const float* hW2   = (const float*)d_in[13];
    const float* hb2   = (const float*)d_in[14];
    float* out = (float*)d_out;

    void *pE, *pProj, *pCat, *pComb, *pHid, *pGate;
    cudaGetSymbolAddress(&pE,    g_hE);
    cudaGetSymbolAddress(&pProj, g_proj);
    cudaGetSymbolAddress(&pCat,  g_cat);
    cudaGetSymbolAddress(&pComb, g_comb);
    cudaGetSymbolAddress(&pGate, g_gate);
    cudaGetSymbolAddress(&pHid,  g_hid);

    cudaFuncSetAttribute(k_all, cudaFuncAttributeMaxDynamicSharedMemorySize, SMEM_BYTES);

    k_prepWE<<<(Rr*KE)/256, 256>>>(Wres, Win);
    k_prepWG<<<(MG*KG)/256, 256>>>(Whh, Wih);
    k_prepX <<<(Tt*Ii*Bb)/256, 256>>>(x);
    k_init0 <<<512, 256>>>();
    k_all<<<NBLK, 128, SMEM_BYTES>>>(bih, bhh);
    k_tr<<<512, 256>>>();
    k_gemm<<<32, 256>>>((const float*)pE,   projW, projb, (float*)pProj, Rr,   Hh, 0);
    k_cat    <<<256, 256>>>();
    k_gemm<<<32, 256>>>((const float*)pCat, gateW, gateb, (float*)pGate, 2*Hh, Hh, 1);
    k_combine<<<128, 256>>>();
    k_gemm<<<32, 256>>>((const float*)pComb, hW1,  hb1,   (float*)pHid,  Hh,   Hh, 2);
    k_gemm<<<8,  256>>>((const float*)pHid,  hW2,  hb2,   out,           Hh,   Oo, 0);
}

// round 12
// speedup vs baseline: 8.8157x; 1.1023x over previous
#include <cuda_runtime.h>
#include <cuda_bf16.h>
#include <math.h>

#define Bb 64
#define Tt 512
#define Ii 128
#define Rr 2048
#define Hh 512
#define Oo 128
#define KE 2176
#define KG 640
#define MG 1536
#define NBLK 140
#define NTHR 256
#define SUB_ELEMS 8448            // bf16 elems per 16-k sub-chunk
#define SUB_BYTES 16896
#define STG_BYTES (2*SUB_BYTES)   // 33792 (k=32 stage)
#define STG_ELEMS (2*SUB_ELEMS)
#define SMEM_BYTES (4*STG_BYTES)  // 135168

typedef __nv_bfloat16 bf;

// ---------------- device scratch ----------------
__device__ bf WEh[Rr*KE], WEl[Rr*KE];      // ESN weights^T hi/lo  [c][k]
__device__ bf WGh[MG*KG], WGl[MG*KG];      // GRU weights^T hi/lo  [m][k]
__device__ bf Xh[Tt*Ii*Bb], Xl[Tt*Ii*Bb];  // x transposed hi/lo   [t][i][b]
__device__ bf HEh[Rr*Bb], HEl[Rr*Bb];      // ESN state bf16       [k][b]
__device__ bf HGh[Hh*Bb], HGl[Hh*Bb];      // GRU state bf16       [j][b]
__device__ float hET[Rr*Bb], hGT[Hh*Bb];   // fp32 states (transposed)
__device__ float accE[7][Rr*Bb];           // ESN K-split partials
__device__ float accRZ[2][1024*Bb];        // GRU r,z rows, K-split
__device__ float accNH[2][Hh*Bb];          // GRU n-gate h-part, K-split
__device__ float accNX[Hh*Bb];             // GRU n-gate x-part
__device__ unsigned g_ctr;
__device__ float g_hE[Bb*Rr], g_hG[Bb*Hh];
__device__ float g_proj[Bb*Hh], g_cat[Bb*2*Hh], g_gate[Bb*Hh], g_comb[Bb*Hh], g_hid[Bb*Hh];

__device__ __forceinline__ float sigm(float x){ return 1.0f/(1.0f+expf(-x)); }
__device__ __forceinline__ float fsig(float x){ return __fdividef(1.0f, 1.0f + __expf(-x)); }
__device__ __forceinline__ float ftanh(float x){
    float e = __expf(2.0f*x);
    return 1.0f - __fdividef(2.0f, e + 1.0f);
}
__device__ __forceinline__ void bsplit(float v, bf* ph, bf* pl){
    bf h = __float2bfloat16(v); *ph = h; *pl = __float2bfloat16(v - __bfloat162float(h));
}
__device__ __forceinline__ unsigned bp2(bf a, bf b){
    return (unsigned)__bfloat16_as_ushort(a) | ((unsigned)__bfloat16_as_ushort(b) << 16);
}
__device__ __forceinline__ void bpack4(float v0,float v1,float v2,float v3, bf* dh, bf* dl){
    bf h0=__float2bfloat16(v0), h1=__float2bfloat16(v1), h2=__float2bfloat16(v2), h3=__float2bfloat16(v3);
    bf l0=__float2bfloat16(v0-__bfloat162float(h0));
    bf l1=__float2bfloat16(v1-__bfloat162float(h1));
    bf l2=__float2bfloat16(v2-__bfloat162float(h2));
    bf l3=__float2bfloat16(v3-__bfloat162float(h3));
    *(uint2*)dh = make_uint2(bp2(h0,h1), bp2(h2,h3));
    *(uint2*)dl = make_uint2(bp2(l0,l1), bp2(l2,l3));
}
__device__ __forceinline__ void ldsm4(unsigned* r, const bf* p){
    unsigned a = (unsigned)__cvta_generic_to_shared(p);
    asm volatile("ldmatrix.sync.aligned.m8n8.x4.shared.b16 {%0,%1,%2,%3},[%4];"
        : "=r"(r[0]),"=r"(r[1]),"=r"(r[2]),"=r"(r[3]) : "r"(a));
}
__device__ __forceinline__ void ldsm4t(unsigned* r, const bf* p){
    unsigned a = (unsigned)__cvta_generic_to_shared(p);
    asm volatile("ldmatrix.sync.aligned.m8n8.x4.trans.shared.b16 {%0,%1,%2,%3},[%4];"
        : "=r"(r[0]),"=r"(r[1]),"=r"(r[2]),"=r"(r[3]) : "r"(a));
}
__device__ __forceinline__ void mma_bf(float* d, const unsigned* a, const unsigned* b){
    asm volatile("mma.sync.aligned.m16n8k16.row.col.f32.bf16.bf16.f32 "
        "{%0,%1,%2,%3},{%4,%5,%6,%7},{%8,%9},{%0,%1,%2,%3};"
        : "+f"(d[0]),"+f"(d[1]),"+f"(d[2]),"+f"(d[3])
        : "r"(a[0]),"r"(a[1]),"r"(a[2]),"r"(a[3]),"r"(b[0]),"r"(b[1]));
}
__device__ __forceinline__ void cp16(unsigned dst, const void* src){
    asm volatile("cp.async.cg.shared.global [%0],[%1],16;" :: "r"(dst),"l"(src));
}

// ---------------- prep ----------------
__global__ void k_prepWE(const float* __restrict__ Wres, const float* __restrict__ Win){
    int idx = blockIdx.x*blockDim.x + threadIdx.x;        // c*KE + k
    int c = idx/KE, k = idx - c*KE;
    float w = (k < Rr) ? Wres[k*Rr + c] : Win[(k-Rr)*Rr + c];
    bsplit(w, &WEh[idx], &WEl[idx]);
}
__global__ void k_prepWG(const float* __restrict__ Whh, const float* __restrict__ Wih){
    int idx = blockIdx.x*blockDim.x + threadIdx.x;        // m*KG + k
    int m = idx/KG, k = idx - m*KG;
    float w = (k < Hh) ? Whh[m*Hh + k] : Wih[m*Ii + (k-Hh)];
    bsplit(w, &WGh[idx], &WGl[idx]);
}
// merged x-transpose + state init (keeps launch count low; k_all should land at ncu -s 5)
__global__ void k_prepXI(const float* __restrict__ x){
    int idx = blockIdx.x*blockDim.x + threadIdx.x;        // t*8192 + i*64 + b
    int t = idx >> 13, r = idx & 8191, i = r >> 6, b = r & 63;
    bsplit(x[b*(Tt*Ii) + t*Ii + i], &Xh[idx], &Xl[idx]);
    bf z = __float2bfloat16(0.0f);
    if(idx == 0) g_ctr = 0u;
    if(idx < Rr*Bb){ hET[idx]=0.0f; HEh[idx]=z; HEl[idx]=z; }
    if(idx < Hh*Bb){ hGT[idx]=0.0f; HGh[idx]=z; HGl[idx]=z; }
}

__device__ __forceinline__ void gbar(unsigned target){
    __threadfence();
    __syncthreads();
    if(threadIdx.x == 0){
        atomicAdd(&g_ctr, 1u);
        volatile unsigned* p = &g_ctr;
        while(*p < target) __nanosleep(32);
    }
    __syncthreads();
    __threadfence();
}

// ---------------- persistent all-timesteps kernel ----------------
// 140 blocks x 256 thr (8 warps: each owns an m16 slice -> 2 warps/SMSP).
// Per step: MMA -> barrier -> epilogue -> barrier. k=32 stages, 4-slot ring, 3 ahead.
// Blocks: [0,112)  ESN: m-tile bx/7, K-split bx%7 (6x320 + 1x256) -> 10/8 stages
//         [112,128) GRU r,z: K-split of 640 -> 10 stages
//         [128,136) GRU n h-part: 2 splits of 512 -> 8 stages
//         [136,140) GRU n x-part: K=[512,640) -> 4 stages
__global__ void __launch_bounds__(NTHR) k_all(
    const float* __restrict__ bih, const float* __restrict__ bhh)
{
    extern __shared__ __align__(16) bf sm[];
    const int tid = threadIdx.x, lane = tid & 31, wid = tid >> 5, bx = blockIdx.x;
    const unsigned sb = (unsigned)__cvta_generic_to_shared(sm);

    // ---- role setup ----
    const bf *Wh, *Wl, *Bh, *Bl; float* acc; int Kst, kbase, nch, kth;
    if(bx < 112){
        int m0 = (bx/7)*128, ks = bx%7;
        kbase = ks*320; nch = (ks < 6) ? 10 : 8; kth = Rr; Kst = KE;
        Wh = WEh + (size_t)m0*KE; Wl = WEl + (size_t)m0*KE;
        Bh = HEh; Bl = HEl; acc = accE[ks] + m0*Bb;
    } else if(bx < 128){
        int g = bx-112, m0 = (g>>1)*128, ks = g&1;
        kbase = ks*320; nch = 10; kth = Hh; Kst = KG;
        Wh = WGh + (size_t)m0*KG; Wl = WGl + (size_t)m0*KG;
        Bh = HGh; Bl = HGl; acc = accRZ[ks] + m0*Bb;
    } else if(bx < 136){
        int g = bx-128, mt = g>>1, ks = g&1;
        kbase = ks*256; nch = 8; kth = Hh; Kst = KG;
        Wh = WGh + (size_t)(1024 + mt*128)*KG; Wl = WGl + (size_t)(1024 + mt*128)*KG;
        Bh = HGh; Bl = HGl; acc = accNH[ks] + mt*128*Bb;
    } else {
        int mt = bx-136;
        kbase = 512; nch = 4; kth = Hh; Kst = KG;
        Wh = WGh + (size_t)(1024 + mt*128)*KG; Wl = WGl + (size_t)(1024 + mt*128)*KG;
        Bh = HGh; Bl = HGl; acc = accNX + mt*128*Bb;
    }
    // loader mapping (256 threads): W row = tid>>1, 16B half = tid&1
    const int wrow = tid >> 1, wpart = tid & 1;
    const unsigned wdh = sb + (unsigned)(wrow*48 + wpart*16);
    const unsigned wdl = wdh + 6144u;
    const bf* wsrc_h = Wh + (size_t)wrow*Kst + wpart*8;
    const bf* wsrc_l = Wl + (size_t)wrow*Kst + wpart*8;
    // B: tid<128 loads hi, tid>=128 loads lo
    const int btid = tid & 127;
    const int krow = btid >> 3, boff = (btid & 7) * 8;
    const unsigned bd = sb + 12288u + (unsigned)(krow*144 + (btid&7)*16) + ((tid < 128) ? 0u : 2304u);
    const bf* SBst = (tid < 128) ? Bh : Bl;
    const int mw = wid*16, ar = lane & 15, ac = (lane>>4)*8;
    const int r4 = lane>>2, c2 = 2*(lane&3);
    const int gbase = bx*NTHR + tid;
    const int NT = NBLK*NTHR;

    for(int t = 0; t < Tt; t++){
        const bf* Xt = ((tid < 128) ? Xh : Xl) + (size_t)t*Ii*Bb;

        auto issue = [&](int c){
            unsigned st = (unsigned)(c & 3) * STG_BYTES;
            int k0 = kbase + c*32;
            #pragma unroll
            for(int sub = 0; sub < 2; ++sub){
                unsigned so = st + sub*SUB_BYTES;
                int ks16 = k0 + sub*16;
                cp16(wdh + so, wsrc_h + ks16);
                cp16(wdl + so, wsrc_l + ks16);
                int kr = ks16 + krow;
                const bf* q = (kr < kth) ? SBst + kr*Bb + boff : Xt + (kr-kth)*Bb + boff;
                cp16(bd + so, q);
            }
            asm volatile("cp.async.commit_group;");
        };

        float d[8][4];
        #pragma unroll
        for(int j=0;j<8;j++)
            #pragma unroll
            for(int q=0;q<4;q++) d[j][q] = 0.0f;

        issue(0); issue(1); issue(2);

        for(int c = 0; c < nch; c++){
            if(c < nch-2)       asm volatile("cp.async.wait_group 2;");
            else if(c == nch-2) asm volatile("cp.async.wait_group 1;");
            else                asm volatile("cp.async.wait_group 0;");
            __syncthreads();
            if(c + 3 < nch) issue(c + 3);

            #pragma unroll
            for(int sub = 0; sub < 2; ++sub){
                const bf* stg = sm + (size_t)(c & 3) * STG_ELEMS + sub*SUB_ELEMS;
                const bf* swh = stg;
                const bf* swl = stg + 3072;
                const bf* sbh = stg + 6144;
                const bf* sbl = stg + 7296;

                unsigned A[2][4], Bf[2][4][4];
                ldsm4(A[0], swh + (mw + ar)*24 + ac);
                ldsm4(A[1], swl + (mw + ar)*24 + ac);
                #pragma unroll
                for(int np=0; np<4; np++){
                    ldsm4t(Bf[0][np], sbh + ar*72 + np*16 + ac);
                    ldsm4t(Bf[1][np], sbl + ar*72 + np*16 + ac);
                }
                #pragma unroll
                for(int nt=0; nt<8; nt++){
                    const unsigned* bh = &Bf[0][nt>>1][(nt&1)*2];
                    const unsigned* bl = &Bf[1][nt>>1][(nt&1)*2];
                    mma_bf(d[nt], A[0], bh);   // hi*hi
                    mma_bf(d[nt], A[1], bh);   // lo*hi
                    mma_bf(d[nt], A[0], bl);   // hi*lo
                }
            }
        }
        #pragma unroll
        for(int nt=0; nt<8; nt++){
            int m = mw + r4, b = nt*8 + c2;
            *(float2*)&acc[m*Bb + b]     = make_float2(d[nt][0], d[nt][1]);
            *(float2*)&acc[(m+8)*Bb + b] = make_float2(d[nt][2], d[nt][3]);
        }

        gbar((unsigned)NBLK * (unsigned)(2*t + 1));

        // ---------- epilogue ----------
        for(int g = gbase; g < (Rr*Bb)/4; g += NT){
            int o = g*4;
            float4 a0 = *(const float4*)&accE[0][o];
            float4 a1 = *(const float4*)&accE[1][o];
            float4 a2 = *(const float4*)&accE[2][o];
            float4 a3 = *(const float4*)&accE[3][o];
            float4 a4 = *(const float4*)&accE[4][o];
            float4 a5 = *(const float4*)&accE[5][o];
            float4 a6 = *(const float4*)&accE[6][o];
            float4 hp = *(const float4*)&hET[o];
            float n0 = 0.7f*hp.x + 0.3f*ftanh(a0.x+a1.x+a2.x+a3.x+a4.x+a5.x+a6.x);
            float n1 = 0.7f*hp.y + 0.3f*ftanh(a0.y+a1.y+a2.y+a3.y+a4.y+a5.y+a6.y);
            float n2 = 0.7f*hp.z + 0.3f*ftanh(a0.z+a1.z+a2.z+a3.z+a4.z+a5.z+a6.z);
            float n3 = 0.7f*hp.w + 0.3f*ftanh(a0.w+a1.w+a2.w+a3.w+a4.w+a5.w+a6.w);
            *(float4*)&hET[o] = make_float4(n0,n1,n2,n3);
            bpack4(n0,n1,n2,n3, &HEh[o], &HEl[o]);
        }
        for(int g = gbase; g < (Hh*Bb)/4; g += NT){
            int j = g >> 4, b4 = (g & 15)*4, ix = j*64 + b4;
            float4 r0 = *(const float4*)&accRZ[0][ix];
            float4 r1 = *(const float4*)&accRZ[1][ix];
            float4 z0 = *(const float4*)&accRZ[0][(j+Hh)*64 + b4];
            float4 z1 = *(const float4*)&accRZ[1][(j+Hh)*64 + b4];
            float4 h0 = *(const float4*)&accNH[0][ix];
            float4 h1 = *(const float4*)&accNH[1][ix];
            float4 xn = *(const float4*)&accNX[ix];
            float4 hp = *(const float4*)&hGT[ix];
            float br  = bih[j] + bhh[j];
            float bz2 = bih[j+Hh] + bhh[j+Hh];
            float bxn = bih[j+2*Hh], bhn = bhh[j+2*Hh];
            float n[4];
            #pragma unroll
            for(int i=0;i<4;i++){
                float rv = (&r0.x)[i] + (&r1.x)[i];
                float zv = (&z0.x)[i] + (&z1.x)[i];
                float hnv = (&h0.x)[i] + (&h1.x)[i];
                float xnv = (&xn.x)[i];
                float hpv = (&hp.x)[i];
                float rg = fsig(rv + br);
                float zg = fsig(zv + bz2);
                float nn = ftanh(xnv + bxn + rg*(hnv + bhn));
                n[i] = (1.0f - zg)*nn + zg*hpv;
            }
            *(float4*)&hGT[ix] = make_float4(n[0],n[1],n[2],n[3]);
            bpack4(n[0],n[1],n[2],n[3], &HGh[ix], &HGl[ix]);
        }

        gbar((unsigned)NBLK * (unsigned)(2*t + 2));
    }
}

// ---------------- final transpose + head ----------------
__global__ void k_tr(){
    int idx = blockIdx.x*blockDim.x + threadIdx.x;
    if(idx < Bb*Rr){ int b = idx/Rr, c = idx - b*Rr; g_hE[idx] = hET[c*Bb + b]; }
    if(idx < Bb*Hh){ int b = idx/Hh, j = idx - b*Hh; g_hG[idx] = hGT[j*Bb + b]; }
}
__global__ __launch_bounds__(256) void k_gemm(
    const float* __restrict__ A, const float* __restrict__ W,
    const float* __restrict__ bias, float* __restrict__ C, int K, int J, int act)
{
    __shared__ __align__(16) float sA[32*68];
    __shared__ float sW2[32*16];
    const int tid = threadIdx.x, tx = tid & 15, ty = tid >> 4, jb = blockIdx.x*16;
    float acc[4] = {0.f,0.f,0.f,0.f};
    for(int ch=0; ch<(K>>5); ch++){
        const int k0 = ch*32;
        #pragma unroll
        for(int r=0;r<2;r++){
            int idx = tid + r*256, b = idx>>3, kq = idx&7;
            float4 v = *(const float4*)(A + b*K + k0 + 4*kq);
            sA[(4*kq+0)*68+b]=v.x; sA[(4*kq+1)*68+b]=v.y;
            sA[(4*kq+2)*68+b]=v.z; sA[(4*kq+3)*68+b]=v.w;
        }
        #pragma unroll
        for(int r=0;r<2;r++){
            int idx = tid + r*256, kr = idx&31, c = idx>>5;
            sW2[kr*16+c] = W[(jb+c)*K + k0 + kr];
        }
        __syncthreads();
        #pragma unroll
        for(int kk=0;kk<32;kk++){
            float w = sW2[kk*16+tx];
            float4 a = *(const float4*)&sA[kk*68 + 4*ty];
            acc[0]+=a.x*w; acc[1]+=a.y*w; acc[2]+=a.z*w; acc[3]+=a.w*w;
        }
        __syncthreads();
    }
    const int j = jb + tx; const float bv = bias[j];
    #pragma unroll
    for(int i=0;i<4;i++){
        float v = acc[i] + bv;
        if(act==1) v = sigm(v); else if(act==2) v = fmaxf(v, 0.0f);
        C[(4*ty+i)*J + j] = v;
    }
}
__global__ void k_cat(){
    int idx = blockIdx.x*blockDim.x + threadIdx.x;
    if(idx < Bb*2*Hh){
        int b = idx>>10, k = idx & 1023;
        g_cat[idx] = (k < Hh) ? g_proj[b*Hh + k] : g_hG[b*Hh + (k-Hh)];
    }
}
__global__ void k_combine(){
    int idx = blockIdx.x*blockDim.x + threadIdx.x;
    if(idx < Bb*Hh){
        float g = g_gate[idx];
        g_comb[idx] = g*g_proj[idx] + (1.0f - g)*g_hG[idx];
    }
}

extern "C" void kernel_launch(void* const* d_in, const int* in_sizes, int n_in,
                              void* d_out, int out_size)
{
    const float* x     = (const float*)d_in[0];
    const float* Win   = (const float*)d_in[1];
    const float* Wres  = (const float*)d_in[2];
    const float* Wih   = (const float*)d_in[3];
    const float* Whh   = (const float*)d_in[4];
    const float* bih   = (const float*)d_in[5];
    const float* bhh   = (const float*)d_in[6];
    const float* projW = (const float*)d_in[7];
    const float* projb = (const float*)d_in[8];
    const float* gateW = (const float*)d_in[9];
    const float* gateb = (const float*)d_in[10];
    const float* hW1   = (const float*)d_in[11];
    const float* hb1   = (const float*)d_in[12];
    const float* hW2   = (const float*)d_in[13];
    const float* hb2   = (const float*)d_in[14];
    float* out = (float*)d_out;

    void *pE, *pProj, *pCat, *pComb, *pHid, *pGate;
    cudaGetSymbolAddress(&pE,    g_hE);
    cudaGetSymbolAddress(&pProj, g_proj);
    cudaGetSymbolAddress(&pCat,  g_cat);
    cudaGetSymbolAddress(&pComb, g_comb);
    cudaGetSymbolAddress(&pGate, g_gate);
    cudaGetSymbolAddress(&pHid,  g_hid);

    cudaFuncSetAttribute(k_all, cudaFuncAttributeMaxDynamicSharedMemorySize, SMEM_BYTES);

    k_prepWE<<<(Rr*KE)/256, 256>>>(Wres, Win);
    k_prepWG<<<(MG*KG)/256, 256>>>(Whh, Wih);
    k_prepXI<<<(Tt*Ii*Bb)/256, 256>>>(x);
    k_all<<<NBLK, NTHR, SMEM_BYTES>>>(bih, bhh);
    k_tr<<<512, 256>>>();
    k_gemm<<<32, 256>>>((const float*)pE,   projW, projb, (float*)pProj, Rr,   Hh, 0);
    k_cat    <<<256, 256>>>();
    k_gemm<<<32, 256>>>((const float*)pCat, gateW, gateb, (float*)pGate, 2*Hh, Hh, 1);
    k_combine<<<128, 256>>>();
    k_gemm<<<32, 256>>>((const float*)pComb, hW1,  hb1,   (float*)pHid,  Hh,   Hh, 2);
    k_gemm<<<8,  256>>>((const float*)pHid,  hW2,  hb2,   out,           Hh,   Oo, 0);
}

// round 13
// speedup vs baseline: 10.8387x; 1.2295x over previous
#include <cuda_runtime.h>
#include <cuda_fp16.h>
#include <math.h>

#define Bb 64
#define Tt 512
#define Ii 128
#define Rr 2048
#define Hh 512
#define Oo 128
#define KE 2176
#define KG 640
#define MG 1536
#define NBLK 140
#define NTHR 256
#define SUB_ELEMS 5376            // halfs per 16-k sub-chunk: W 3072 + Bhi 1152 + Blo 1152
#define SUB_BYTES 10752
#define STG_BYTES (2*SUB_BYTES)   // 21504 (k=32 stage)
#define STG_ELEMS (2*SUB_ELEMS)
#define SMEM_BYTES (4*STG_BYTES)  // 86016

typedef __half hf;

// ---------------- device scratch ----------------
__device__ hf WEH[Rr*KE];                  // ESN weights^T fp16 [c][k]
__device__ hf WGH[MG*KG];                  // GRU weights^T fp16 [m][k]
__device__ hf Xh[Tt*Ii*Bb], Xl[Tt*Ii*Bb];  // x transposed hi/lo [t][i][b]
__device__ hf HEh[Rr*Bb], HEl[Rr*Bb];      // ESN state fp16 hi/lo [k][b]
__device__ hf HGh[Hh*Bb], HGl[Hh*Bb];      // GRU state fp16 hi/lo [j][b]
__device__ float hET[Rr*Bb], hGT[Hh*Bb];   // fp32 states (transposed)
__device__ float accE[7][Rr*Bb];           // ESN K-split partials
__device__ float accRZ[2][1024*Bb];        // GRU r,z rows, K-split
__device__ float accNH[2][Hh*Bb];          // GRU n-gate h-part, K-split
__device__ float accNX[Hh*Bb];             // GRU n-gate x-part
__device__ unsigned g_ctr;
__device__ float g_hE[Bb*Rr], g_hG[Bb*Hh];
__device__ float g_proj[Bb*Hh], g_cat[Bb*2*Hh], g_gate[Bb*Hh], g_comb[Bb*Hh], g_hid[Bb*Hh];

__device__ __forceinline__ float sigm(float x){ return 1.0f/(1.0f+expf(-x)); }
__device__ __forceinline__ float fsig(float x){ return __fdividef(1.0f, 1.0f + __expf(-x)); }
__device__ __forceinline__ float ftanh(float x){
    float e = __expf(2.0f*x);
    return 1.0f - __fdividef(2.0f, e + 1.0f);
}
__device__ __forceinline__ void hsplit(float v, hf* ph, hf* pl){
    hf h = __float2half_rn(v); *ph = h; *pl = __float2half_rn(v - __half2float(h));
}
__device__ __forceinline__ unsigned hp2(hf a, hf b){
    return (unsigned)__half_as_ushort(a) | ((unsigned)__half_as_ushort(b) << 16);
}
__device__ __forceinline__ void hpack4(float v0,float v1,float v2,float v3, hf* dh, hf* dl){
    hf h0=__float2half_rn(v0), h1=__float2half_rn(v1), h2=__float2half_rn(v2), h3=__float2half_rn(v3);
    hf l0=__float2half_rn(v0-__half2float(h0));
    hf l1=__float2half_rn(v1-__half2float(h1));
    hf l2=__float2half_rn(v2-__half2float(h2));
    hf l3=__float2half_rn(v3-__half2float(h3));
    *(uint2*)dh = make_uint2(hp2(h0,h1), hp2(h2,h3));
    *(uint2*)dl = make_uint2(hp2(l0,l1), hp2(l2,l3));
}
__device__ __forceinline__ void ldsm4(unsigned* r, const hf* p){
    unsigned a = (unsigned)__cvta_generic_to_shared(p);
    asm volatile("ldmatrix.sync.aligned.m8n8.x4.shared.b16 {%0,%1,%2,%3},[%4];"
        : "=r"(r[0]),"=r"(r[1]),"=r"(r[2]),"=r"(r[3]) : "r"(a));
}
__device__ __forceinline__ void ldsm4t(unsigned* r, const hf* p){
    unsigned a = (unsigned)__cvta_generic_to_shared(p);
    asm volatile("ldmatrix.sync.aligned.m8n8.x4.trans.shared.b16 {%0,%1,%2,%3},[%4];"
        : "=r"(r[0]),"=r"(r[1]),"=r"(r[2]),"=r"(r[3]) : "r"(a));
}
__device__ __forceinline__ void mma_hf(float* d, const unsigned* a, const unsigned* b){
    asm volatile("mma.sync.aligned.m16n8k16.row.col.f32.f16.f16.f32 "
        "{%0,%1,%2,%3},{%4,%5,%6,%7},{%8,%9},{%0,%1,%2,%3};"
        : "+f"(d[0]),"+f"(d[1]),"+f"(d[2]),"+f"(d[3])
        : "r"(a[0]),"r"(a[1]),"r"(a[2]),"r"(a[3]),"r"(b[0]),"r"(b[1]));
}
__device__ __forceinline__ void cp16(unsigned dst, const void* src){
    asm volatile("cp.async.cg.shared.global [%0],[%1],16;" :: "r"(dst),"l"(src));
}

// ---------------- prep ----------------
__global__ void k_prepWE(const float* __restrict__ Wres, const float* __restrict__ Win){
    int idx = blockIdx.x*blockDim.x + threadIdx.x;        // c*KE + k
    int c = idx/KE, k = idx - c*KE;
    float w = (k < Rr) ? Wres[k*Rr + c] : Win[(k-Rr)*Rr + c];
    WEH[idx] = __float2half_rn(w);
}
__global__ void k_prepWG(const float* __restrict__ Whh, const float* __restrict__ Wih){
    int idx = blockIdx.x*blockDim.x + threadIdx.x;        // m*KG + k
    int m = idx/KG, k = idx - m*KG;
    float w = (k < Hh) ? Whh[m*Hh + k] : Wih[m*Ii + (k-Hh)];
    WGH[idx] = __float2half_rn(w);
}
// merged x-transpose + state init
__global__ void k_prepXI(const float* __restrict__ x){
    int idx = blockIdx.x*blockDim.x + threadIdx.x;        // t*8192 + i*64 + b
    int t = idx >> 13, r = idx & 8191, i = r >> 6, b = r & 63;
    hsplit(x[b*(Tt*Ii) + t*Ii + i], &Xh[idx], &Xl[idx]);
    hf z = __float2half_rn(0.0f);
    if(idx == 0) g_ctr = 0u;
    if(idx < Rr*Bb){ hET[idx]=0.0f; HEh[idx]=z; HEl[idx]=z; }
    if(idx < Hh*Bb){ hGT[idx]=0.0f; HGh[idx]=z; HGl[idx]=z; }
}

__device__ __forceinline__ void gbar(unsigned target){
    __threadfence();
    __syncthreads();
    if(threadIdx.x == 0){
        atomicAdd(&g_ctr, 1u);
        volatile unsigned* p = &g_ctr;
        while(*p < target) __nanosleep(32);
    }
    __syncthreads();
    __threadfence();
}

// ---------------- persistent all-timesteps kernel ----------------
// 140 blocks x 256 thr (8 warps, each owns an m16 slice).
// fp16 2-product: D = W_fp16 x (h_hi + h_lo). Per sub: 1 ldsm4 + 8 ldsm4t + 16 MMA.
// Blocks: [0,112)  ESN: m-tile bx/7, K-split bx%7 (6x320 + 1x256) -> 10/8 stages
//         [112,128) GRU r,z: K-split of 640 -> 10 stages
//         [128,136) GRU n h-part: 2 splits of 512 -> 8 stages
//         [136,140) GRU n x-part: K=[512,640) -> 4 stages
__global__ void __launch_bounds__(NTHR) k_all(
    const float* __restrict__ bih, const float* __restrict__ bhh)
{
    extern __shared__ __align__(16) hf sm[];
    const int tid = threadIdx.x, lane = tid & 31, wid = tid >> 5, bx = blockIdx.x;
    const unsigned sb = (unsigned)__cvta_generic_to_shared(sm);

    // ---- role setup ----
    const hf *Wp, *Bh, *Bl; float* acc; int Kst, kbase, nch, kth;
    if(bx < 112){
        int m0 = (bx/7)*128, ks = bx%7;
        kbase = ks*320; nch = (ks < 6) ? 10 : 8; kth = Rr; Kst = KE;
        Wp = WEH + (size_t)m0*KE;
        Bh = HEh; Bl = HEl; acc = accE[ks] + m0*Bb;
    } else if(bx < 128){
        int g = bx-112, m0 = (g>>1)*128, ks = g&1;
        kbase = ks*320; nch = 10; kth = Hh; Kst = KG;
        Wp = WGH + (size_t)m0*KG;
        Bh = HGh; Bl = HGl; acc = accRZ[ks] + m0*Bb;
    } else if(bx < 136){
        int g = bx-128, mt = g>>1, ks = g&1;
        kbase = ks*256; nch = 8; kth = Hh; Kst = KG;
        Wp = WGH + (size_t)(1024 + mt*128)*KG;
        Bh = HGh; Bl = HGl; acc = accNH[ks] + mt*128*Bb;
    } else {
        int mt = bx-136;
        kbase = 512; nch = 4; kth = Hh; Kst = KG;
        Wp = WGH + (size_t)(1024 + mt*128)*KG;
        Bh = HGh; Bl = HGl; acc = accNX + mt*128*Bb;
    }
    // loader mapping (256 threads): W row = tid>>1 (32B/row = 2x16B), half = tid&1
    const int wrow = tid >> 1, wpart = tid & 1;
    const unsigned wd = sb + (unsigned)(wrow*48 + wpart*16);
    const hf* wsrc = Wp + (size_t)wrow*Kst + wpart*8;
    // B: tid<128 loads hi, tid>=128 loads lo
    const int btid = tid & 127;
    const int krow = btid >> 3, boff = (btid & 7) * 8;
    const unsigned bd = sb + 6144u + (unsigned)(krow*144 + (btid&7)*16) + ((tid < 128) ? 0u : 2304u);
    const hf* SBst = (tid < 128) ? Bh : Bl;
    const int mw = wid*16, ar = lane & 15, ac = (lane>>4)*8;
    const int r4 = lane>>2, c2 = 2*(lane&3);
    const int gbase = bx*NTHR + tid;
    const int NT = NBLK*NTHR;

    for(int t = 0; t < Tt; t++){
        const hf* Xt = ((tid < 128) ? Xh : Xl) + (size_t)t*Ii*Bb;

        auto issue = [&](int c){
            unsigned st = (unsigned)(c & 3) * STG_BYTES;
            int k0 = kbase + c*32;
            #pragma unroll
            for(int sub = 0; sub < 2; ++sub){
                unsigned so = st + sub*SUB_BYTES;
                int ks16 = k0 + sub*16;
                cp16(wd + so, wsrc + ks16);
                int kr = ks16 + krow;
                const hf* q = (kr < kth) ? SBst + kr*Bb + boff : Xt + (kr-kth)*Bb + boff;
                cp16(bd + so, q);
            }
            asm volatile("cp.async.commit_group;");
        };

        float d[8][4];
        #pragma unroll
        for(int j=0;j<8;j++)
            #pragma unroll
            for(int q=0;q<4;q++) d[j][q] = 0.0f;

        issue(0); issue(1); issue(2);

        for(int c = 0; c < nch; c++){
            if(c < nch-2)       asm volatile("cp.async.wait_group 2;");
            else if(c == nch-2) asm volatile("cp.async.wait_group 1;");
            else                asm volatile("cp.async.wait_group 0;");
            __syncthreads();
            if(c + 3 < nch) issue(c + 3);

            #pragma unroll
            for(int sub = 0; sub < 2; ++sub){
                const hf* stg = sm + (size_t)(c & 3) * STG_ELEMS + sub*SUB_ELEMS;
                const hf* sw  = stg;           // W: 128 rows x 24 stride
                const hf* sbh = stg + 3072;    // B hi: 16k x 72 stride
                const hf* sbl = stg + 4224;    // B lo

                unsigned A[4], Bf[2][4][4];
                ldsm4(A, sw + (mw + ar)*24 + ac);
                #pragma unroll
                for(int np=0; np<4; np++){
                    ldsm4t(Bf[0][np], sbh + ar*72 + np*16 + ac);
                    ldsm4t(Bf[1][np], sbl + ar*72 + np*16 + ac);
                }
                #pragma unroll
                for(int nt=0; nt<8; nt++){
                    mma_hf(d[nt], A, &Bf[0][nt>>1][(nt&1)*2]);   // W * h_hi
                    mma_hf(d[nt], A, &Bf[1][nt>>1][(nt&1)*2]);   // W * h_lo
                }
            }
        }
        #pragma unroll
        for(int nt=0; nt<8; nt++){
            int m = mw + r4, b = nt*8 + c2;
            *(float2*)&acc[m*Bb + b]     = make_float2(d[nt][0], d[nt][1]);
            *(float2*)&acc[(m+8)*Bb + b] = make_float2(d[nt][2], d[nt][3]);
        }

        gbar((unsigned)NBLK * (unsigned)(2*t + 1));

        // ---------- epilogue ----------
        for(int g = gbase; g < (Rr*Bb)/4; g += NT){
            int o = g*4;
            float4 a0 = *(const float4*)&accE[0][o];
            float4 a1 = *(const float4*)&accE[1][o];
            float4 a2 = *(const float4*)&accE[2][o];
            float4 a3 = *(const float4*)&accE[3][o];
            float4 a4 = *(const float4*)&accE[4][o];
            float4 a5 = *(const float4*)&accE[5][o];
            float4 a6 = *(const float4*)&accE[6][o];
            float4 hp = *(const float4*)&hET[o];
            float n0 = 0.7f*hp.x + 0.3f*ftanh(a0.x+a1.x+a2.x+a3.x+a4.x+a5.x+a6.x);
            float n1 = 0.7f*hp.y + 0.3f*ftanh(a0.y+a1.y+a2.y+a3.y+a4.y+a5.y+a6.y);
            float n2 = 0.7f*hp.z + 0.3f*ftanh(a0.z+a1.z+a2.z+a3.z+a4.z+a5.z+a6.z);
            float n3 = 0.7f*hp.w + 0.3f*ftanh(a0.w+a1.w+a2.w+a3.w+a4.w+a5.w+a6.w);
            *(float4*)&hET[o] = make_float4(n0,n1,n2,n3);
            hpack4(n0,n1,n2,n3, &HEh[o], &HEl[o]);
        }
        for(int g = gbase; g < (Hh*Bb)/4; g += NT){
            int j = g >> 4, b4 = (g & 15)*4, ix = j*64 + b4;
            float4 r0 = *(const float4*)&accRZ[0][ix];
            float4 r1 = *(const float4*)&accRZ[1][ix];
            float4 z0 = *(const float4*)&accRZ[0][(j+Hh)*64 + b4];
            float4 z1 = *(const float4*)&accRZ[1][(j+Hh)*64 + b4];
            float4 h0 = *(const float4*)&accNH[0][ix];
            float4 h1 = *(const float4*)&accNH[1][ix];
            float4 xn = *(const float4*)&accNX[ix];
            float4 hp = *(const float4*)&hGT[ix];
            float br  = bih[j] + bhh[j];
            float bz2 = bih[j+Hh] + bhh[j+Hh];
            float bxn = bih[j+2*Hh], bhn = bhh[j+2*Hh];
            float n[4];
            #pragma unroll
            for(int i=0;i<4;i++){
                float rv = (&r0.x)[i] + (&r1.x)[i];
                float zv = (&z0.x)[i] + (&z1.x)[i];
                float hnv = (&h0.x)[i] + (&h1.x)[i];
                float xnv = (&xn.x)[i];
                float hpv = (&hp.x)[i];
                float rg = fsig(rv + br);
                float zg = fsig(zv + bz2);
                float nn = ftanh(xnv + bxn + rg*(hnv + bhn));
                n[i] = (1.0f - zg)*nn + zg*hpv;
            }
            *(float4*)&hGT[ix] = make_float4(n[0],n[1],n[2],n[3]);
            hpack4(n[0],n[1],n[2],n[3], &HGh[ix], &HGl[ix]);
        }

        gbar((unsigned)NBLK * (unsigned)(2*t + 2));
    }
}

// ---------------- final transpose + head ----------------
__global__ void k_tr(){
    int idx = blockIdx.x*blockDim.x + threadIdx.x;
    if(idx < Bb*Rr){ int b = idx/Rr, c = idx - b*Rr; g_hE[idx] = hET[c*Bb + b]; }
    if(idx < Bb*Hh){ int b = idx/Hh, j = idx - b*Hh; g_hG[idx] = hGT[j*Bb + b]; }
}
__global__ __launch_bounds__(256) void k_gemm(
    const float* __restrict__ A, const float* __restrict__ W,
    const float* __restrict__ bias, float* __restrict__ C, int K, int J, int act)
{
    __shared__ __align__(16) float sA[32*68];
    __shared__ float sW2[32*16];
    const int tid = threadIdx.x, tx = tid & 15, ty = tid >> 4, jb = blockIdx.x*16;
    float acc[4] = {0.f,0.f,0.f,0.f};
    for(int ch=0; ch<(K>>5); ch++){
        const int k0 = ch*32;
        #pragma unroll
        for(int r=0;r<2;r++){
            int idx = tid + r*256, b = idx>>3, kq = idx&7;
            float4 v = *(const float4*)(A + b*K + k0 + 4*kq);
            sA[(4*kq+0)*68+b]=v.x; sA[(4*kq+1)*68+b]=v.y;
            sA[(4*kq+2)*68+b]=v.z; sA[(4*kq+3)*68+b]=v.w;
        }
        #pragma unroll
        for(int r=0;r<2;r++){
            int idx = tid + r*256, kr = idx&31, c = idx>>5;
            sW2[kr*16+c] = W[(jb+c)*K + k0 + kr];
        }
        __syncthreads();
        #pragma unroll
        for(int kk=0;kk<32;kk++){
            float w = sW2[kk*16+tx];
            float4 a = *(const float4*)&sA[kk*68 + 4*ty];
            acc[0]+=a.x*w; acc[1]+=a.y*w; acc[2]+=a.z*w; acc[3]+=a.w*w;
        }
        __syncthreads();
    }
    const int j = jb + tx; const float bv = bias[j];
    #pragma unroll
    for(int i=0;i<4;i++){
        float v = acc[i] + bv;
        if(act==1) v = sigm(v); else if(act==2) v = fmaxf(v, 0.0f);
        C[(4*ty+i)*J + j] = v;
    }
}
__global__ void k_cat(){
    int idx = blockIdx.x*blockDim.x + threadIdx.x;
    if(idx < Bb*2*Hh){
        int b = idx>>10, k = idx & 1023;
        g_cat[idx] = (k < Hh) ? g_proj[b*Hh + k] : g_hG[b*Hh + (k-Hh)];
    }
}
__global__ void k_combine(){
    int idx = blockIdx.x*blockDim.x + threadIdx.x;
    if(idx < Bb*Hh){
        float g = g_gate[idx];
        g_comb[idx] = g*g_proj[idx] + (1.0f - g)*g_hG[idx];
    }
}

extern "C" void kernel_launch(void* const* d_in, const int* in_sizes, int n_in,
                              void* d_out, int out_size)
{
    const float* x     = (const float*)d_in[0];
    const float* Win   = (const float*)d_in[1];
    const float* Wres  = (const float*)d_in[2];
    const float* Wih   = (const float*)d_in[3];
    const float* Whh   = (const float*)d_in[4];
    const float* bih   = (const float*)d_in[5];
    const float* bhh   = (const float*)d_in[6];
    const float* projW = (const float*)d_in[7];
    const float* projb = (const float*)d_in[8];
    const float* gateW = (const float*)d_in[9];
    const float* gateb = (const float*)d_in[10];
    const float* hW1   = (const float*)d_in[11];
    const float* hb1   = (const float*)d_in[12];
    const float* hW2   = (const float*)d_in[13];
    const float* hb2   = (const float*)d_in[14];
    float* out = (float*)d_out;

    void *pE, *pProj, *pCat, *pComb, *pHid, *pGate;
    cudaGetSymbolAddress(&pE,    g_hE);
    cudaGetSymbolAddress(&pProj, g_proj);
    cudaGetSymbolAddress(&pCat,  g_cat);
    cudaGetSymbolAddress(&pComb, g_comb);
    cudaGetSymbolAddress(&pGate, g_gate);
    cudaGetSymbolAddress(&pHid,  g_hid);

    cudaFuncSetAttribute(k_all, cudaFuncAttributeMaxDynamicSharedMemorySize, SMEM_BYTES);

    k_prepWE<<<(Rr*KE)/256, 256>>>(Wres, Win);
    k_prepWG<<<(MG*KG)/256, 256>>>(Whh, Wih);
    k_prepXI<<<(Tt*Ii*Bb)/256, 256>>>(x);
    k_all<<<NBLK, NTHR, SMEM_BYTES>>>(bih, bhh);
    k_tr<<<512, 256>>>();
    k_gemm<<<32, 256>>>((const float*)pE,   projW, projb, (float*)pProj, Rr,   Hh, 0);
    k_cat    <<<256, 256>>>();
    k_gemm<<<32, 256>>>((const float*)pCat, gateW, gateb, (float*)pGate, 2*Hh, Hh, 1);
    k_combine<<<128, 256>>>();
    k_gemm<<<32, 256>>>((const float*)pComb, hW1,  hb1,   (float*)pHid,  Hh,   Hh, 2);
    k_gemm<<<8,  256>>>((const float*)pHid,  hW2,  hb2,   out,           Hh,   Oo, 0);
}

// round 14
// speedup vs baseline: 11.2101x; 1.0343x over previous
#include <cuda_runtime.h>
#include <cuda_fp16.h>
#include <math.h>

#define Bb 64
#define Tt 512
#define Ii 128
#define Rr 2048
#define Hh 512
#define Oo 128
#define KE 2176
#define KG 640
#define MG 1536
#define NBLK 140
#define NTHR 512
#define BCH_BYTES 9216                  // B ring: one k=32 chunk (2 subs x (hi+lo) x 2304B)
#define BRING_BYTES (4*BCH_BYTES)       // 36864
#define WSUB_HALFS 3072                 // W per 16-k sub: 128 rows x 24 halfs
#define SMEM_BYTES (BRING_BYTES + 20*6144)  // 159744

typedef __half hf;

// ---------------- device scratch ----------------
__device__ hf WEH[Rr*KE];                  // ESN weights^T fp16 [c][k]
__device__ hf WGH[MG*KG];                  // GRU weights^T fp16 [m][k]
__device__ hf Xh[Tt*Ii*Bb], Xl[Tt*Ii*Bb];  // x transposed hi/lo [t][i][b]
__device__ hf HEh[Rr*Bb], HEl[Rr*Bb];      // ESN state fp16 hi/lo [k][b]
__device__ hf HGh[Hh*Bb], HGl[Hh*Bb];      // GRU state fp16 hi/lo [j][b]
__device__ float hET[Rr*Bb], hGT[Hh*Bb];   // fp32 states (transposed)
__device__ float accE[7][Rr*Bb];           // ESN K-split partials
__device__ float accRZ[2][1024*Bb];        // GRU r,z rows, K-split
__device__ float accNH[2][Hh*Bb];          // GRU n-gate h-part, K-split
__device__ float accNX[Hh*Bb];             // GRU n-gate x-part
__device__ unsigned g_ctr;
__device__ float g_hE[Bb*Rr], g_hG[Bb*Hh];
__device__ float g_proj[Bb*Hh], g_cat[Bb*2*Hh], g_gate[Bb*Hh], g_comb[Bb*Hh], g_hid[Bb*Hh];

__device__ __forceinline__ float sigm(float x){ return 1.0f/(1.0f+expf(-x)); }
__device__ __forceinline__ float fsig(float x){ return __fdividef(1.0f, 1.0f + __expf(-x)); }
__device__ __forceinline__ float ftanh(float x){
    float e = __expf(2.0f*x);
    return 1.0f - __fdividef(2.0f, e + 1.0f);
}
__device__ __forceinline__ void hsplit(float v, hf* ph, hf* pl){
    hf h = __float2half_rn(v); *ph = h; *pl = __float2half_rn(v - __half2float(h));
}
__device__ __forceinline__ unsigned hp2(hf a, hf b){
    return (unsigned)__half_as_ushort(a) | ((unsigned)__half_as_ushort(b) << 16);
}
__device__ __forceinline__ void hpack4(float v0,float v1,float v2,float v3, hf* dh, hf* dl){
    hf h0=__float2half_rn(v0), h1=__float2half_rn(v1), h2=__float2half_rn(v2), h3=__float2half_rn(v3);
    hf l0=__float2half_rn(v0-__half2float(h0));
    hf l1=__float2half_rn(v1-__half2float(h1));
    hf l2=__float2half_rn(v2-__half2float(h2));
    hf l3=__float2half_rn(v3-__half2float(h3));
    *(uint2*)dh = make_uint2(hp2(h0,h1), hp2(h2,h3));
    *(uint2*)dl = make_uint2(hp2(l0,l1), hp2(l2,l3));
}
__device__ __forceinline__ void ldsm4(unsigned* r, const hf* p){
    unsigned a = (unsigned)__cvta_generic_to_shared(p);
    asm volatile("ldmatrix.sync.aligned.m8n8.x4.shared.b16 {%0,%1,%2,%3},[%4];"
        : "=r"(r[0]),"=r"(r[1]),"=r"(r[2]),"=r"(r[3]) : "r"(a));
}
__device__ __forceinline__ void ldsm4t(unsigned* r, const hf* p){
    unsigned a = (unsigned)__cvta_generic_to_shared(p);
    asm volatile("ldmatrix.sync.aligned.m8n8.x4.trans.shared.b16 {%0,%1,%2,%3},[%4];"
        : "=r"(r[0]),"=r"(r[1]),"=r"(r[2]),"=r"(r[3]) : "r"(a));
}
__device__ __forceinline__ void mma_hf(float* d, const unsigned* a, const unsigned* b){
    asm volatile("mma.sync.aligned.m16n8k16.row.col.f32.f16.f16.f32 "
        "{%0,%1,%2,%3},{%4,%5,%6,%7},{%8,%9},{%0,%1,%2,%3};"
        : "+f"(d[0]),"+f"(d[1]),"+f"(d[2]),"+f"(d[3])
        : "r"(a[0]),"r"(a[1]),"r"(a[2]),"r"(a[3]),"r"(b[0]),"r"(b[1]));
}
__device__ __forceinline__ void cp16(unsigned dst, const void* src){
    asm volatile("cp.async.cg.shared.global [%0],[%1],16;" :: "r"(dst),"l"(src));
}

// ---------------- prep ----------------
__global__ void k_prepWE(const float* __restrict__ Wres, const float* __restrict__ Win){
    int idx = blockIdx.x*blockDim.x + threadIdx.x;        // c*KE + k
    int c = idx/KE, k = idx - c*KE;
    float w = (k < Rr) ? Wres[k*Rr + c] : Win[(k-Rr)*Rr + c];
    WEH[idx] = __float2half_rn(w);
}
__global__ void k_prepWG(const float* __restrict__ Whh, const float* __restrict__ Wih){
    int idx = blockIdx.x*blockDim.x + threadIdx.x;        // m*KG + k
    int m = idx/KG, k = idx - m*KG;
    float w = (k < Hh) ? Whh[m*Hh + k] : Wih[m*Ii + (k-Hh)];
    WGH[idx] = __float2half_rn(w);
}
__global__ void k_prepXI(const float* __restrict__ x){
    int idx = blockIdx.x*blockDim.x + threadIdx.x;        // t*8192 + i*64 + b
    int t = idx >> 13, r = idx & 8191, i = r >> 6, b = r & 63;
    hsplit(x[b*(Tt*Ii) + t*Ii + i], &Xh[idx], &Xl[idx]);
    hf z = __float2half_rn(0.0f);
    if(idx == 0) g_ctr = 0u;
    if(idx < Rr*Bb){ hET[idx]=0.0f; HEh[idx]=z; HEl[idx]=z; }
    if(idx < Hh*Bb){ hGT[idx]=0.0f; HGh[idx]=z; HGl[idx]=z; }
}

__device__ __forceinline__ void gbar(unsigned target){
    __threadfence();
    __syncthreads();
    if(threadIdx.x == 0){
        atomicAdd(&g_ctr, 1u);
        volatile unsigned* p = &g_ctr;
        while(*p < target) __nanosleep(32);
    }
    __syncthreads();
    __threadfence();
}

// ---------------- persistent all-timesteps kernel ----------------
// 140 blocks x 512 thr (16 warps: m16 x n32 tiles -> 4 warps/SMSP).
// W slice loaded ONCE into persistent smem; per-step stream = state only
// (4-slot B ring, 1 cp16/thread/chunk). fp16 2-product arithmetic.
// Blocks: [0,112)  ESN: m-tile bx/7, K-split bx%7 (6x320 + 1x256) -> 10/8 chunks
//         [112,128) GRU r,z: K-split of 640 -> 10 chunks
//         [128,136) GRU n h-part: 2 splits of 512 -> 8 chunks
//         [136,140) GRU n x-part: K=[512,640) -> 4 chunks
__global__ void __launch_bounds__(NTHR) k_all(
    const float* __restrict__ bih, const float* __restrict__ bhh)
{
    extern __shared__ __align__(16) hf sm[];
    const int tid = threadIdx.x, lane = tid & 31, wid = tid >> 5, bx = blockIdx.x;
    const unsigned sb = (unsigned)__cvta_generic_to_shared(sm);

    // ---- role setup ----
    const hf *Wp, *Bh, *Bl; float* acc; int Kst, kbase, nch, kth;
    if(bx < 112){
        int m0 = (bx/7)*128, ks = bx%7;
        kbase = ks*320; nch = (ks < 6) ? 10 : 8; kth = Rr; Kst = KE;
        Wp = WEH + (size_t)m0*KE;
        Bh = HEh; Bl = HEl; acc = accE[ks] + m0*Bb;
    } else if(bx < 128){
        int g = bx-112, m0 = (g>>1)*128, ks = g&1;
        kbase = ks*320; nch = 10; kth = Hh; Kst = KG;
        Wp = WGH + (size_t)m0*KG;
        Bh = HGh; Bl = HGl; acc = accRZ[ks] + m0*Bb;
    } else if(bx < 136){
        int g = bx-128, mt = g>>1, ks = g&1;
        kbase = ks*256; nch = 8; kth = Hh; Kst = KG;
        Wp = WGH + (size_t)(1024 + mt*128)*KG;
        Bh = HGh; Bl = HGl; acc = accNH[ks] + mt*128*Bb;
    } else {
        int mt = bx-136;
        kbase = 512; nch = 4; kth = Hh; Kst = KG;
        Wp = WGH + (size_t)(1024 + mt*128)*KG;
        Bh = HGh; Bl = HGl; acc = accNX + mt*128*Bb;
    }

    // ---- one-time W prologue: nch*2 subs, each 128 rows x 24-half stride ----
    {
        const int nsubs = nch*2;
        int rp = tid & 255, row = rp >> 1, part = rp & 1;
        for(int s2 = 0; s2 < nsubs; s2 += 2){
            int sub = s2 + (tid >> 8);
            if(sub < nsubs)
                cp16(sb + (unsigned)BRING_BYTES + (unsigned)(sub*6144 + row*48 + part*16),
                     Wp + (size_t)row*Kst + kbase + sub*16 + part*8);
        }
        asm volatile("cp.async.commit_group;");
        asm volatile("cp.async.wait_group 0;");
        __syncthreads();
    }

    // ---- B loader mapping: 512 threads -> one k=32 chunk (2 subs x hi/lo x 128) ----
    const int bsub = (tid >> 8) & 1, bhalf = (tid >> 7) & 1, btid = tid & 127;
    const int krow = btid >> 3, boff = (btid & 7) * 8;
    const unsigned bd = sb + (unsigned)(bsub*4608 + bhalf*2304 + krow*144 + (btid&7)*16);
    const hf* SBst = bhalf ? Bl : Bh;
    const hf* Xbase = bhalf ? Xl : Xh;

    // ---- warp tiling: warp = (m16 slice, n32 half) ----
    const int mw = (wid >> 1) * 16, nh = wid & 1;
    const int ar = lane & 15, ac = (lane>>4)*8;
    const int r4 = lane>>2, c2 = 2*(lane&3);
    const int gbase = bx*NTHR + tid;
    const int NT = NBLK*NTHR;

    for(int t = 0; t < Tt; t++){
        const hf* Xt = Xbase + (size_t)t*Ii*Bb;

        auto issue = [&](int c){
            int kr = kbase + c*32 + bsub*16 + krow;
            const hf* q = (kr < kth) ? SBst + kr*Bb + boff : Xt + (kr-kth)*Bb + boff;
            cp16(bd + (unsigned)(c & 3)*BCH_BYTES, q);
            asm volatile("cp.async.commit_group;");
        };

        float d[4][4];
        #pragma unroll
        for(int j=0;j<4;j++)
            #pragma unroll
            for(int q=0;q<4;q++) d[j][q] = 0.0f;

        issue(0); issue(1); issue(2);

        for(int c = 0; c < nch; c++){
            if(c < nch-2)       asm volatile("cp.async.wait_group 2;");
            else if(c == nch-2) asm volatile("cp.async.wait_group 1;");
            else                asm volatile("cp.async.wait_group 0;");
            __syncthreads();
            if(c + 3 < nch) issue(c + 3);

            #pragma unroll
            for(int sub = 0; sub < 2; ++sub){
                const hf* sw  = sm + (BRING_BYTES/2) + (size_t)(c*2 + sub)*WSUB_HALFS;
                const hf* sbh = sm + (size_t)(c & 3)*(BCH_BYTES/2) + sub*2304;
                const hf* sbl = sbh + 1152;

                unsigned A[4], Bf[2][2][4];
                ldsm4(A, sw + (mw + ar)*24 + ac);
                #pragma unroll
                for(int i=0; i<2; i++){
                    ldsm4t(Bf[0][i], sbh + ar*72 + (2*nh + i)*16 + ac);
                    ldsm4t(Bf[1][i], sbl + ar*72 + (2*nh + i)*16 + ac);
                }
                #pragma unroll
                for(int nt=0; nt<4; nt++){
                    mma_hf(d[nt], A, &Bf[0][nt>>1][(nt&1)*2]);   // W * h_hi
                    mma_hf(d[nt], A, &Bf[1][nt>>1][(nt&1)*2]);   // W * h_lo
                }
            }
        }
        #pragma unroll
        for(int nt=0; nt<4; nt++){
            int m = mw + r4, b = nh*32 + nt*8 + c2;
            *(float2*)&acc[m*Bb + b]     = make_float2(d[nt][0], d[nt][1]);
            *(float2*)&acc[(m+8)*Bb + b] = make_float2(d[nt][2], d[nt][3]);
        }

        gbar((unsigned)NBLK * (unsigned)(2*t + 1));

        // ---------- epilogue ----------
        for(int g = gbase; g < (Rr*Bb)/4; g += NT){
            int o = g*4;
            float4 a0 = *(const float4*)&accE[0][o];
            float4 a1 = *(const float4*)&accE[1][o];
            float4 a2 = *(const float4*)&accE[2][o];
            float4 a3 = *(const float4*)&accE[3][o];
            float4 a4 = *(const float4*)&accE[4][o];
            float4 a5 = *(const float4*)&accE[5][o];
            float4 a6 = *(const float4*)&accE[6][o];
            float4 hp = *(const float4*)&hET[o];
            float n0 = 0.7f*hp.x + 0.3f*ftanh(a0.x+a1.x+a2.x+a3.x+a4.x+a5.x+a6.x);
            float n1 = 0.7f*hp.y + 0.3f*ftanh(a0.y+a1.y+a2.y+a3.y+a4.y+a5.y+a6.y);
            float n2 = 0.7f*hp.z + 0.3f*ftanh(a0.z+a1.z+a2.z+a3.z+a4.z+a5.z+a6.z);
            float n3 = 0.7f*hp.w + 0.3f*ftanh(a0.w+a1.w+a2.w+a3.w+a4.w+a5.w+a6.w);
            *(float4*)&hET[o] = make_float4(n0,n1,n2,n3);
            hpack4(n0,n1,n2,n3, &HEh[o], &HEl[o]);
        }
        for(int g = gbase; g < (Hh*Bb)/4; g += NT){
            int j = g >> 4, b4 = (g & 15)*4, ix = j*64 + b4;
            float4 r0 = *(const float4*)&accRZ[0][ix];
            float4 r1 = *(const float4*)&accRZ[1][ix];
            float4 z0 = *(const float4*)&accRZ[0][(j+Hh)*64 + b4];
            float4 z1 = *(const float4*)&accRZ[1][(j+Hh)*64 + b4];
            float4 h0 = *(const float4*)&accNH[0][ix];
            float4 h1 = *(const float4*)&accNH[1][ix];
            float4 xn = *(const float4*)&accNX[ix];
            float4 hp = *(const float4*)&hGT[ix];
            float br  = bih[j] + bhh[j];
            float bz2 = bih[j+Hh] + bhh[j+Hh];
            float bxn = bih[j+2*Hh], bhn = bhh[j+2*Hh];
            float n[4];
            #pragma unroll
            for(int i=0;i<4;i++){
                float rv = (&r0.x)[i] + (&r1.x)[i];
                float zv = (&z0.x)[i] + (&z1.x)[i];
                float hnv = (&h0.x)[i] + (&h1.x)[i];
                float xnv = (&xn.x)[i];
                float hpv = (&hp.x)[i];
                float rg = fsig(rv + br);
                float zg = fsig(zv + bz2);
                float nn = ftanh(xnv + bxn + rg*(hnv + bhn));
                n[i] = (1.0f - zg)*nn + zg*hpv;
            }
            *(float4*)&hGT[ix] = make_float4(n[0],n[1],n[2],n[3]);
            hpack4(n[0],n[1],n[2],n[3], &HGh[ix], &HGl[ix]);
        }

        gbar((unsigned)NBLK * (unsigned)(2*t + 2));
    }
}

// ---------------- final transpose + head ----------------
__global__ void k_tr(){
    int idx = blockIdx.x*blockDim.x + threadIdx.x;
    if(idx < Bb*Rr){ int b = idx/Rr, c = idx - b*Rr; g_hE[idx] = hET[c*Bb + b]; }
    if(idx < Bb*Hh){ int b = idx/Hh, j = idx - b*Hh; g_hG[idx] = hGT[j*Bb + b]; }
}
__global__ __launch_bounds__(256) void k_gemm(
    const float* __restrict__ A, const float* __restrict__ W,
    const float* __restrict__ bias, float* __restrict__ C, int K, int J, int act)
{
    __shared__ __align__(16) float sA[32*68];
    __shared__ float sW2[32*16];
    const int tid = threadIdx.x, tx = tid & 15, ty = tid >> 4, jb = blockIdx.x*16;
    float acc[4] = {0.f,0.f,0.f,0.f};
    for(int ch=0; ch<(K>>5); ch++){
        const int k0 = ch*32;
        #pragma unroll
        for(int r=0;r<2;r++){
            int idx = tid + r*256, b = idx>>3, kq = idx&7;
            float4 v = *(const float4*)(A + b*K + k0 + 4*kq);
            sA[(4*kq+0)*68+b]=v.x; sA[(4*kq+1)*68+b]=v.y;
            sA[(4*kq+2)*68+b]=v.z; sA[(4*kq+3)*68+b]=v.w;
        }
        #pragma unroll
        for(int r=0;r<2;r++){
            int idx = tid + r*256, kr = idx&31, c = idx>>5;
            sW2[kr*16+c] = W[(jb+c)*K + k0 + kr];
        }
        __syncthreads();
        #pragma unroll
        for(int kk=0;kk<32;kk++){
            float w = sW2[kk*16+tx];
            float4 a = *(const float4*)&sA[kk*68 + 4*ty];
            acc[0]+=a.x*w; acc[1]+=a.y*w; acc[2]+=a.z*w; acc[3]+=a.w*w;
        }
        __syncthreads();
    }
    const int j = jb + tx; const float bv = bias[j];
    #pragma unroll
    for(int i=0;i<4;i++){
        float v = acc[i] + bv;
        if(act==1) v = sigm(v); else if(act==2) v = fmaxf(v, 0.0f);
        C[(4*ty+i)*J + j] = v;
    }
}
__global__ void k_cat(){
    int idx = blockIdx.x*blockDim.x + threadIdx.x;
    if(idx < Bb*2*Hh){
        int b = idx>>10, k = idx & 1023;
        g_cat[idx] = (k < Hh) ? g_proj[b*Hh + k] : g_hG[b*Hh + (k-Hh)];
    }
}
__global__ void k_combine(){
    int idx = blockIdx.x*blockDim.x + threadIdx.x;
    if(idx < Bb*Hh){
        float g = g_gate[idx];
        g_comb[idx] = g*g_proj[idx] + (1.0f - g)*g_hG[idx];
    }
}

extern "C" void kernel_launch(void* const* d_in, const int* in_sizes, int n_in,
                              void* d_out, int out_size)
{
    const float* x     = (const float*)d_in[0];
    const float* Win   = (const float*)d_in[1];
    const float* Wres  = (const float*)d_in[2];
    const float* Wih   = (const float*)d_in[3];
    const float* Whh   = (const float*)d_in[4];
    const float* bih   = (const float*)d_in[5];
    const float* bhh   = (const float*)d_in[6];
    const float* projW = (const float*)d_in[7];
    const float* projb = (const float*)d_in[8];
    const float* gateW = (const float*)d_in[9];
    const float* gateb = (const float*)d_in[10];
    const float* hW1   = (const float*)d_in[11];
    const float* hb1   = (const float*)d_in[12];
    const float* hW2   = (const float*)d_in[13];
    const float* hb2   = (const float*)d_in[14];
    float* out = (float*)d_out;

    void *pE, *pProj, *pCat, *pComb, *pHid, *pGate;
    cudaGetSymbolAddress(&pE,    g_hE);
    cudaGetSymbolAddress(&pProj, g_proj);
    cudaGetSymbolAddress(&pCat,  g_cat);
    cudaGetSymbolAddress(&pComb, g_comb);
    cudaGetSymbolAddress(&pGate, g_gate);
    cudaGetSymbolAddress(&pHid,  g_hid);

    cudaFuncSetAttribute(k_all, cudaFuncAttributeMaxDynamicSharedMemorySize, SMEM_BYTES);

    k_prepWE<<<(Rr*KE)/256, 256>>>(Wres, Win);
    k_prepWG<<<(MG*KG)/256, 256>>>(Whh, Wih);
    k_prepXI<<<(Tt*Ii*Bb)/256, 256>>>(x);
    k_all<<<NBLK, NTHR, SMEM_BYTES>>>(bih, bhh);
    k_tr<<<512, 256>>>();
    k_gemm<<<32, 256>>>((const float*)pE,   projW, projb, (float*)pProj, Rr,   Hh, 0);
    k_cat    <<<256, 256>>>();
    k_gemm<<<32, 256>>>((const float*)pCat, gateW, gateb, (float*)pGate, 2*Hh, Hh, 1);
    k_combine<<<128, 256>>>();
    k_gemm<<<32, 256>>>((const float*)pComb, hW1,  hb1,   (float*)pHid,  Hh,   Hh, 2);
    k_gemm<<<8,  256>>>((const float*)pHid,  hW2,  hb2,   out,           Hh,   Oo, 0);
}

// round 15
// speedup vs baseline: 12.8502x; 1.1463x over previous
#include <cuda_runtime.h>
#include <cuda_fp16.h>
#include <math.h>

#define Bb 64
#define Tt 512
#define Ii 128
#define Rr 2048
#define Hh 512
#define Oo 128
#define KE 2176
#define KG 640
#define MG 1536
#define NBLK 140
#define NBE 112
#define NBG 28
#define NTHR 512
#define BCH_BYTES 18432                 // B ring chunk: k=64 = 4 subs x (hi+lo) x 2304B
#define BRING_BYTES (4*BCH_BYTES)       // 73728
#define WSUB_HALFS 3072                 // W per 16-k sub: 128 rows x 24 halfs
#define SMEM_BYTES (BRING_BYTES + 20*6144)  // 196608

typedef __half hf;

// ---------------- device scratch ----------------
__device__ hf WEH[Rr*KE];                  // ESN weights^T fp16 [c][k]
__device__ hf WGH[MG*KG];                  // GRU weights^T fp16 [m][k]
__device__ hf Xh[Tt*Ii*Bb], Xl[Tt*Ii*Bb];  // x transposed hi/lo [t][i][b]
__device__ hf HEh[Rr*Bb], HEl[Rr*Bb];      // ESN state fp16 hi/lo [k][b]
__device__ hf HGh[Hh*Bb], HGl[Hh*Bb];      // GRU state fp16 hi/lo [j][b]
__device__ float hET[Rr*Bb], hGT[Hh*Bb];   // fp32 states (transposed)
__device__ float accE[7][Rr*Bb];           // ESN K-split partials
__device__ float accRZ[2][1024*Bb];        // GRU r,z rows, K-split
__device__ float accNH[2][Hh*Bb];          // GRU n-gate h-part, K-split
__device__ float accNX[Hh*Bb];             // GRU n-gate x-part
__device__ unsigned g_ctrE, g_ctrG;
__device__ float g_hE[Bb*Rr], g_hG[Bb*Hh];
__device__ float g_proj[Bb*Hh], g_cat[Bb*2*Hh], g_gate[Bb*Hh], g_comb[Bb*Hh], g_hid[Bb*Hh];

__device__ __forceinline__ float sigm(float x){ return 1.0f/(1.0f+expf(-x)); }
__device__ __forceinline__ float fsig(float x){ return __fdividef(1.0f, 1.0f + __expf(-x)); }
__device__ __forceinline__ float ftanh(float x){
    float e = __expf(2.0f*x);
    return 1.0f - __fdividef(2.0f, e + 1.0f);
}
__device__ __forceinline__ void hsplit(float v, hf* ph, hf* pl){
    hf h = __float2half_rn(v); *ph = h; *pl = __float2half_rn(v - __half2float(h));
}
__device__ __forceinline__ unsigned hp2(hf a, hf b){
    return (unsigned)__half_as_ushort(a) | ((unsigned)__half_as_ushort(b) << 16);
}
__device__ __forceinline__ void hpack4(float v0,float v1,float v2,float v3, hf* dh, hf* dl){
    hf h0=__float2half_rn(v0), h1=__float2half_rn(v1), h2=__float2half_rn(v2), h3=__float2half_rn(v3);
    hf l0=__float2half_rn(v0-__half2float(h0));
    hf l1=__float2half_rn(v1-__half2float(h1));
    hf l2=__float2half_rn(v2-__half2float(h2));
    hf l3=__float2half_rn(v3-__half2float(h3));
    *(uint2*)dh = make_uint2(hp2(h0,h1), hp2(h2,h3));
    *(uint2*)dl = make_uint2(hp2(l0,l1), hp2(l2,l3));
}
__device__ __forceinline__ void ldsm4(unsigned* r, const hf* p){
    unsigned a = (unsigned)__cvta_generic_to_shared(p);
    asm volatile("ldmatrix.sync.aligned.m8n8.x4.shared.b16 {%0,%1,%2,%3},[%4];"
        : "=r"(r[0]),"=r"(r[1]),"=r"(r[2]),"=r"(r[3]) : "r"(a));
}
__device__ __forceinline__ void ldsm4t(unsigned* r, const hf* p){
    unsigned a = (unsigned)__cvta_generic_to_shared(p);
    asm volatile("ldmatrix.sync.aligned.m8n8.x4.trans.shared.b16 {%0,%1,%2,%3},[%4];"
        : "=r"(r[0]),"=r"(r[1]),"=r"(r[2]),"=r"(r[3]) : "r"(a));
}
__device__ __forceinline__ void mma_hf(float* d, const unsigned* a, const unsigned* b){
    asm volatile("mma.sync.aligned.m16n8k16.row.col.f32.f16.f16.f32 "
        "{%0,%1,%2,%3},{%4,%5,%6,%7},{%8,%9},{%0,%1,%2,%3};"
        : "+f"(d[0]),"+f"(d[1]),"+f"(d[2]),"+f"(d[3])
        : "r"(a[0]),"r"(a[1]),"r"(a[2]),"r"(a[3]),"r"(b[0]),"r"(b[1]));
}
__device__ __forceinline__ void cp16(unsigned dst, const void* src){
    asm volatile("cp.async.cg.shared.global [%0],[%1],16;" :: "r"(dst),"l"(src));
}

// ---------------- prep ----------------
__global__ void k_prepWE(const float* __restrict__ Wres, const float* __restrict__ Win){
    int idx = blockIdx.x*blockDim.x + threadIdx.x;        // c*KE + k
    int c = idx/KE, k = idx - c*KE;
    float w = (k < Rr) ? Wres[k*Rr + c] : Win[(k-Rr)*Rr + c];
    WEH[idx] = __float2half_rn(w);
}
__global__ void k_prepWG(const float* __restrict__ Whh, const float* __restrict__ Wih){
    int idx = blockIdx.x*blockDim.x + threadIdx.x;        // m*KG + k
    int m = idx/KG, k = idx - m*KG;
    float w = (k < Hh) ? Whh[m*Hh + k] : Wih[m*Ii + (k-Hh)];
    WGH[idx] = __float2half_rn(w);
}
__global__ void k_prepXI(const float* __restrict__ x){
    int idx = blockIdx.x*blockDim.x + threadIdx.x;        // t*8192 + i*64 + b
    int t = idx >> 13, r = idx & 8191, i = r >> 6, b = r & 63;
    hsplit(x[b*(Tt*Ii) + t*Ii + i], &Xh[idx], &Xl[idx]);
    hf z = __float2half_rn(0.0f);
    if(idx == 0){ g_ctrE = 0u; g_ctrG = 0u; }
    if(idx < Rr*Bb){ hET[idx]=0.0f; HEh[idx]=z; HEl[idx]=z; }
    if(idx < Hh*Bb){ hGT[idx]=0.0f; HGh[idx]=z; HGl[idx]=z; }
}

__device__ __forceinline__ void gbar(unsigned* ctr, unsigned target){
    __threadfence();
    __syncthreads();
    if(threadIdx.x == 0){
        atomicAdd(ctr, 1u);
        volatile unsigned* p = ctr;
        while(*p < target) __nanosleep(32);
    }
    __syncthreads();
    __threadfence();
}

// ---------------- persistent all-timesteps kernel ----------------
// 140 blocks x 512 thr. ESN group (112 blocks) and GRU group (28) sync on
// SEPARATE counters — the two recurrences are independent within a step.
// W persistent in smem; B ring of k=64 chunks (4 subs). fp16 2-product.
// Blocks: [0,112)  ESN: m-tile bx/7, K-split bx%7 (6x320 + 1x256) -> 5/4 chunks
//         [112,128) GRU r,z: K-split of 640 -> 5 chunks
//         [128,136) GRU n h-part: 2 splits of 512 -> 4 chunks
//         [136,140) GRU n x-part: K=[512,640) -> 2 chunks
__global__ void __launch_bounds__(NTHR) k_all(
    const float* __restrict__ bih, const float* __restrict__ bhh)
{
    extern __shared__ __align__(16) hf sm[];
    const int tid = threadIdx.x, lane = tid & 31, wid = tid >> 5, bx = blockIdx.x;
    const unsigned sb = (unsigned)__cvta_generic_to_shared(sm);
    const bool isE = (bx < NBE);

    // ---- role setup ----
    const hf *Wp, *Bh, *Bl; float* acc; int Kst, kbase, nch, kth;
    if(isE){
        int m0 = (bx/7)*128, ks = bx%7;
        kbase = ks*320; nch = (ks < 6) ? 5 : 4; kth = Rr; Kst = KE;
        Wp = WEH + (size_t)m0*KE;
        Bh = HEh; Bl = HEl; acc = accE[ks] + m0*Bb;
    } else if(bx < 128){
        int g = bx-112, m0 = (g>>1)*128, ks = g&1;
        kbase = ks*320; nch = 5; kth = Hh; Kst = KG;
        Wp = WGH + (size_t)m0*KG;
        Bh = HGh; Bl = HGl; acc = accRZ[ks] + m0*Bb;
    } else if(bx < 136){
        int g = bx-128, mt = g>>1, ks = g&1;
        kbase = ks*256; nch = 4; kth = Hh; Kst = KG;
        Wp = WGH + (size_t)(1024 + mt*128)*KG;
        Bh = HGh; Bl = HGl; acc = accNH[ks] + mt*128*Bb;
    } else {
        int mt = bx-136;
        kbase = 512; nch = 2; kth = Hh; Kst = KG;
        Wp = WGH + (size_t)(1024 + mt*128)*KG;
        Bh = HGh; Bl = HGl; acc = accNX + mt*128*Bb;
    }
    unsigned* ctr = isE ? &g_ctrE : &g_ctrG;
    const unsigned NB = isE ? NBE : NBG;

    // ---- one-time W prologue: nch*4 subs, each 128 rows x 24-half stride ----
    {
        const int nsubs = nch*4;
        int rp = tid & 255, row = rp >> 1, part = rp & 1;
        for(int s2 = 0; s2 < nsubs; s2 += 2){
            int sub = s2 + (tid >> 8);
            if(sub < nsubs)
                cp16(sb + (unsigned)BRING_BYTES + (unsigned)(sub*6144 + row*48 + part*16),
                     Wp + (size_t)row*Kst + kbase + sub*16 + part*8);
        }
        asm volatile("cp.async.commit_group;");
        asm volatile("cp.async.wait_group 0;");
        __syncthreads();
    }

    // ---- B loader mapping: each thread does 2 cp16 per k=64 chunk ----
    // unit = tid>>7 selects sub (0..3); thread covers (sub, hi) and (sub, lo)
    const int bsub = tid >> 7, btid = tid & 127;
    const int krow = btid >> 3, boff = (btid & 7) * 8;
    const unsigned bd0 = sb + (unsigned)(bsub*4608 + krow*144 + (btid&7)*16);

    // ---- warp tiling: warp = (m16 slice, n32 half) ----
    const int mw = (wid >> 1) * 16, nh = wid & 1;
    const int ar = lane & 15, ac = (lane>>4)*8;
    const int r4 = lane>>2, c2 = 2*(lane&3);
    const int gbaseE = bx*NTHR + tid;
    const int gbaseG = (bx - NBE)*NTHR + tid;
    const int NT_E = NBE*NTHR, NT_G = NBG*NTHR;

    for(int t = 0; t < Tt; t++){
        const hf* XtH = Xh + (size_t)t*Ii*Bb;
        const hf* XtL = Xl + (size_t)t*Ii*Bb;

        auto issue = [&](int c){
            if(c >= nch) return;
            unsigned dst = bd0 + (unsigned)(c & 3)*BCH_BYTES;
            int kr = kbase + c*64 + bsub*16 + krow;
            const hf* qh = (kr < kth) ? Bh + kr*Bb + boff : XtH + (kr-kth)*Bb + boff;
            const hf* ql = (kr < kth) ? Bl + kr*Bb + boff : XtL + (kr-kth)*Bb + boff;
            cp16(dst, qh);
            cp16(dst + 2304u, ql);
            asm volatile("cp.async.commit_group;");
        };

        float d[4][4];
        #pragma unroll
        for(int j=0;j<4;j++)
            #pragma unroll
            for(int q=0;q<4;q++) d[j][q] = 0.0f;

        issue(0); issue(1); issue(2);

        for(int c = 0; c < nch; c++){
            if(c < nch-3)       asm volatile("cp.async.wait_group 2;");
            else if(c == nch-3) asm volatile("cp.async.wait_group 2;");
            else if(c == nch-2) asm volatile("cp.async.wait_group 1;");
            else                asm volatile("cp.async.wait_group 0;");
            __syncthreads();
            if(c + 3 < nch) issue(c + 3);

            #pragma unroll
            for(int sub = 0; sub < 4; ++sub){
                const hf* sw  = sm + (BRING_BYTES/2) + (size_t)(c*4 + sub)*WSUB_HALFS;
                const hf* sbh = sm + (size_t)(c & 3)*(BCH_BYTES/2) + sub*2304;
                const hf* sbl = sbh + 1152;

                unsigned A[4], Bf[2][2][4];
                ldsm4(A, sw + (mw + ar)*24 + ac);
                #pragma unroll
                for(int i=0; i<2; i++){
                    ldsm4t(Bf[0][i], sbh + ar*72 + (2*nh + i)*16 + ac);
                    ldsm4t(Bf[1][i], sbl + ar*72 + (2*nh + i)*16 + ac);
                }
                #pragma unroll
                for(int nt=0; nt<4; nt++){
                    mma_hf(d[nt], A, &Bf[0][nt>>1][(nt&1)*2]);   // W * h_hi
                    mma_hf(d[nt], A, &Bf[1][nt>>1][(nt&1)*2]);   // W * h_lo
                }
            }
        }
        #pragma unroll
        for(int nt=0; nt<4; nt++){
            int m = mw + r4, b = nh*32 + nt*8 + c2;
            *(float2*)&acc[m*Bb + b]     = make_float2(d[nt][0], d[nt][1]);
            *(float2*)&acc[(m+8)*Bb + b] = make_float2(d[nt][2], d[nt][3]);
        }

        gbar(ctr, NB * (unsigned)(2*t + 1));

        // ---------- epilogue (group-local) ----------
        if(isE){
            for(int g = gbaseE; g < (Rr*Bb)/4; g += NT_E){
                int o = g*4;
                float4 a0 = *(const float4*)&accE[0][o];
                float4 a1 = *(const float4*)&accE[1][o];
                float4 a2 = *(const float4*)&accE[2][o];
                float4 a3 = *(const float4*)&accE[3][o];
                float4 a4 = *(const float4*)&accE[4][o];
                float4 a5 = *(const float4*)&accE[5][o];
                float4 a6 = *(const float4*)&accE[6][o];
                float4 hp = *(const float4*)&hET[o];
                float n0 = 0.7f*hp.x + 0.3f*ftanh(a0.x+a1.x+a2.x+a3.x+a4.x+a5.x+a6.x);
                float n1 = 0.7f*hp.y + 0.3f*ftanh(a0.y+a1.y+a2.y+a3.y+a4.y+a5.y+a6.y);
                float n2 = 0.7f*hp.z + 0.3f*ftanh(a0.z+a1.z+a2.z+a3.z+a4.z+a5.z+a6.z);
                float n3 = 0.7f*hp.w + 0.3f*ftanh(a0.w+a1.w+a2.w+a3.w+a4.w+a5.w+a6.w);
                *(float4*)&hET[o] = make_float4(n0,n1,n2,n3);
                hpack4(n0,n1,n2,n3, &HEh[o], &HEl[o]);
            }
        } else {
            for(int g = gbaseG; g < (Hh*Bb)/4; g += NT_G){
                int j = g >> 4, b4 = (g & 15)*4, ix = j*64 + b4;
                float4 r0 = *(const float4*)&accRZ[0][ix];
                float4 r1 = *(const float4*)&accRZ[1][ix];
                float4 z0 = *(const float4*)&accRZ[0][(j+Hh)*64 + b4];
                float4 z1 = *(const float4*)&accRZ[1][(j+Hh)*64 + b4];
                float4 h0 = *(const float4*)&accNH[0][ix];
                float4 h1 = *(const float4*)&accNH[1][ix];
                float4 xn = *(const float4*)&accNX[ix];
                float4 hp = *(const float4*)&hGT[ix];
                float br  = bih[j] + bhh[j];
                float bz2 = bih[j+Hh] + bhh[j+Hh];
                float bxn = bih[j+2*Hh], bhn = bhh[j+2*Hh];
                float n[4];
                #pragma unroll
                for(int i=0;i<4;i++){
                    float rv = (&r0.x)[i] + (&r1.x)[i];
                    float zv = (&z0.x)[i] + (&z1.x)[i];
                    float hnv = (&h0.x)[i] + (&h1.x)[i];
                    float xnv = (&xn.x)[i];
                    float hpv = (&hp.x)[i];
                    float rg = fsig(rv + br);
                    float zg = fsig(zv + bz2);
                    float nn = ftanh(xnv + bxn + rg*(hnv + bhn));
                    n[i] = (1.0f - zg)*nn + zg*hpv;
                }
                *(float4*)&hGT[ix] = make_float4(n[0],n[1],n[2],n[3]);
                hpack4(n[0],n[1],n[2],n[3], &HGh[ix], &HGl[ix]);
            }
        }

        gbar(ctr, NB * (unsigned)(2*t + 2));
    }
}

// ---------------- final transpose + head ----------------
__global__ void k_tr(){
    int idx = blockIdx.x*blockDim.x + threadIdx.x;
    if(idx < Bb*Rr){ int b = idx/Rr, c = idx - b*Rr; g_hE[idx] = hET[c*Bb + b]; }
    if(idx < Bb*Hh){ int b = idx/Hh, j = idx - b*Hh; g_hG[idx] = hGT[j*Bb + b]; }
}
__global__ __launch_bounds__(256) void k_gemm(
    const float* __restrict__ A, const float* __restrict__ W,
    const float* __restrict__ bias, float* __restrict__ C, int K, int J, int act)
{
    __shared__ __align__(16) float sA[32*68];
    __shared__ float sW2[32*16];
    const int tid = threadIdx.x, tx = tid & 15, ty = tid >> 4, jb = blockIdx.x*16;
    float acc[4] = {0.f,0.f,0.f,0.f};
    for(int ch=0; ch<(K>>5); ch++){
        const int k0 = ch*32;
        #pragma unroll
        for(int r=0;r<2;r++){
            int idx = tid + r*256, b = idx>>3, kq = idx&7;
            float4 v = *(const float4*)(A + b*K + k0 + 4*kq);
            sA[(4*kq+0)*68+b]=v.x; sA[(4*kq+1)*68+b]=v.y;
            sA[(4*kq+2)*68+b]=v.z; sA[(4*kq+3)*68+b]=v.w;
        }
        #pragma unroll
        for(int r=0;r<2;r++){
            int idx = tid + r*256, kr = idx&31, c = idx>>5;
            sW2[kr*16+c] = W[(jb+c)*K + k0 + kr];
        }
        __syncthreads();
        #pragma unroll
        for(int kk=0;kk<32;kk++){
            float w = sW2[kk*16+tx];
            float4 a = *(const float4*)&sA[kk*68 + 4*ty];
            acc[0]+=a.x*w; acc[1]+=a.y*w; acc[2]+=a.z*w; acc[3]+=a.w*w;
        }
        __syncthreads();
    }
    const int j = jb + tx; const float bv = bias[j];
    #pragma unroll
    for(int i=0;i<4;i++){
        float v = acc[i] + bv;
        if(act==1) v = sigm(v); else if(act==2) v = fmaxf(v, 0.0f);
        C[(4*ty+i)*J + j] = v;
    }
}
__global__ void k_cat(){
    int idx = blockIdx.x*blockDim.x + threadIdx.x;
    if(idx < Bb*2*Hh){
        int b = idx>>10, k = idx & 1023;
        g_cat[idx] = (k < Hh) ? g_proj[b*Hh + k] : g_hG[b*Hh + (k-Hh)];
    }
}
__global__ void k_combine(){
    int idx = blockIdx.x*blockDim.x + threadIdx.x;
    if(idx < Bb*Hh){
        float g = g_gate[idx];
        g_comb[idx] = g*g_proj[idx] + (1.0f - g)*g_hG[idx];
    }
}

extern "C" void kernel_launch(void* const* d_in, const int* in_sizes, int n_in,
                              void* d_out, int out_size)
{
    const float* x     = (const float*)d_in[0];
    const float* Win   = (const float*)d_in[1];
    const float* Wres  = (const float*)d_in[2];
    const float* Wih   = (const float*)d_in[3];
    const float* Whh   = (const float*)d_in[4];
    const float* bih   = (const float*)d_in[5];
    const float* bhh   = (const float*)d_in[6];
    const float* projW = (const float*)d_in[7];
    const float* projb = (const float*)d_in[8];
    const float* gateW = (const float*)d_in[9];
    const float* gateb = (const float*)d_in[10];
    const float* hW1   = (const float*)d_in[11];
    const float* hb1   = (const float*)d_in[12];
    const float* hW2   = (const float*)d_in[13];
    const float* hb2   = (const float*)d_in[14];
    float* out = (float*)d_out;

    void *pE, *pProj, *pCat, *pComb, *pHid, *pGate;
    cudaGetSymbolAddress(&pE,    g_hE);
    cudaGetSymbolAddress(&pProj, g_proj);
    cudaGetSymbolAddress(&pCat,  g_cat);
    cudaGetSymbolAddress(&pComb, g_comb);
    cudaGetSymbolAddress(&pGate, g_gate);
    cudaGetSymbolAddress(&pHid,  g_hid);

    cudaFuncSetAttribute(k_all, cudaFuncAttributeMaxDynamicSharedMemorySize, SMEM_BYTES);

    k_prepWE<<<(Rr*KE)/256, 256>>>(Wres, Win);
    k_prepWG<<<(MG*KG)/256, 256>>>(Whh, Wih);
    k_prepXI<<<(Tt*Ii*Bb)/256, 256>>>(x);
    k_all<<<NBLK, NTHR, SMEM_BYTES>>>(bih, bhh);
    k_tr<<<512, 256>>>();
    k_gemm<<<32, 256>>>((const float*)pE,   projW, projb, (float*)pProj, Rr,   Hh, 0);
    k_cat    <<<256, 256>>>();
    k_gemm<<<32, 256>>>((const float*)pCat, gateW, gateb, (float*)pGate, 2*Hh, Hh, 1);
    k_combine<<<128, 256>>>();
    k_gemm<<<32, 256>>>((const float*)pComb, hW1,  hb1,   (float*)pHid,  Hh,   Hh, 2);
    k_gemm<<<8,  256>>>((const float*)pHid,  hW2,  hb2,   out,           Hh,   Oo, 0);
}